// round 9
// baseline (speedup 1.0000x reference)
#include <cuda_runtime.h>
#include <mma.h>
using namespace nvcuda;

#define Nn   10000
#define Ne   320000
#define EAt  330000      // edges + self loops
#define HID  256
#define NRED 20          // partial-reduction blocks for final softmax

// ---------------- scratch (static device globals; zero-initialized at load) ------
__device__ float    g_loop[Nn];
__device__ int      g_cnt[Nn];
__device__ int      g_row[Nn+1];
__device__ int      g_woff[Nn];
__device__ int2     g_ced[EAt];      // (src, edge_attr bits)
__device__ float    g_xl[Nn*HID];
__device__ float    g_xr[Nn*HID];
__device__ float    g_h[Nn*HID];
__device__ float    g_pl[Nn*4];
__device__ float    g_pmax[NRED];
__device__ float    g_psum[NRED];

__device__ __forceinline__ float lrelu(float v){ return v > 0.f ? v : 0.2f * v; }

__device__ __forceinline__ float dot8(float4 l0, float4 l1, float4 r0, float4 r1,
                                      float ev, float4 w0, float4 w1,
                                      float4 t0, float4 t1){
    float p = 0.f;
    p += lrelu(l0.x + r0.x + ev*w0.x) * t0.x;
    p += lrelu(l0.y + r0.y + ev*w0.y) * t0.y;
    p += lrelu(l0.z + r0.z + ev*w0.z) * t0.z;
    p += lrelu(l0.w + r0.w + ev*w0.w) * t0.w;
    p += lrelu(l1.x + r1.x + ev*w1.x) * t1.x;
    p += lrelu(l1.y + r1.y + ev*w1.y) * t1.y;
    p += lrelu(l1.z + r1.z + ev*w1.z) * t1.z;
    p += lrelu(l1.w + r1.w + ev*w1.w) * t1.w;
    return p;
}

// ---------------- kernel 1: edge histogram (+loop attr sum)  ||  lin1 ----------------
#define HB 1250   // (Ne+255)/256
__global__ void k_hist_lin1(const int* __restrict__ dst, const float* __restrict__ ea,
                            const float* __restrict__ x,
                            const float* __restrict__ Wl, const float* __restrict__ bl,
                            const float* __restrict__ Wr, const float* __restrict__ br){
    int b = blockIdx.x;
    if(b < HB){
        int e = b*256 + threadIdx.x;
        if(e < Ne){
            int d = dst[e];
            atomicAdd(&g_cnt[d], 1);
            atomicAdd(&g_loop[d], ea[e]);
        }
    } else {
        int t = (b - HB)*256 + threadIdx.x;
        if(t < Nn*64){
            int n = t >> 6, c4 = (t & 63) << 2;
            float4 xv = *(const float4*)(x + n*4);
            float4 l = *(const float4*)(bl + c4);
            float4 r = *(const float4*)(br + c4);
            float4 w;
            w = *(const float4*)(Wl + 0*256 + c4); l.x+=xv.x*w.x; l.y+=xv.x*w.y; l.z+=xv.x*w.z; l.w+=xv.x*w.w;
            w = *(const float4*)(Wl + 1*256 + c4); l.x+=xv.y*w.x; l.y+=xv.y*w.y; l.z+=xv.y*w.z; l.w+=xv.y*w.w;
            w = *(const float4*)(Wl + 2*256 + c4); l.x+=xv.z*w.x; l.y+=xv.z*w.y; l.z+=xv.z*w.z; l.w+=xv.z*w.w;
            w = *(const float4*)(Wl + 3*256 + c4); l.x+=xv.w*w.x; l.y+=xv.w*w.y; l.z+=xv.w*w.z; l.w+=xv.w*w.w;
            w = *(const float4*)(Wr + 0*256 + c4); r.x+=xv.x*w.x; r.y+=xv.x*w.y; r.z+=xv.x*w.z; r.w+=xv.x*w.w;
            w = *(const float4*)(Wr + 1*256 + c4); r.x+=xv.y*w.x; r.y+=xv.y*w.y; r.z+=xv.y*w.z; r.w+=xv.y*w.w;
            w = *(const float4*)(Wr + 2*256 + c4); r.x+=xv.z*w.x; r.y+=xv.z*w.y; r.z+=xv.z*w.z; r.w+=xv.z*w.w;
            w = *(const float4*)(Wr + 3*256 + c4); r.x+=xv.w*w.x; r.y+=xv.w*w.y; r.z+=xv.w*w.z; r.w+=xv.w*w.w;
            *(float4*)(g_xl + n*256 + c4) = l;
            *(float4*)(g_xr + n*256 + c4) = r;
        }
    }
}

// ---------------- kernel 2: scan + prep (single block) ----------------
__global__ void k_scanprep(){
    __shared__ int part[1024];
    const int NP = 10;
    int tid = threadIdx.x;
    int base = tid * NP;
    int cnt[NP], loc[NP];
    int s = 0;
    #pragma unroll
    for(int i = 0; i < NP; i++){
        int idx = base + i;
        int c = (idx < Nn) ? g_cnt[idx] : 0;
        cnt[i] = c;
        loc[i] = s;
        s += (idx < Nn) ? (c + 1) : 0;
    }
    part[tid] = s; __syncthreads();
    for(int o = 1; o < 1024; o <<= 1){
        int v = (tid >= o) ? part[tid - o] : 0;
        __syncthreads();
        if(tid >= o) part[tid] += v;
        __syncthreads();
    }
    int off = (tid > 0) ? part[tid - 1] : 0;
    #pragma unroll
    for(int i = 0; i < NP; i++){
        int idx = base + i;
        if(idx < Nn){
            int rs = off + loc[i];
            int re = rs + cnt[i] + 1;
            g_row[idx] = rs;
            if(idx == Nn-1) g_row[Nn] = re;
            float lp = g_loop[idx] / fmaxf((float)cnt[i], 1.f);
            g_ced[re-1] = make_int2(idx, __float_as_int(lp));
            g_woff[idx] = rs;
        }
    }
}

// ---------------- kernel 3: scatter edges into CSR ----------------
__global__ void k_scatter(const int* __restrict__ src, const int* __restrict__ dst,
                          const float* __restrict__ ea){
    int e = blockIdx.x*blockDim.x + threadIdx.x;
    if(e >= Ne) return;
    int d = dst[e];
    int pos = atomicAdd(&g_woff[d], 1);
    g_ced[pos] = make_int2(src[e], __float_as_int(ea[e]));
}

// ---------------- fused conv1 (low-rank aggregation over 4-dim input x) ----------
__global__ void __launch_bounds__(32) k_conv1lr(
        const float* __restrict__ x,
        const float* __restrict__ Wl, const float* __restrict__ bl,
        const float* __restrict__ We, const float* __restrict__ att,
        const float* __restrict__ bias, const float* __restrict__ gam,
        const float* __restrict__ bet){
    int n = blockIdx.x;
    int lane = threadIdx.x;
    int c0 = lane * 8;
    const float4* pr = (const float4*)(g_xr + n*HID + c0);
    float4 r0 = pr[0], r1 = pr[1];
    float4 w0 = *(const float4*)(We + c0),  w1 = *(const float4*)(We + c0 + 4);
    float4 t0 = *(const float4*)(att + c0), t1 = *(const float4*)(att + c0 + 4);
    int j = lane & 3;
    float acc1 = 0.f, den = 0.f;
    int b = g_row[n], e = g_row[n+1];
    int i = b;
    for(; i + 1 < e; i += 2){
        int2 ed0 = g_ced[i], ed1 = g_ced[i+1];
        float ev0 = __int_as_float(ed0.y), ev1 = __int_as_float(ed1.y);
        const float4* pA = (const float4*)(g_xl + ed0.x*HID + c0);
        const float4* pB = (const float4*)(g_xl + ed1.x*HID + c0);
        float4 a0 = pA[0], a1 = pA[1];
        float4 b0 = pB[0], b1 = pB[1];
        float xs0 = x[ed0.x*4 + j];
        float xs1 = x[ed1.x*4 + j];
        float p0 = dot8(a0, a1, r0, r1, ev0, w0, w1, t0, t1);
        float p1 = dot8(b0, b1, r0, r1, ev1, w0, w1, t0, t1);
        #pragma unroll
        for(int o = 0; o < 3; o++){
            p0 += __shfl_xor_sync(0xffffffffu, p0, 1 << o);
            p1 += __shfl_xor_sync(0xffffffffu, p1, 1 << o);
        }
        float e0 = __expf(p0);
        float e1 = __expf(p1);
        den += e0 + e1;
        acc1 += xs0*e0 + xs1*e1;
    }
    if(i < e){
        int2 ed0 = g_ced[i];
        float ev0 = __int_as_float(ed0.y);
        const float4* pA = (const float4*)(g_xl + ed0.x*HID + c0);
        float4 a0 = pA[0], a1 = pA[1];
        float xs0 = x[ed0.x*4 + j];
        float p0 = dot8(a0, a1, r0, r1, ev0, w0, w1, t0, t1);
        #pragma unroll
        for(int o = 0; o < 3; o++)
            p0 += __shfl_xor_sync(0xffffffffu, p0, 1 << o);
        float e0 = __expf(p0);
        den += e0;
        acc1 += xs0*e0;
    }
    float inv = 1.f / den;
    int h8 = lane & 24;
    float ax0 = __shfl_sync(0xffffffffu, acc1, h8+0) * inv;
    float ax1 = __shfl_sync(0xffffffffu, acc1, h8+1) * inv;
    float ax2 = __shfl_sync(0xffffffffu, acc1, h8+2) * inv;
    float ax3 = __shfl_sync(0xffffffffu, acc1, h8+3) * inv;
    float4 wr0A = *(const float4*)(Wl + 0*256 + c0), wr0B = *(const float4*)(Wl + 0*256 + c0 + 4);
    float4 wr1A = *(const float4*)(Wl + 1*256 + c0), wr1B = *(const float4*)(Wl + 1*256 + c0 + 4);
    float4 wr2A = *(const float4*)(Wl + 2*256 + c0), wr2B = *(const float4*)(Wl + 2*256 + c0 + 4);
    float4 wr3A = *(const float4*)(Wl + 3*256 + c0), wr3B = *(const float4*)(Wl + 3*256 + c0 + 4);
    float4 blA = *(const float4*)(bl + c0),   blB = *(const float4*)(bl + c0 + 4);
    float4 biA = *(const float4*)(bias + c0), biB = *(const float4*)(bias + c0 + 4);
    float v[8];
    v[0] = ax0*wr0A.x + ax1*wr1A.x + ax2*wr2A.x + ax3*wr3A.x + blA.x + biA.x;
    v[1] = ax0*wr0A.y + ax1*wr1A.y + ax2*wr2A.y + ax3*wr3A.y + blA.y + biA.y;
    v[2] = ax0*wr0A.z + ax1*wr1A.z + ax2*wr2A.z + ax3*wr3A.z + blA.z + biA.z;
    v[3] = ax0*wr0A.w + ax1*wr1A.w + ax2*wr2A.w + ax3*wr3A.w + blA.w + biA.w;
    v[4] = ax0*wr0B.x + ax1*wr1B.x + ax2*wr2B.x + ax3*wr3B.x + blB.x + biB.x;
    v[5] = ax0*wr0B.y + ax1*wr1B.y + ax2*wr2B.y + ax3*wr3B.y + blB.y + biB.y;
    v[6] = ax0*wr0B.z + ax1*wr1B.z + ax2*wr2B.z + ax3*wr3B.z + blB.z + biB.z;
    v[7] = ax0*wr0B.w + ax1*wr1B.w + ax2*wr2B.w + ax3*wr3B.w + blB.w + biB.w;
    float s = 0.f;
    #pragma unroll
    for(int k = 0; k < 8; k++) s += v[k];
    #pragma unroll
    for(int o = 16; o; o >>= 1) s += __shfl_xor_sync(0xffffffffu, s, o);
    float mu = s * (1.f/256.f);
    float q = 0.f;
    #pragma unroll
    for(int k = 0; k < 8; k++){ float dd = v[k]-mu; q += dd*dd; }
    #pragma unroll
    for(int o = 16; o; o >>= 1) q += __shfl_xor_sync(0xffffffffu, q, o);
    float rstd = rsqrtf(q*(1.f/256.f) + 1e-5f);
    float4 gA = *(const float4*)(gam + c0), gB = *(const float4*)(gam + c0 + 4);
    float4 eA = *(const float4*)(bet + c0), eB = *(const float4*)(bet + c0 + 4);
    float gv[8] = {gA.x,gA.y,gA.z,gA.w,gB.x,gB.y,gB.z,gB.w};
    float ev[8] = {eA.x,eA.y,eA.z,eA.w,eB.x,eB.y,eB.z,eB.w};
    float o0[8];
    #pragma unroll
    for(int k = 0; k < 8; k++)
        o0[k] = fmaxf((v[k]-mu)*rstd*gv[k] + ev[k], 0.f);
    *(float4*)(g_h + n*HID + c0)     = make_float4(o0[0],o0[1],o0[2],o0[3]);
    *(float4*)(g_h + n*HID + c0 + 4) = make_float4(o0[4],o0[5],o0[6],o0[7]);
}

// ---------------- fused conv2 (H=1, C=256): scalar loop, warp-block per node -----
__global__ void __launch_bounds__(32) k_conv2(
        const float* __restrict__ We, const float* __restrict__ att,
        const float* __restrict__ bias, const float* __restrict__ gam,
        const float* __restrict__ bet){
    int n = blockIdx.x;
    int lane = threadIdx.x;
    int c0 = lane * 8;
    const float4* pr = (const float4*)(g_xr + n*HID + c0);
    float4 r0 = pr[0], r1 = pr[1];
    float4 w0 = *(const float4*)(We + c0),  w1 = *(const float4*)(We + c0 + 4);
    float4 t0 = *(const float4*)(att + c0), t1 = *(const float4*)(att + c0 + 4);
    float acc[8] = {0,0,0,0,0,0,0,0};
    float den = 0.f;
    int b = g_row[n], e = g_row[n+1];
    int i = b;
    for(; i + 1 < e; i += 2){
        int2 ed0 = g_ced[i], ed1 = g_ced[i+1];
        float ev0 = __int_as_float(ed0.y), ev1 = __int_as_float(ed1.y);
        const float4* pA = (const float4*)(g_xl + ed0.x*HID + c0);
        const float4* pB = (const float4*)(g_xl + ed1.x*HID + c0);
        float4 a0 = pA[0], a1 = pA[1];
        float4 b0 = pB[0], b1 = pB[1];
        float p0 = dot8(a0, a1, r0, r1, ev0, w0, w1, t0, t1);
        float p1 = dot8(b0, b1, r0, r1, ev1, w0, w1, t0, t1);
        #pragma unroll
        for(int o = 0; o < 5; o++){
            p0 += __shfl_xor_sync(0xffffffffu, p0, 1 << o);
            p1 += __shfl_xor_sync(0xffffffffu, p1, 1 << o);
        }
        float e0 = __expf(p0);
        float e1 = __expf(p1);
        den += e0 + e1;
        acc[0] += a0.x*e0 + b0.x*e1; acc[1] += a0.y*e0 + b0.y*e1;
        acc[2] += a0.z*e0 + b0.z*e1; acc[3] += a0.w*e0 + b0.w*e1;
        acc[4] += a1.x*e0 + b1.x*e1; acc[5] += a1.y*e0 + b1.y*e1;
        acc[6] += a1.z*e0 + b1.z*e1; acc[7] += a1.w*e0 + b1.w*e1;
    }
    if(i < e){
        int2 ed0 = g_ced[i];
        float ev0 = __int_as_float(ed0.y);
        const float4* pA = (const float4*)(g_xl + ed0.x*HID + c0);
        float4 a0 = pA[0], a1 = pA[1];
        float p0 = dot8(a0, a1, r0, r1, ev0, w0, w1, t0, t1);
        #pragma unroll
        for(int o = 0; o < 5; o++)
            p0 += __shfl_xor_sync(0xffffffffu, p0, 1 << o);
        float e0 = __expf(p0);
        den += e0;
        acc[0] += a0.x*e0; acc[1] += a0.y*e0;
        acc[2] += a0.z*e0; acc[3] += a0.w*e0;
        acc[4] += a1.x*e0; acc[5] += a1.y*e0;
        acc[6] += a1.z*e0; acc[7] += a1.w*e0;
    }
    float inv = 1.f / den;
    float4 biA = *(const float4*)(bias + c0), biB = *(const float4*)(bias + c0 + 4);
    float bi[8] = {biA.x,biA.y,biA.z,biA.w,biB.x,biB.y,biB.z,biB.w};
    float v[8];
    float s = 0.f;
    #pragma unroll
    for(int k = 0; k < 8; k++){ v[k] = acc[k]*inv + bi[k]; s += v[k]; }
    #pragma unroll
    for(int o = 16; o; o >>= 1) s += __shfl_xor_sync(0xffffffffu, s, o);
    float mu = s * (1.f/256.f);
    float q = 0.f;
    #pragma unroll
    for(int k = 0; k < 8; k++){ float dd = v[k]-mu; q += dd*dd; }
    #pragma unroll
    for(int o = 16; o; o >>= 1) q += __shfl_xor_sync(0xffffffffu, q, o);
    float rstd = rsqrtf(q*(1.f/256.f) + 1e-5f);
    float4 gA = *(const float4*)(gam + c0), gB = *(const float4*)(gam + c0 + 4);
    float4 eA = *(const float4*)(bet + c0), eB = *(const float4*)(bet + c0 + 4);
    float gv[8] = {gA.x,gA.y,gA.z,gA.w,gB.x,gB.y,gB.z,gB.w};
    float evv[8] = {eA.x,eA.y,eA.z,eA.w,eB.x,eB.y,eB.z,eB.w};
    float o0[8];
    #pragma unroll
    for(int k = 0; k < 8; k++)
        o0[k] = fmaxf((v[k]-mu)*rstd*gv[k] + evv[k], 0.f);
    *(float4*)(g_h + n*HID + c0)     = make_float4(o0[0],o0[1],o0[2],o0[3]);
    *(float4*)(g_h + n*HID + c0 + 4) = make_float4(o0[4],o0[5],o0[6],o0[7]);
}

// ---------------- dual GEMM via 3xTF32 tensor cores (WMMA) ----------------
// C = g_h[Nn,256] @ W[256,256] + bias, for Wl2 (-> g_xl) and Wr2 (-> g_xr).
// Dekker split per operand: hi = tf32(v), lo = tf32(v-hi);
// acc += Ahi*Bhi + Ahi*Blo + Alo*Bhi  (fp32 accumulate, ~fp32 precision).
__global__ void __launch_bounds__(128) k_gemm_dual(
        const float* __restrict__ Wl, const float* __restrict__ bl,
        const float* __restrict__ Wr, const float* __restrict__ br){
    __shared__ __align__(16) float As[64][20];
    __shared__ __align__(16) float Bs[16][68];
    __shared__ __align__(16) float Cs[64][68];
    int half = blockIdx.x >> 2;
    int nblk = blockIdx.x & 3;
    const float* B    = half ? Wr   : Wl;
    const float* bias = half ? br   : bl;
    float*       C    = half ? g_xr : g_xl;
    int m0 = blockIdx.y*64, n0 = nblk*64;
    int t = threadIdx.x;
    int warp = t >> 5;
    int wy = warp >> 1, wx = warp & 1;

    wmma::fragment<wmma::accumulator,16,16,8,float> acc[2][2];
    #pragma unroll
    for(int i = 0; i < 2; i++)
        #pragma unroll
        for(int jj = 0; jj < 2; jj++)
            wmma::fill_fragment(acc[i][jj], 0.f);

    for(int k0 = 0; k0 < 256; k0 += 16){
        // load A chunk: 64 rows x 16 k (row-major in smem)
        #pragma unroll
        for(int h = 0; h < 2; h++){
            int row = (t >> 2) + h*32;
            int kq = (t & 3) * 4;
            int gm = m0 + row;
            float4 av = make_float4(0.f,0.f,0.f,0.f);
            if(gm < Nn) av = *(const float4*)(g_h + gm*256 + k0 + kq);
            *(float4*)&As[row][kq] = av;
        }
        // load B chunk: 16 k x 64 n
        #pragma unroll
        for(int h = 0; h < 2; h++){
            int kk = (t >> 4) + h*8;
            int n4 = (t & 15) * 4;
            *(float4*)&Bs[kk][n4] = *(const float4*)(B + (k0+kk)*256 + n0 + n4);
        }
        __syncthreads();
        #pragma unroll
        for(int s = 0; s < 2; s++){
            wmma::fragment<wmma::matrix_a,16,16,8,wmma::precision::tf32,wmma::row_major> ahi[2], alo[2];
            wmma::fragment<wmma::matrix_b,16,16,8,wmma::precision::tf32,wmma::row_major> bhi[2], blo[2];
            #pragma unroll
            for(int i = 0; i < 2; i++){
                wmma::load_matrix_sync(ahi[i], &As[wy*32 + i*16][s*8], 20);
                #pragma unroll
                for(int e = 0; e < ahi[i].num_elements; e++){
                    float v  = ahi[i].x[e];
                    float hi = wmma::__float_to_tf32(v);
                    ahi[i].x[e] = hi;
                    alo[i].x[e] = wmma::__float_to_tf32(v - hi);
                }
            }
            #pragma unroll
            for(int jj = 0; jj < 2; jj++){
                wmma::load_matrix_sync(bhi[jj], &Bs[s*8][wx*32 + jj*16], 68);
                #pragma unroll
                for(int e = 0; e < bhi[jj].num_elements; e++){
                    float v  = bhi[jj].x[e];
                    float hi = wmma::__float_to_tf32(v);
                    bhi[jj].x[e] = hi;
                    blo[jj].x[e] = wmma::__float_to_tf32(v - hi);
                }
            }
            #pragma unroll
            for(int i = 0; i < 2; i++)
                #pragma unroll
                for(int jj = 0; jj < 2; jj++){
                    wmma::mma_sync(acc[i][jj], ahi[i], bhi[jj], acc[i][jj]);
                    wmma::mma_sync(acc[i][jj], ahi[i], blo[jj], acc[i][jj]);
                    wmma::mma_sync(acc[i][jj], alo[i], bhi[jj], acc[i][jj]);
                }
        }
        __syncthreads();
    }
    // epilogue: stage to smem, add bias, store
    #pragma unroll
    for(int i = 0; i < 2; i++)
        #pragma unroll
        for(int jj = 0; jj < 2; jj++)
            wmma::store_matrix_sync(&Cs[wy*32 + i*16][wx*32 + jj*16], acc[i][jj], 68, wmma::mem_row_major);
    __syncthreads();
    for(int idx = t; idx < 64*16; idx += 128){
        int row = idx >> 4;
        int c4 = (idx & 15) * 4;
        int gm = m0 + row;
        if(gm < Nn){
            float4 v = *(float4*)&Cs[row][c4];
            float4 bv = *(const float4*)(bias + n0 + c4);
            v.x += bv.x; v.y += bv.y; v.z += bv.z; v.w += bv.w;
            *(float4*)(C + gm*256 + n0 + c4) = v;
        }
    }
}

// ---------------- policy GEMM (fp32 mainloop) + fused final projection ----------
__global__ void k_gemm_pol(const float* __restrict__ Wp1, const float* __restrict__ bp1,
                           const float* __restrict__ Wp2, const float* __restrict__ bp2){
    __shared__ __align__(16) float As[16][68];
    __shared__ __align__(16) float Bs[16][132];
    int m0 = blockIdx.x * 64;
    int t = threadIdx.x;
    int tx = t & 15, ty = t >> 4;
    int ar = t >> 2, ak = (t & 3) * 4;
    int br_ = t >> 4, bc = (t & 15) * 8;
    float acc[4][8] = {};
    for(int k0 = 0; k0 < 256; k0 += 16){
        float4 av = make_float4(0.f,0.f,0.f,0.f);
        int gm = m0 + ar;
        if(gm < Nn) av = *(const float4*)(g_h + gm*256 + k0 + ak);
        As[ak+0][ar] = av.x; As[ak+1][ar] = av.y;
        As[ak+2][ar] = av.z; As[ak+3][ar] = av.w;
        *(float4*)&Bs[br_][bc]   = *(const float4*)(Wp1 + (k0+br_)*128 + bc);
        *(float4*)&Bs[br_][bc+4] = *(const float4*)(Wp1 + (k0+br_)*128 + bc + 4);
        __syncthreads();
        #pragma unroll
        for(int kk = 0; kk < 16; kk++){
            float4 a = *(float4*)&As[kk][ty*4];
            float4 b0 = *(float4*)&Bs[kk][tx*8];
            float4 b1 = *(float4*)&Bs[kk][tx*8+4];
            float av4[4] = {a.x,a.y,a.z,a.w};
            float bv[8] = {b0.x,b0.y,b0.z,b0.w,b1.x,b1.y,b1.z,b1.w};
            #pragma unroll
            for(int i = 0; i < 4; i++)
                #pragma unroll
                for(int j = 0; j < 8; j++)
                    acc[i][j] += av4[i]*bv[j];
        }
        __syncthreads();
    }
    float4 bpA = *(const float4*)(bp1 + tx*8);
    float4 bpB = *(const float4*)(bp1 + tx*8 + 4);
    float bb[8] = {bpA.x,bpA.y,bpA.z,bpA.w,bpB.x,bpB.y,bpB.z,bpB.w};
    float4 wv[8];
    const float4* wp = (const float4*)(Wp2 + tx*32);
    #pragma unroll
    for(int j = 0; j < 8; j++) wv[j] = wp[j];
    float part[4][4];
    #pragma unroll
    for(int i = 0; i < 4; i++){
        part[i][0] = part[i][1] = part[i][2] = part[i][3] = 0.f;
        bool ok = (m0 + ty*4 + i) < Nn;
        #pragma unroll
        for(int j = 0; j < 8; j++){
            float v0 = ok ? fmaxf(acc[i][j] + bb[j], 0.f) : 0.f;
            part[i][0] += v0*wv[j].x;
            part[i][1] += v0*wv[j].y;
            part[i][2] += v0*wv[j].z;
            part[i][3] += v0*wv[j].w;
        }
    }
    #pragma unroll
    for(int i = 0; i < 4; i++)
        #pragma unroll
        for(int c = 0; c < 4; c++){
            #pragma unroll
            for(int o = 1; o < 16; o <<= 1)
                part[i][c] += __shfl_xor_sync(0xffffffffu, part[i][c], o);
        }
    if(tx == 0){
        #pragma unroll
        for(int i = 0; i < 4; i++){
            int gm = m0 + ty*4 + i;
            if(gm < Nn){
                float4 r4 = make_float4(part[i][0]+bp2[0], part[i][1]+bp2[1],
                                        part[i][2]+bp2[2], part[i][3]+bp2[3]);
                *(float4*)(g_pl + gm*4) = r4;
            }
        }
    }
}

// ---------------- two-phase global softmax over 40000 logits ----------------
__global__ void k_red1(){
    __shared__ float sm[256];
    int bid = blockIdx.x, tid = threadIdx.x;
    const int chunk = (Nn*4 + NRED - 1) / NRED;
    int lo = bid*chunk, hi = min(lo + chunk, Nn*4);
    float m = -3.4e38f;
    for(int i = lo + tid; i < hi; i += 256) m = fmaxf(m, g_pl[i]);
    sm[tid] = m; __syncthreads();
    for(int o = 128; o > 0; o >>= 1){ if(tid < o) sm[tid] = fmaxf(sm[tid], sm[tid+o]); __syncthreads(); }
    float mx = sm[0]; __syncthreads();
    float s = 0.f;
    for(int i = lo + tid; i < hi; i += 256) s += __expf(g_pl[i] - mx);
    sm[tid] = s; __syncthreads();
    for(int o = 128; o > 0; o >>= 1){ if(tid < o) sm[tid] += sm[tid+o]; __syncthreads(); }
    if(tid == 0){ g_pmax[bid] = mx; g_psum[bid] = sm[0]; }
}
// output (combines the NRED partials in-block) + restore state for next replay
__global__ void k_out(float* __restrict__ out){
    __shared__ float sMS[2];
    if(threadIdx.x == 0){
        float M = -3.4e38f;
        #pragma unroll
        for(int j = 0; j < NRED; j++) M = fmaxf(M, g_pmax[j]);
        float S = 0.f;
        #pragma unroll
        for(int j = 0; j < NRED; j++) S += g_psum[j] * __expf(g_pmax[j] - M);
        sMS[0] = M; sMS[1] = 1.f / S;
    }
    __syncthreads();
    int i = blockIdx.x*blockDim.x + threadIdx.x;
    if(i < Nn*4) out[i] = __expf(g_pl[i] - sMS[0]) * sMS[1];
    if(i < Nn){ g_cnt[i] = 0; g_loop[i] = 0.f; }
}

// ---------------- launch ----------------
extern "C" void kernel_launch(void* const* d_in, const int* in_sizes, int n_in,
                              void* d_out, int out_size){
    const float* x     = (const float*)d_in[0];
    const int*   ei    = (const int*)  d_in[1];
    const float* ea    = (const float*)d_in[2];
    const float* Wl1   = (const float*)d_in[3];
    const float* bl1   = (const float*)d_in[4];
    const float* Wr1   = (const float*)d_in[5];
    const float* br1   = (const float*)d_in[6];
    const float* We1   = (const float*)d_in[7];
    const float* att1  = (const float*)d_in[8];
    const float* bias1 = (const float*)d_in[9];
    const float* g1    = (const float*)d_in[10];
    const float* be1   = (const float*)d_in[11];
    const float* Wl2   = (const float*)d_in[12];
    const float* bl2   = (const float*)d_in[13];
    const float* Wr2   = (const float*)d_in[14];
    const float* br2   = (const float*)d_in[15];
    const float* We2   = (const float*)d_in[16];
    const float* att2  = (const float*)d_in[17];
    const float* bias2 = (const float*)d_in[18];
    const float* g2    = (const float*)d_in[19];
    const float* be2   = (const float*)d_in[20];
    const float* Wp1   = (const float*)d_in[21];
    const float* bp1   = (const float*)d_in[22];
    const float* Wp2   = (const float*)d_in[23];
    const float* bp2   = (const float*)d_in[24];
    const int* src = ei;
    const int* dst = ei + Ne;
    float* out = (float*)d_out;

    const int TB = 256;

    // CSR build + conv1 linear (merged)
    k_hist_lin1<<<HB + (Nn*64+TB-1)/TB, TB>>>(dst, ea, x, Wl1, bl1, Wr1, br1);
    k_scanprep<<<1, 1024>>>();
    k_scatter<<<(Ne+TB-1)/TB, TB>>>(src, dst, ea);

    // conv1 (low-rank aggregation) — one warp-block per node
    k_conv1lr<<<Nn, 32>>>(x, Wl1, bl1, We1, att1, bias1, g1, be1);

    // conv2 (3xTF32 tensor-core dual GEMM)
    k_gemm_dual<<<dim3(8, (Nn+63)/64), 128>>>(Wl2, bl2, Wr2, br2);
    k_conv2<<<Nn, 32>>>(We2, att2, bias2, g2, be2);

    // policy head (fused final projection)
    k_gemm_pol<<<(Nn+63)/64, 256>>>(Wp1, bp1, Wp2, bp2);

    // global softmax (two-phase)
    k_red1<<<NRED, 256>>>();
    k_out<<<(Nn*4+TB-1)/TB, TB>>>(out);
}

// round 10
// speedup vs baseline: 1.0299x; 1.0299x over previous
#include <cuda_runtime.h>

#define Nn   10000
#define Ne   320000
#define EAt  330000      // edges + self loops
#define HID  256
#define NRED 20          // partial-reduction blocks for final softmax

// ---------------- scratch (static device globals; zero-initialized at load) ------
__device__ float    g_loop[Nn];
__device__ int      g_cnt[Nn];
__device__ int      g_row[Nn+1];
__device__ int      g_woff[Nn];
__device__ int2     g_ced[EAt];      // (src, edge_attr bits)
__device__ float    g_xl[Nn*HID];
__device__ float    g_xr[Nn*HID];
__device__ float    g_h[Nn*HID];
__device__ float    g_pl[Nn*4];
__device__ float    g_pmax[NRED];
__device__ float    g_psum[NRED];

__device__ __forceinline__ float lrelu(float v){ return v > 0.f ? v : 0.2f * v; }

__device__ __forceinline__ float dot8(float4 l0, float4 l1, float4 r0, float4 r1,
                                      float ev, float4 w0, float4 w1,
                                      float4 t0, float4 t1){
    float p = 0.f;
    p += lrelu(l0.x + r0.x + ev*w0.x) * t0.x;
    p += lrelu(l0.y + r0.y + ev*w0.y) * t0.y;
    p += lrelu(l0.z + r0.z + ev*w0.z) * t0.z;
    p += lrelu(l0.w + r0.w + ev*w0.w) * t0.w;
    p += lrelu(l1.x + r1.x + ev*w1.x) * t1.x;
    p += lrelu(l1.y + r1.y + ev*w1.y) * t1.y;
    p += lrelu(l1.z + r1.z + ev*w1.z) * t1.z;
    p += lrelu(l1.w + r1.w + ev*w1.w) * t1.w;
    return p;
}

// ---------------- kernel 1: edge histogram (+loop attr sum)  ||  lin1 ----------------
#define HB 1250   // (Ne+255)/256
__global__ void k_hist_lin1(const int* __restrict__ dst, const float* __restrict__ ea,
                            const float* __restrict__ x,
                            const float* __restrict__ Wl, const float* __restrict__ bl,
                            const float* __restrict__ Wr, const float* __restrict__ br){
    int b = blockIdx.x;
    if(b < HB){
        int e = b*256 + threadIdx.x;
        if(e < Ne){
            int d = dst[e];
            atomicAdd(&g_cnt[d], 1);
            atomicAdd(&g_loop[d], ea[e]);
        }
    } else {
        int t = (b - HB)*256 + threadIdx.x;
        if(t < Nn*64){
            int n = t >> 6, c4 = (t & 63) << 2;
            float4 xv = *(const float4*)(x + n*4);
            float4 l = *(const float4*)(bl + c4);
            float4 r = *(const float4*)(br + c4);
            float4 w;
            w = *(const float4*)(Wl + 0*256 + c4); l.x+=xv.x*w.x; l.y+=xv.x*w.y; l.z+=xv.x*w.z; l.w+=xv.x*w.w;
            w = *(const float4*)(Wl + 1*256 + c4); l.x+=xv.y*w.x; l.y+=xv.y*w.y; l.z+=xv.y*w.z; l.w+=xv.y*w.w;
            w = *(const float4*)(Wl + 2*256 + c4); l.x+=xv.z*w.x; l.y+=xv.z*w.y; l.z+=xv.z*w.z; l.w+=xv.z*w.w;
            w = *(const float4*)(Wl + 3*256 + c4); l.x+=xv.w*w.x; l.y+=xv.w*w.y; l.z+=xv.w*w.z; l.w+=xv.w*w.w;
            w = *(const float4*)(Wr + 0*256 + c4); r.x+=xv.x*w.x; r.y+=xv.x*w.y; r.z+=xv.x*w.z; r.w+=xv.x*w.w;
            w = *(const float4*)(Wr + 1*256 + c4); r.x+=xv.y*w.x; r.y+=xv.y*w.y; r.z+=xv.y*w.z; r.w+=xv.y*w.w;
            w = *(const float4*)(Wr + 2*256 + c4); r.x+=xv.z*w.x; r.y+=xv.z*w.y; r.z+=xv.z*w.z; r.w+=xv.z*w.w;
            w = *(const float4*)(Wr + 3*256 + c4); r.x+=xv.w*w.x; r.y+=xv.w*w.y; r.z+=xv.w*w.z; r.w+=xv.w*w.w;
            *(float4*)(g_xl + n*256 + c4) = l;
            *(float4*)(g_xr + n*256 + c4) = r;
        }
    }
}

// ---------------- kernel 2: scan + prep (single block) ----------------
__global__ void k_scanprep(){
    __shared__ int part[1024];
    const int NP = 10;
    int tid = threadIdx.x;
    int base = tid * NP;
    int cnt[NP], loc[NP];
    int s = 0;
    #pragma unroll
    for(int i = 0; i < NP; i++){
        int idx = base + i;
        int c = (idx < Nn) ? g_cnt[idx] : 0;
        cnt[i] = c;
        loc[i] = s;
        s += (idx < Nn) ? (c + 1) : 0;
    }
    part[tid] = s; __syncthreads();
    for(int o = 1; o < 1024; o <<= 1){
        int v = (tid >= o) ? part[tid - o] : 0;
        __syncthreads();
        if(tid >= o) part[tid] += v;
        __syncthreads();
    }
    int off = (tid > 0) ? part[tid - 1] : 0;
    #pragma unroll
    for(int i = 0; i < NP; i++){
        int idx = base + i;
        if(idx < Nn){
            int rs = off + loc[i];
            int re = rs + cnt[i] + 1;
            g_row[idx] = rs;
            if(idx == Nn-1) g_row[Nn] = re;
            float lp = g_loop[idx] / fmaxf((float)cnt[i], 1.f);
            g_ced[re-1] = make_int2(idx, __float_as_int(lp));
            g_woff[idx] = rs;
        }
    }
}

// ---------------- kernel 3: scatter edges into CSR ----------------
__global__ void k_scatter(const int* __restrict__ src, const int* __restrict__ dst,
                          const float* __restrict__ ea){
    int e = blockIdx.x*blockDim.x + threadIdx.x;
    if(e >= Ne) return;
    int d = dst[e];
    int pos = atomicAdd(&g_woff[d], 1);
    g_ced[pos] = make_int2(src[e], __float_as_int(ea[e]));
}

// ---------------- fused conv1 (low-rank aggregation over 4-dim input x) ----------
// edge-record prefetch: next pair's g_ced load overlaps current pair's gathers
__global__ void __launch_bounds__(32) k_conv1lr(
        const float* __restrict__ x,
        const float* __restrict__ Wl, const float* __restrict__ bl,
        const float* __restrict__ We, const float* __restrict__ att,
        const float* __restrict__ bias, const float* __restrict__ gam,
        const float* __restrict__ bet){
    int n = blockIdx.x;
    int lane = threadIdx.x;
    int c0 = lane * 8;
    const float4* pr = (const float4*)(g_xr + n*HID + c0);
    float4 r0 = pr[0], r1 = pr[1];
    float4 w0 = *(const float4*)(We + c0),  w1 = *(const float4*)(We + c0 + 4);
    float4 t0 = *(const float4*)(att + c0), t1 = *(const float4*)(att + c0 + 4);
    int j = lane & 3;
    float acc1 = 0.f, den = 0.f;
    int b = g_row[n], e = g_row[n+1];
    int i = b;
    int2 nx0, nx1;
    if(i + 1 < e){ nx0 = g_ced[i]; nx1 = g_ced[i+1]; }
    for(; i + 1 < e; i += 2){
        int2 ed0 = nx0, ed1 = nx1;
        if(i + 3 < e){ nx0 = g_ced[i+2]; nx1 = g_ced[i+3]; }
        float ev0 = __int_as_float(ed0.y), ev1 = __int_as_float(ed1.y);
        const float4* pA = (const float4*)(g_xl + ed0.x*HID + c0);
        const float4* pB = (const float4*)(g_xl + ed1.x*HID + c0);
        float4 a0 = pA[0], a1 = pA[1];
        float4 b0 = pB[0], b1 = pB[1];
        float xs0 = x[ed0.x*4 + j];
        float xs1 = x[ed1.x*4 + j];
        float p0 = dot8(a0, a1, r0, r1, ev0, w0, w1, t0, t1);
        float p1 = dot8(b0, b1, r0, r1, ev1, w0, w1, t0, t1);
        #pragma unroll
        for(int o = 0; o < 3; o++){
            p0 += __shfl_xor_sync(0xffffffffu, p0, 1 << o);
            p1 += __shfl_xor_sync(0xffffffffu, p1, 1 << o);
        }
        float e0 = __expf(p0);
        float e1 = __expf(p1);
        den += e0 + e1;
        acc1 += xs0*e0 + xs1*e1;
    }
    if(i < e){
        int2 ed0 = g_ced[i];
        float ev0 = __int_as_float(ed0.y);
        const float4* pA = (const float4*)(g_xl + ed0.x*HID + c0);
        float4 a0 = pA[0], a1 = pA[1];
        float xs0 = x[ed0.x*4 + j];
        float p0 = dot8(a0, a1, r0, r1, ev0, w0, w1, t0, t1);
        #pragma unroll
        for(int o = 0; o < 3; o++)
            p0 += __shfl_xor_sync(0xffffffffu, p0, 1 << o);
        float e0 = __expf(p0);
        den += e0;
        acc1 += xs0*e0;
    }
    float inv = 1.f / den;
    int h8 = lane & 24;
    float ax0 = __shfl_sync(0xffffffffu, acc1, h8+0) * inv;
    float ax1 = __shfl_sync(0xffffffffu, acc1, h8+1) * inv;
    float ax2 = __shfl_sync(0xffffffffu, acc1, h8+2) * inv;
    float ax3 = __shfl_sync(0xffffffffu, acc1, h8+3) * inv;
    float4 wr0A = *(const float4*)(Wl + 0*256 + c0), wr0B = *(const float4*)(Wl + 0*256 + c0 + 4);
    float4 wr1A = *(const float4*)(Wl + 1*256 + c0), wr1B = *(const float4*)(Wl + 1*256 + c0 + 4);
    float4 wr2A = *(const float4*)(Wl + 2*256 + c0), wr2B = *(const float4*)(Wl + 2*256 + c0 + 4);
    float4 wr3A = *(const float4*)(Wl + 3*256 + c0), wr3B = *(const float4*)(Wl + 3*256 + c0 + 4);
    float4 blA = *(const float4*)(bl + c0),   blB = *(const float4*)(bl + c0 + 4);
    float4 biA = *(const float4*)(bias + c0), biB = *(const float4*)(bias + c0 + 4);
    float v[8];
    v[0] = ax0*wr0A.x + ax1*wr1A.x + ax2*wr2A.x + ax3*wr3A.x + blA.x + biA.x;
    v[1] = ax0*wr0A.y + ax1*wr1A.y + ax2*wr2A.y + ax3*wr3A.y + blA.y + biA.y;
    v[2] = ax0*wr0A.z + ax1*wr1A.z + ax2*wr2A.z + ax3*wr3A.z + blA.z + biA.z;
    v[3] = ax0*wr0A.w + ax1*wr1A.w + ax2*wr2A.w + ax3*wr3A.w + blA.w + biA.w;
    v[4] = ax0*wr0B.x + ax1*wr1B.x + ax2*wr2B.x + ax3*wr3B.x + blB.x + biB.x;
    v[5] = ax0*wr0B.y + ax1*wr1B.y + ax2*wr2B.y + ax3*wr3B.y + blB.y + biB.y;
    v[6] = ax0*wr0B.z + ax1*wr1B.z + ax2*wr2B.z + ax3*wr3B.z + blB.z + biB.z;
    v[7] = ax0*wr0B.w + ax1*wr1B.w + ax2*wr2B.w + ax3*wr3B.w + blB.w + biB.w;
    float s = 0.f;
    #pragma unroll
    for(int k = 0; k < 8; k++) s += v[k];
    #pragma unroll
    for(int o = 16; o; o >>= 1) s += __shfl_xor_sync(0xffffffffu, s, o);
    float mu = s * (1.f/256.f);
    float q = 0.f;
    #pragma unroll
    for(int k = 0; k < 8; k++){ float dd = v[k]-mu; q += dd*dd; }
    #pragma unroll
    for(int o = 16; o; o >>= 1) q += __shfl_xor_sync(0xffffffffu, q, o);
    float rstd = rsqrtf(q*(1.f/256.f) + 1e-5f);
    float4 gA = *(const float4*)(gam + c0), gB = *(const float4*)(gam + c0 + 4);
    float4 eA = *(const float4*)(bet + c0), eB = *(const float4*)(bet + c0 + 4);
    float gv[8] = {gA.x,gA.y,gA.z,gA.w,gB.x,gB.y,gB.z,gB.w};
    float ev[8] = {eA.x,eA.y,eA.z,eA.w,eB.x,eB.y,eB.z,eB.w};
    float o0[8];
    #pragma unroll
    for(int k = 0; k < 8; k++)
        o0[k] = fmaxf((v[k]-mu)*rstd*gv[k] + ev[k], 0.f);
    *(float4*)(g_h + n*HID + c0)     = make_float4(o0[0],o0[1],o0[2],o0[3]);
    *(float4*)(g_h + n*HID + c0 + 4) = make_float4(o0[4],o0[5],o0[6],o0[7]);
}

// ---------------- fused conv2 (H=1, C=256): scalar loop + edge-record prefetch ---
__global__ void __launch_bounds__(32) k_conv2(
        const float* __restrict__ We, const float* __restrict__ att,
        const float* __restrict__ bias, const float* __restrict__ gam,
        const float* __restrict__ bet){
    int n = blockIdx.x;
    int lane = threadIdx.x;
    int c0 = lane * 8;
    const float4* pr = (const float4*)(g_xr + n*HID + c0);
    float4 r0 = pr[0], r1 = pr[1];
    float4 w0 = *(const float4*)(We + c0),  w1 = *(const float4*)(We + c0 + 4);
    float4 t0 = *(const float4*)(att + c0), t1 = *(const float4*)(att + c0 + 4);
    float acc[8] = {0,0,0,0,0,0,0,0};
    float den = 0.f;
    int b = g_row[n], e = g_row[n+1];
    int i = b;
    int2 nx0, nx1;
    if(i + 1 < e){ nx0 = g_ced[i]; nx1 = g_ced[i+1]; }
    for(; i + 1 < e; i += 2){
        int2 ed0 = nx0, ed1 = nx1;
        if(i + 3 < e){ nx0 = g_ced[i+2]; nx1 = g_ced[i+3]; }
        float ev0 = __int_as_float(ed0.y), ev1 = __int_as_float(ed1.y);
        const float4* pA = (const float4*)(g_xl + ed0.x*HID + c0);
        const float4* pB = (const float4*)(g_xl + ed1.x*HID + c0);
        float4 a0 = pA[0], a1 = pA[1];
        float4 b0 = pB[0], b1 = pB[1];
        float p0 = dot8(a0, a1, r0, r1, ev0, w0, w1, t0, t1);
        float p1 = dot8(b0, b1, r0, r1, ev1, w0, w1, t0, t1);
        #pragma unroll
        for(int o = 0; o < 5; o++){
            p0 += __shfl_xor_sync(0xffffffffu, p0, 1 << o);
            p1 += __shfl_xor_sync(0xffffffffu, p1, 1 << o);
        }
        float e0 = __expf(p0);
        float e1 = __expf(p1);
        den += e0 + e1;
        acc[0] += a0.x*e0 + b0.x*e1; acc[1] += a0.y*e0 + b0.y*e1;
        acc[2] += a0.z*e0 + b0.z*e1; acc[3] += a0.w*e0 + b0.w*e1;
        acc[4] += a1.x*e0 + b1.x*e1; acc[5] += a1.y*e0 + b1.y*e1;
        acc[6] += a1.z*e0 + b1.z*e1; acc[7] += a1.w*e0 + b1.w*e1;
    }
    if(i < e){
        int2 ed0 = g_ced[i];
        float ev0 = __int_as_float(ed0.y);
        const float4* pA = (const float4*)(g_xl + ed0.x*HID + c0);
        float4 a0 = pA[0], a1 = pA[1];
        float p0 = dot8(a0, a1, r0, r1, ev0, w0, w1, t0, t1);
        #pragma unroll
        for(int o = 0; o < 5; o++)
            p0 += __shfl_xor_sync(0xffffffffu, p0, 1 << o);
        float e0 = __expf(p0);
        den += e0;
        acc[0] += a0.x*e0; acc[1] += a0.y*e0;
        acc[2] += a0.z*e0; acc[3] += a0.w*e0;
        acc[4] += a1.x*e0; acc[5] += a1.y*e0;
        acc[6] += a1.z*e0; acc[7] += a1.w*e0;
    }
    float inv = 1.f / den;
    float4 biA = *(const float4*)(bias + c0), biB = *(const float4*)(bias + c0 + 4);
    float bi[8] = {biA.x,biA.y,biA.z,biA.w,biB.x,biB.y,biB.z,biB.w};
    float v[8];
    float s = 0.f;
    #pragma unroll
    for(int k = 0; k < 8; k++){ v[k] = acc[k]*inv + bi[k]; s += v[k]; }
    #pragma unroll
    for(int o = 16; o; o >>= 1) s += __shfl_xor_sync(0xffffffffu, s, o);
    float mu = s * (1.f/256.f);
    float q = 0.f;
    #pragma unroll
    for(int k = 0; k < 8; k++){ float dd = v[k]-mu; q += dd*dd; }
    #pragma unroll
    for(int o = 16; o; o >>= 1) q += __shfl_xor_sync(0xffffffffu, q, o);
    float rstd = rsqrtf(q*(1.f/256.f) + 1e-5f);
    float4 gA = *(const float4*)(gam + c0), gB = *(const float4*)(gam + c0 + 4);
    float4 eA = *(const float4*)(bet + c0), eB = *(const float4*)(bet + c0 + 4);
    float gv[8] = {gA.x,gA.y,gA.z,gA.w,gB.x,gB.y,gB.z,gB.w};
    float evv[8] = {eA.x,eA.y,eA.z,eA.w,eB.x,eB.y,eB.z,eB.w};
    float o0[8];
    #pragma unroll
    for(int k = 0; k < 8; k++)
        o0[k] = fmaxf((v[k]-mu)*rstd*gv[k] + evv[k], 0.f);
    *(float4*)(g_h + n*HID + c0)     = make_float4(o0[0],o0[1],o0[2],o0[3]);
    *(float4*)(g_h + n*HID + c0 + 4) = make_float4(o0[4],o0[5],o0[6],o0[7]);
}

// ---------------- dual GEMM (proven 64x64 fp32 tile), one launch ----------------
__global__ void k_gemm_dual(const float* __restrict__ Wl, const float* __restrict__ bl,
                            const float* __restrict__ Wr, const float* __restrict__ br){
    __shared__ __align__(16) float As[16][68];
    __shared__ __align__(16) float Bs[16][68];
    int half = blockIdx.x >> 2;
    int nblk = blockIdx.x & 3;
    const float* B    = half ? Wr   : Wl;
    const float* bias = half ? br   : bl;
    float*       C    = half ? g_xr : g_xl;
    int m0 = blockIdx.y*64, n0 = nblk*64;
    int t = threadIdx.x;
    int tx = t & 15, ty = t >> 4;
    float acc[4][4] = {};
    int arow = t >> 2, ak = (t & 3) * 4;
    int brow = t >> 4, bc = (t & 15) * 4;
    for(int k0 = 0; k0 < 256; k0 += 16){
        float4 av = make_float4(0.f,0.f,0.f,0.f);
        int gm = m0 + arow;
        if(gm < Nn) av = *(const float4*)(g_h + gm*256 + k0 + ak);
        As[ak+0][arow] = av.x; As[ak+1][arow] = av.y;
        As[ak+2][arow] = av.z; As[ak+3][arow] = av.w;
        *(float4*)&Bs[brow][bc] = *(const float4*)(B + (k0+brow)*256 + n0 + bc);
        __syncthreads();
        #pragma unroll
        for(int kk = 0; kk < 16; kk++){
            float4 a = *(float4*)&As[kk][ty*4];
            float4 b = *(float4*)&Bs[kk][tx*4];
            acc[0][0]+=a.x*b.x; acc[0][1]+=a.x*b.y; acc[0][2]+=a.x*b.z; acc[0][3]+=a.x*b.w;
            acc[1][0]+=a.y*b.x; acc[1][1]+=a.y*b.y; acc[1][2]+=a.y*b.z; acc[1][3]+=a.y*b.w;
            acc[2][0]+=a.z*b.x; acc[2][1]+=a.z*b.y; acc[2][2]+=a.z*b.z; acc[2][3]+=a.z*b.w;
            acc[3][0]+=a.w*b.x; acc[3][1]+=a.w*b.y; acc[3][2]+=a.w*b.z; acc[3][3]+=a.w*b.w;
        }
        __syncthreads();
    }
    #pragma unroll
    for(int i = 0; i < 4; i++){
        int gm = m0 + ty*4 + i;
        if(gm >= Nn) continue;
        #pragma unroll
        for(int j = 0; j < 4; j++){
            int col = n0 + tx*4 + j;
            C[gm*256 + col] = acc[i][j] + bias[col];
        }
    }
}

// ---------------- policy GEMM (fp32 mainloop) + fused final projection ----------
__global__ void k_gemm_pol(const float* __restrict__ Wp1, const float* __restrict__ bp1,
                           const float* __restrict__ Wp2, const float* __restrict__ bp2){
    __shared__ __align__(16) float As[16][68];
    __shared__ __align__(16) float Bs[16][132];
    int m0 = blockIdx.x * 64;
    int t = threadIdx.x;
    int tx = t & 15, ty = t >> 4;
    int ar = t >> 2, ak = (t & 3) * 4;
    int br_ = t >> 4, bc = (t & 15) * 8;
    float acc[4][8] = {};
    for(int k0 = 0; k0 < 256; k0 += 16){
        float4 av = make_float4(0.f,0.f,0.f,0.f);
        int gm = m0 + ar;
        if(gm < Nn) av = *(const float4*)(g_h + gm*256 + k0 + ak);
        As[ak+0][ar] = av.x; As[ak+1][ar] = av.y;
        As[ak+2][ar] = av.z; As[ak+3][ar] = av.w;
        *(float4*)&Bs[br_][bc]   = *(const float4*)(Wp1 + (k0+br_)*128 + bc);
        *(float4*)&Bs[br_][bc+4] = *(const float4*)(Wp1 + (k0+br_)*128 + bc + 4);
        __syncthreads();
        #pragma unroll
        for(int kk = 0; kk < 16; kk++){
            float4 a = *(float4*)&As[kk][ty*4];
            float4 b0 = *(float4*)&Bs[kk][tx*8];
            float4 b1 = *(float4*)&Bs[kk][tx*8+4];
            float av4[4] = {a.x,a.y,a.z,a.w};
            float bv[8] = {b0.x,b0.y,b0.z,b0.w,b1.x,b1.y,b1.z,b1.w};
            #pragma unroll
            for(int i = 0; i < 4; i++)
                #pragma unroll
                for(int j = 0; j < 8; j++)
                    acc[i][j] += av4[i]*bv[j];
        }
        __syncthreads();
    }
    float4 bpA = *(const float4*)(bp1 + tx*8);
    float4 bpB = *(const float4*)(bp1 + tx*8 + 4);
    float bb[8] = {bpA.x,bpA.y,bpA.z,bpA.w,bpB.x,bpB.y,bpB.z,bpB.w};
    float4 wv[8];
    const float4* wp = (const float4*)(Wp2 + tx*32);
    #pragma unroll
    for(int j = 0; j < 8; j++) wv[j] = wp[j];
    float part[4][4];
    #pragma unroll
    for(int i = 0; i < 4; i++){
        part[i][0] = part[i][1] = part[i][2] = part[i][3] = 0.f;
        bool ok = (m0 + ty*4 + i) < Nn;
        #pragma unroll
        for(int j = 0; j < 8; j++){
            float v0 = ok ? fmaxf(acc[i][j] + bb[j], 0.f) : 0.f;
            part[i][0] += v0*wv[j].x;
            part[i][1] += v0*wv[j].y;
            part[i][2] += v0*wv[j].z;
            part[i][3] += v0*wv[j].w;
        }
    }
    #pragma unroll
    for(int i = 0; i < 4; i++)
        #pragma unroll
        for(int c = 0; c < 4; c++){
            #pragma unroll
            for(int o = 1; o < 16; o <<= 1)
                part[i][c] += __shfl_xor_sync(0xffffffffu, part[i][c], o);
        }
    if(tx == 0){
        #pragma unroll
        for(int i = 0; i < 4; i++){
            int gm = m0 + ty*4 + i;
            if(gm < Nn){
                float4 r4 = make_float4(part[i][0]+bp2[0], part[i][1]+bp2[1],
                                        part[i][2]+bp2[2], part[i][3]+bp2[3]);
                *(float4*)(g_pl + gm*4) = r4;
            }
        }
    }
}

// ---------------- two-phase global softmax over 40000 logits ----------------
__global__ void k_red1(){
    __shared__ float sm[256];
    int bid = blockIdx.x, tid = threadIdx.x;
    const int chunk = (Nn*4 + NRED - 1) / NRED;
    int lo = bid*chunk, hi = min(lo + chunk, Nn*4);
    float m = -3.4e38f;
    for(int i = lo + tid; i < hi; i += 256) m = fmaxf(m, g_pl[i]);
    sm[tid] = m; __syncthreads();
    for(int o = 128; o > 0; o >>= 1){ if(tid < o) sm[tid] = fmaxf(sm[tid], sm[tid+o]); __syncthreads(); }
    float mx = sm[0]; __syncthreads();
    float s = 0.f;
    for(int i = lo + tid; i < hi; i += 256) s += __expf(g_pl[i] - mx);
    sm[tid] = s; __syncthreads();
    for(int o = 128; o > 0; o >>= 1){ if(tid < o) sm[tid] += sm[tid+o]; __syncthreads(); }
    if(tid == 0){ g_pmax[bid] = mx; g_psum[bid] = sm[0]; }
}
// output (combines the NRED partials in-block) + restore state for next replay
__global__ void k_out(float* __restrict__ out){
    __shared__ float sMS[2];
    if(threadIdx.x == 0){
        float M = -3.4e38f;
        #pragma unroll
        for(int j = 0; j < NRED; j++) M = fmaxf(M, g_pmax[j]);
        float S = 0.f;
        #pragma unroll
        for(int j = 0; j < NRED; j++) S += g_psum[j] * __expf(g_pmax[j] - M);
        sMS[0] = M; sMS[1] = 1.f / S;
    }
    __syncthreads();
    int i = blockIdx.x*blockDim.x + threadIdx.x;
    if(i < Nn*4) out[i] = __expf(g_pl[i] - sMS[0]) * sMS[1];
    if(i < Nn){ g_cnt[i] = 0; g_loop[i] = 0.f; }
}

// ---------------- launch ----------------
extern "C" void kernel_launch(void* const* d_in, const int* in_sizes, int n_in,
                              void* d_out, int out_size){
    const float* x     = (const float*)d_in[0];
    const int*   ei    = (const int*)  d_in[1];
    const float* ea    = (const float*)d_in[2];
    const float* Wl1   = (const float*)d_in[3];
    const float* bl1   = (const float*)d_in[4];
    const float* Wr1   = (const float*)d_in[5];
    const float* br1   = (const float*)d_in[6];
    const float* We1   = (const float*)d_in[7];
    const float* att1  = (const float*)d_in[8];
    const float* bias1 = (const float*)d_in[9];
    const float* g1    = (const float*)d_in[10];
    const float* be1   = (const float*)d_in[11];
    const float* Wl2   = (const float*)d_in[12];
    const float* bl2   = (const float*)d_in[13];
    const float* Wr2   = (const float*)d_in[14];
    const float* br2   = (const float*)d_in[15];
    const float* We2   = (const float*)d_in[16];
    const float* att2  = (const float*)d_in[17];
    const float* bias2 = (const float*)d_in[18];
    const float* g2    = (const float*)d_in[19];
    const float* be2   = (const float*)d_in[20];
    const float* Wp1   = (const float*)d_in[21];
    const float* bp1   = (const float*)d_in[22];
    const float* Wp2   = (const float*)d_in[23];
    const float* bp2   = (const float*)d_in[24];
    const int* src = ei;
    const int* dst = ei + Ne;
    float* out = (float*)d_out;

    const int TB = 256;

    // CSR build + conv1 linear (merged)
    k_hist_lin1<<<HB + (Nn*64+TB-1)/TB, TB>>>(dst, ea, x, Wl1, bl1, Wr1, br1);
    k_scanprep<<<1, 1024>>>();
    k_scatter<<<(Ne+TB-1)/TB, TB>>>(src, dst, ea);

    // conv1 (low-rank aggregation) — one warp-block per node
    k_conv1lr<<<Nn, 32>>>(x, Wl1, bl1, We1, att1, bias1, g1, be1);

    // conv2
    k_gemm_dual<<<dim3(8, (Nn+63)/64), 256>>>(Wl2, bl2, Wr2, br2);
    k_conv2<<<Nn, 32>>>(We2, att2, bias2, g2, be2);

    // policy head (fused final projection)
    k_gemm_pol<<<(Nn+63)/64, 256>>>(Wp1, bp1, Wp2, bp2);

    // global softmax (two-phase)
    k_red1<<<NRED, 256>>>();
    k_out<<<(Nn*4+TB-1)/TB, TB>>>(out);
}

// round 11
// speedup vs baseline: 1.0757x; 1.0445x over previous
#include <cuda_runtime.h>
#include <cuda_fp16.h>

#define Nn   10000
#define Ne   320000
#define EAt  330000      // edges + self loops
#define HID  256
#define NRED 20          // partial-reduction blocks for final softmax

// ---------------- scratch (static device globals; zero-initialized at load) ------
__device__ float    g_loop[Nn];
__device__ int      g_cnt[Nn];
__device__ int      g_row[Nn+1];
__device__ int      g_woff[Nn];
__device__ int2     g_ced[EAt];        // (src, edge_attr bits)
__device__ __half2  g_xlh[Nn*128];     // fp16 feature table gathered per edge
__device__ float    g_xr[Nn*HID];
__device__ float    g_h[Nn*HID];
__device__ float    g_pl[Nn*4];
__device__ float    g_pmax[NRED];
__device__ float    g_psum[NRED];

__device__ __forceinline__ float lrelu(float v){ return v > 0.f ? v : 0.2f * v; }

__device__ __forceinline__ float dot8(float4 l0, float4 l1, float4 r0, float4 r1,
                                      float ev, float4 w0, float4 w1,
                                      float4 t0, float4 t1){
    float p = 0.f;
    p += lrelu(l0.x + r0.x + ev*w0.x) * t0.x;
    p += lrelu(l0.y + r0.y + ev*w0.y) * t0.y;
    p += lrelu(l0.z + r0.z + ev*w0.z) * t0.z;
    p += lrelu(l0.w + r0.w + ev*w0.w) * t0.w;
    p += lrelu(l1.x + r1.x + ev*w1.x) * t1.x;
    p += lrelu(l1.y + r1.y + ev*w1.y) * t1.y;
    p += lrelu(l1.z + r1.z + ev*w1.z) * t1.z;
    p += lrelu(l1.w + r1.w + ev*w1.w) * t1.w;
    return p;
}

// load 8 fp16 channels (one 16B load) -> two float4
__device__ __forceinline__ void ldh8(const __half2* base, float4& lo, float4& hi){
    uint4 raw = *(const uint4*)base;
    float2 f0 = __half22float2(*(__half2*)&raw.x);
    float2 f1 = __half22float2(*(__half2*)&raw.y);
    float2 f2 = __half22float2(*(__half2*)&raw.z);
    float2 f3 = __half22float2(*(__half2*)&raw.w);
    lo = make_float4(f0.x, f0.y, f1.x, f1.y);
    hi = make_float4(f2.x, f2.y, f3.x, f3.y);
}

// ---------------- kernel 1: edge histogram (+loop attr sum)  ||  lin1 ----------------
#define HB 1250   // (Ne+255)/256
__global__ void k_hist_lin1(const int* __restrict__ dst, const float* __restrict__ ea,
                            const float* __restrict__ x,
                            const float* __restrict__ Wl, const float* __restrict__ bl,
                            const float* __restrict__ Wr, const float* __restrict__ br){
    int b = blockIdx.x;
    if(b < HB){
        int e = b*256 + threadIdx.x;
        if(e < Ne){
            int d = dst[e];
            atomicAdd(&g_cnt[d], 1);
            atomicAdd(&g_loop[d], ea[e]);
        }
    } else {
        int t = (b - HB)*256 + threadIdx.x;
        if(t < Nn*64){
            int n = t >> 6, c4 = (t & 63) << 2;
            float4 xv = *(const float4*)(x + n*4);
            float4 l = *(const float4*)(bl + c4);
            float4 r = *(const float4*)(br + c4);
            float4 w;
            w = *(const float4*)(Wl + 0*256 + c4); l.x+=xv.x*w.x; l.y+=xv.x*w.y; l.z+=xv.x*w.z; l.w+=xv.x*w.w;
            w = *(const float4*)(Wl + 1*256 + c4); l.x+=xv.y*w.x; l.y+=xv.y*w.y; l.z+=xv.y*w.z; l.w+=xv.y*w.w;
            w = *(const float4*)(Wl + 2*256 + c4); l.x+=xv.z*w.x; l.y+=xv.z*w.y; l.z+=xv.z*w.z; l.w+=xv.z*w.w;
            w = *(const float4*)(Wl + 3*256 + c4); l.x+=xv.w*w.x; l.y+=xv.w*w.y; l.z+=xv.w*w.z; l.w+=xv.w*w.w;
            w = *(const float4*)(Wr + 0*256 + c4); r.x+=xv.x*w.x; r.y+=xv.x*w.y; r.z+=xv.x*w.z; r.w+=xv.x*w.w;
            w = *(const float4*)(Wr + 1*256 + c4); r.x+=xv.y*w.x; r.y+=xv.y*w.y; r.z+=xv.y*w.z; r.w+=xv.y*w.w;
            w = *(const float4*)(Wr + 2*256 + c4); r.x+=xv.z*w.x; r.y+=xv.z*w.y; r.z+=xv.z*w.z; r.w+=xv.z*w.w;
            w = *(const float4*)(Wr + 3*256 + c4); r.x+=xv.w*w.x; r.y+=xv.w*w.y; r.z+=xv.w*w.z; r.w+=xv.w*w.w;
            __half2 h0 = __floats2half2_rn(l.x, l.y);
            __half2 h1 = __floats2half2_rn(l.z, l.w);
            __half2* dst2 = g_xlh + n*128 + (c4 >> 1);
            dst2[0] = h0; dst2[1] = h1;
            *(float4*)(g_xr + n*256 + c4) = r;
        }
    }
}

// ---------------- kernel 2: scan + prep (single block) ----------------
__global__ void k_scanprep(){
    __shared__ int part[1024];
    const int NP = 10;
    int tid = threadIdx.x;
    int base = tid * NP;
    int cnt[NP], loc[NP];
    int s = 0;
    #pragma unroll
    for(int i = 0; i < NP; i++){
        int idx = base + i;
        int c = (idx < Nn) ? g_cnt[idx] : 0;
        cnt[i] = c;
        loc[i] = s;
        s += (idx < Nn) ? (c + 1) : 0;
    }
    part[tid] = s; __syncthreads();
    for(int o = 1; o < 1024; o <<= 1){
        int v = (tid >= o) ? part[tid - o] : 0;
        __syncthreads();
        if(tid >= o) part[tid] += v;
        __syncthreads();
    }
    int off = (tid > 0) ? part[tid - 1] : 0;
    #pragma unroll
    for(int i = 0; i < NP; i++){
        int idx = base + i;
        if(idx < Nn){
            int rs = off + loc[i];
            int re = rs + cnt[i] + 1;
            g_row[idx] = rs;
            if(idx == Nn-1) g_row[Nn] = re;
            float lp = g_loop[idx] / fmaxf((float)cnt[i], 1.f);
            g_ced[re-1] = make_int2(idx, __float_as_int(lp));
            g_woff[idx] = rs;
        }
    }
}

// ---------------- kernel 3: scatter edges into CSR ----------------
__global__ void k_scatter(const int* __restrict__ src, const int* __restrict__ dst,
                          const float* __restrict__ ea){
    int e = blockIdx.x*blockDim.x + threadIdx.x;
    if(e >= Ne) return;
    int d = dst[e];
    int pos = atomicAdd(&g_woff[d], 1);
    g_ced[pos] = make_int2(src[e], __float_as_int(ea[e]));
}

// ---------------- fused conv1 (low-rank aggregation; fp16 logit gathers) ---------
__global__ void __launch_bounds__(32) k_conv1lr(
        const float* __restrict__ x,
        const float* __restrict__ Wl, const float* __restrict__ bl,
        const float* __restrict__ We, const float* __restrict__ att,
        const float* __restrict__ bias, const float* __restrict__ gam,
        const float* __restrict__ bet){
    int n = blockIdx.x;
    int lane = threadIdx.x;
    int c0 = lane * 8;
    const float4* pr = (const float4*)(g_xr + n*HID + c0);
    float4 r0 = pr[0], r1 = pr[1];
    float4 w0 = *(const float4*)(We + c0),  w1 = *(const float4*)(We + c0 + 4);
    float4 t0 = *(const float4*)(att + c0), t1 = *(const float4*)(att + c0 + 4);
    int j = lane & 3;
    float acc1 = 0.f, den = 0.f;
    int b = g_row[n], e = g_row[n+1];
    int i = b;
    for(; i + 1 < e; i += 2){
        int2 ed0 = g_ced[i], ed1 = g_ced[i+1];
        float ev0 = __int_as_float(ed0.y), ev1 = __int_as_float(ed1.y);
        float4 a0, a1, b0, b1;
        ldh8(g_xlh + ed0.x*128 + lane*4, a0, a1);
        ldh8(g_xlh + ed1.x*128 + lane*4, b0, b1);
        float xs0 = x[ed0.x*4 + j];
        float xs1 = x[ed1.x*4 + j];
        float p0 = dot8(a0, a1, r0, r1, ev0, w0, w1, t0, t1);
        float p1 = dot8(b0, b1, r0, r1, ev1, w0, w1, t0, t1);
        #pragma unroll
        for(int o = 0; o < 3; o++){
            p0 += __shfl_xor_sync(0xffffffffu, p0, 1 << o);
            p1 += __shfl_xor_sync(0xffffffffu, p1, 1 << o);
        }
        float e0 = __expf(p0);
        float e1 = __expf(p1);
        den += e0 + e1;
        acc1 += xs0*e0 + xs1*e1;
    }
    if(i < e){
        int2 ed0 = g_ced[i];
        float ev0 = __int_as_float(ed0.y);
        float4 a0, a1;
        ldh8(g_xlh + ed0.x*128 + lane*4, a0, a1);
        float xs0 = x[ed0.x*4 + j];
        float p0 = dot8(a0, a1, r0, r1, ev0, w0, w1, t0, t1);
        #pragma unroll
        for(int o = 0; o < 3; o++)
            p0 += __shfl_xor_sync(0xffffffffu, p0, 1 << o);
        float e0 = __expf(p0);
        den += e0;
        acc1 += xs0*e0;
    }
    float inv = 1.f / den;
    int h8 = lane & 24;
    float ax0 = __shfl_sync(0xffffffffu, acc1, h8+0) * inv;
    float ax1 = __shfl_sync(0xffffffffu, acc1, h8+1) * inv;
    float ax2 = __shfl_sync(0xffffffffu, acc1, h8+2) * inv;
    float ax3 = __shfl_sync(0xffffffffu, acc1, h8+3) * inv;
    float4 wr0A = *(const float4*)(Wl + 0*256 + c0), wr0B = *(const float4*)(Wl + 0*256 + c0 + 4);
    float4 wr1A = *(const float4*)(Wl + 1*256 + c0), wr1B = *(const float4*)(Wl + 1*256 + c0 + 4);
    float4 wr2A = *(const float4*)(Wl + 2*256 + c0), wr2B = *(const float4*)(Wl + 2*256 + c0 + 4);
    float4 wr3A = *(const float4*)(Wl + 3*256 + c0), wr3B = *(const float4*)(Wl + 3*256 + c0 + 4);
    float4 blA = *(const float4*)(bl + c0),   blB = *(const float4*)(bl + c0 + 4);
    float4 biA = *(const float4*)(bias + c0), biB = *(const float4*)(bias + c0 + 4);
    float v[8];
    v[0] = ax0*wr0A.x + ax1*wr1A.x + ax2*wr2A.x + ax3*wr3A.x + blA.x + biA.x;
    v[1] = ax0*wr0A.y + ax1*wr1A.y + ax2*wr2A.y + ax3*wr3A.y + blA.y + biA.y;
    v[2] = ax0*wr0A.z + ax1*wr1A.z + ax2*wr2A.z + ax3*wr3A.z + blA.z + biA.z;
    v[3] = ax0*wr0A.w + ax1*wr1A.w + ax2*wr2A.w + ax3*wr3A.w + blA.w + biA.w;
    v[4] = ax0*wr0B.x + ax1*wr1B.x + ax2*wr2B.x + ax3*wr3B.x + blB.x + biB.x;
    v[5] = ax0*wr0B.y + ax1*wr1B.y + ax2*wr2B.y + ax3*wr3B.y + blB.y + biB.y;
    v[6] = ax0*wr0B.z + ax1*wr1B.z + ax2*wr2B.z + ax3*wr3B.z + blB.z + biB.z;
    v[7] = ax0*wr0B.w + ax1*wr1B.w + ax2*wr2B.w + ax3*wr3B.w + blB.w + biB.w;
    float s = 0.f;
    #pragma unroll
    for(int k = 0; k < 8; k++) s += v[k];
    #pragma unroll
    for(int o = 16; o; o >>= 1) s += __shfl_xor_sync(0xffffffffu, s, o);
    float mu = s * (1.f/256.f);
    float q = 0.f;
    #pragma unroll
    for(int k = 0; k < 8; k++){ float dd = v[k]-mu; q += dd*dd; }
    #pragma unroll
    for(int o = 16; o; o >>= 1) q += __shfl_xor_sync(0xffffffffu, q, o);
    float rstd = rsqrtf(q*(1.f/256.f) + 1e-5f);
    float4 gA = *(const float4*)(gam + c0), gB = *(const float4*)(gam + c0 + 4);
    float4 eA = *(const float4*)(bet + c0), eB = *(const float4*)(bet + c0 + 4);
    float gv[8] = {gA.x,gA.y,gA.z,gA.w,gB.x,gB.y,gB.z,gB.w};
    float ev[8] = {eA.x,eA.y,eA.z,eA.w,eB.x,eB.y,eB.z,eB.w};
    float o0[8];
    #pragma unroll
    for(int k = 0; k < 8; k++)
        o0[k] = fmaxf((v[k]-mu)*rstd*gv[k] + ev[k], 0.f);
    *(float4*)(g_h + n*HID + c0)     = make_float4(o0[0],o0[1],o0[2],o0[3]);
    *(float4*)(g_h + n*HID + c0 + 4) = make_float4(o0[4],o0[5],o0[6],o0[7]);
}

// ---------------- fused conv2 (H=1, C=256): fp16 gathers, fp32 accumulate --------
__global__ void __launch_bounds__(32) k_conv2(
        const float* __restrict__ We, const float* __restrict__ att,
        const float* __restrict__ bias, const float* __restrict__ gam,
        const float* __restrict__ bet){
    int n = blockIdx.x;
    int lane = threadIdx.x;
    int c0 = lane * 8;
    const float4* pr = (const float4*)(g_xr + n*HID + c0);
    float4 r0 = pr[0], r1 = pr[1];
    float4 w0 = *(const float4*)(We + c0),  w1 = *(const float4*)(We + c0 + 4);
    float4 t0 = *(const float4*)(att + c0), t1 = *(const float4*)(att + c0 + 4);
    float acc[8] = {0,0,0,0,0,0,0,0};
    float den = 0.f;
    int b = g_row[n], e = g_row[n+1];
    int i = b;
    for(; i + 1 < e; i += 2){
        int2 ed0 = g_ced[i], ed1 = g_ced[i+1];
        float ev0 = __int_as_float(ed0.y), ev1 = __int_as_float(ed1.y);
        float4 a0, a1, b0, b1;
        ldh8(g_xlh + ed0.x*128 + lane*4, a0, a1);
        ldh8(g_xlh + ed1.x*128 + lane*4, b0, b1);
        float p0 = dot8(a0, a1, r0, r1, ev0, w0, w1, t0, t1);
        float p1 = dot8(b0, b1, r0, r1, ev1, w0, w1, t0, t1);
        #pragma unroll
        for(int o = 0; o < 5; o++){
            p0 += __shfl_xor_sync(0xffffffffu, p0, 1 << o);
            p1 += __shfl_xor_sync(0xffffffffu, p1, 1 << o);
        }
        float e0 = __expf(p0);
        float e1 = __expf(p1);
        den += e0 + e1;
        acc[0] += a0.x*e0 + b0.x*e1; acc[1] += a0.y*e0 + b0.y*e1;
        acc[2] += a0.z*e0 + b0.z*e1; acc[3] += a0.w*e0 + b0.w*e1;
        acc[4] += a1.x*e0 + b1.x*e1; acc[5] += a1.y*e0 + b1.y*e1;
        acc[6] += a1.z*e0 + b1.z*e1; acc[7] += a1.w*e0 + b1.w*e1;
    }
    if(i < e){
        int2 ed0 = g_ced[i];
        float ev0 = __int_as_float(ed0.y);
        float4 a0, a1;
        ldh8(g_xlh + ed0.x*128 + lane*4, a0, a1);
        float p0 = dot8(a0, a1, r0, r1, ev0, w0, w1, t0, t1);
        #pragma unroll
        for(int o = 0; o < 5; o++)
            p0 += __shfl_xor_sync(0xffffffffu, p0, 1 << o);
        float e0 = __expf(p0);
        den += e0;
        acc[0] += a0.x*e0; acc[1] += a0.y*e0;
        acc[2] += a0.z*e0; acc[3] += a0.w*e0;
        acc[4] += a1.x*e0; acc[5] += a1.y*e0;
        acc[6] += a1.z*e0; acc[7] += a1.w*e0;
    }
    float inv = 1.f / den;
    float4 biA = *(const float4*)(bias + c0), biB = *(const float4*)(bias + c0 + 4);
    float bi[8] = {biA.x,biA.y,biA.z,biA.w,biB.x,biB.y,biB.z,biB.w};
    float v[8];
    float s = 0.f;
    #pragma unroll
    for(int k = 0; k < 8; k++){ v[k] = acc[k]*inv + bi[k]; s += v[k]; }
    #pragma unroll
    for(int o = 16; o; o >>= 1) s += __shfl_xor_sync(0xffffffffu, s, o);
    float mu = s * (1.f/256.f);
    float q = 0.f;
    #pragma unroll
    for(int k = 0; k < 8; k++){ float dd = v[k]-mu; q += dd*dd; }
    #pragma unroll
    for(int o = 16; o; o >>= 1) q += __shfl_xor_sync(0xffffffffu, q, o);
    float rstd = rsqrtf(q*(1.f/256.f) + 1e-5f);
    float4 gA = *(const float4*)(gam + c0), gB = *(const float4*)(gam + c0 + 4);
    float4 eA = *(const float4*)(bet + c0), eB = *(const float4*)(bet + c0 + 4);
    float gv[8] = {gA.x,gA.y,gA.z,gA.w,gB.x,gB.y,gB.z,gB.w};
    float evv[8] = {eA.x,eA.y,eA.z,eA.w,eB.x,eB.y,eB.z,eB.w};
    float o0[8];
    #pragma unroll
    for(int k = 0; k < 8; k++)
        o0[k] = fmaxf((v[k]-mu)*rstd*gv[k] + evv[k], 0.f);
    *(float4*)(g_h + n*HID + c0)     = make_float4(o0[0],o0[1],o0[2],o0[3]);
    *(float4*)(g_h + n*HID + c0 + 4) = make_float4(o0[4],o0[5],o0[6],o0[7]);
}

// ---------------- dual GEMM (64x64 fp32 tile); xl half writes, xr fp32 ----------
__global__ void k_gemm_dual(const float* __restrict__ Wl, const float* __restrict__ bl,
                            const float* __restrict__ Wr, const float* __restrict__ br){
    __shared__ __align__(16) float As[16][68];
    __shared__ __align__(16) float Bs[16][68];
    int half_ = blockIdx.x >> 2;
    int nblk = blockIdx.x & 3;
    const float* B    = half_ ? Wr : Wl;
    const float* bias = half_ ? br : bl;
    int m0 = blockIdx.y*64, n0 = nblk*64;
    int t = threadIdx.x;
    int tx = t & 15, ty = t >> 4;
    float acc[4][4] = {};
    int arow = t >> 2, ak = (t & 3) * 4;
    int brow = t >> 4, bc = (t & 15) * 4;
    for(int k0 = 0; k0 < 256; k0 += 16){
        float4 av = make_float4(0.f,0.f,0.f,0.f);
        int gm = m0 + arow;
        if(gm < Nn) av = *(const float4*)(g_h + gm*256 + k0 + ak);
        As[ak+0][arow] = av.x; As[ak+1][arow] = av.y;
        As[ak+2][arow] = av.z; As[ak+3][arow] = av.w;
        *(float4*)&Bs[brow][bc] = *(const float4*)(B + (k0+brow)*256 + n0 + bc);
        __syncthreads();
        #pragma unroll
        for(int kk = 0; kk < 16; kk++){
            float4 a = *(float4*)&As[kk][ty*4];
            float4 b = *(float4*)&Bs[kk][tx*4];
            acc[0][0]+=a.x*b.x; acc[0][1]+=a.x*b.y; acc[0][2]+=a.x*b.z; acc[0][3]+=a.x*b.w;
            acc[1][0]+=a.y*b.x; acc[1][1]+=a.y*b.y; acc[1][2]+=a.y*b.z; acc[1][3]+=a.y*b.w;
            acc[2][0]+=a.z*b.x; acc[2][1]+=a.z*b.y; acc[2][2]+=a.z*b.z; acc[2][3]+=a.z*b.w;
            acc[3][0]+=a.w*b.x; acc[3][1]+=a.w*b.y; acc[3][2]+=a.w*b.z; acc[3][3]+=a.w*b.w;
        }
        __syncthreads();
    }
    int colb = n0 + tx*4;
    float4 bv = *(const float4*)(bias + colb);
    #pragma unroll
    for(int i = 0; i < 4; i++){
        int gm = m0 + ty*4 + i;
        if(gm >= Nn) continue;
        float v0 = acc[i][0] + bv.x;
        float v1 = acc[i][1] + bv.y;
        float v2 = acc[i][2] + bv.z;
        float v3 = acc[i][3] + bv.w;
        if(half_){
            *(float4*)(g_xr + gm*256 + colb) = make_float4(v0,v1,v2,v3);
        } else {
            __half2 h0 = __floats2half2_rn(v0, v1);
            __half2 h1 = __floats2half2_rn(v2, v3);
            __half2* d2 = g_xlh + gm*128 + (colb >> 1);
            d2[0] = h0; d2[1] = h1;
        }
    }
}

// ---------------- policy GEMM (fp32 mainloop) + fused final projection ----------
__global__ void k_gemm_pol(const float* __restrict__ Wp1, const float* __restrict__ bp1,
                           const float* __restrict__ Wp2, const float* __restrict__ bp2){
    __shared__ __align__(16) float As[16][68];
    __shared__ __align__(16) float Bs[16][132];
    int m0 = blockIdx.x * 64;
    int t = threadIdx.x;
    int tx = t & 15, ty = t >> 4;
    int ar = t >> 2, ak = (t & 3) * 4;
    int br_ = t >> 4, bc = (t & 15) * 8;
    float acc[4][8] = {};
    for(int k0 = 0; k0 < 256; k0 += 16){
        float4 av = make_float4(0.f,0.f,0.f,0.f);
        int gm = m0 + ar;
        if(gm < Nn) av = *(const float4*)(g_h + gm*256 + k0 + ak);
        As[ak+0][ar] = av.x; As[ak+1][ar] = av.y;
        As[ak+2][ar] = av.z; As[ak+3][ar] = av.w;
        *(float4*)&Bs[br_][bc]   = *(const float4*)(Wp1 + (k0+br_)*128 + bc);
        *(float4*)&Bs[br_][bc+4] = *(const float4*)(Wp1 + (k0+br_)*128 + bc + 4);
        __syncthreads();
        #pragma unroll
        for(int kk = 0; kk < 16; kk++){
            float4 a = *(float4*)&As[kk][ty*4];
            float4 b0 = *(float4*)&Bs[kk][tx*8];
            float4 b1 = *(float4*)&Bs[kk][tx*8+4];
            float av4[4] = {a.x,a.y,a.z,a.w};
            float bv[8] = {b0.x,b0.y,b0.z,b0.w,b1.x,b1.y,b1.z,b1.w};
            #pragma unroll
            for(int i = 0; i < 4; i++)
                #pragma unroll
                for(int j = 0; j < 8; j++)
                    acc[i][j] += av4[i]*bv[j];
        }
        __syncthreads();
    }
    float4 bpA = *(const float4*)(bp1 + tx*8);
    float4 bpB = *(const float4*)(bp1 + tx*8 + 4);
    float bb[8] = {bpA.x,bpA.y,bpA.z,bpA.w,bpB.x,bpB.y,bpB.z,bpB.w};
    float4 wv[8];
    const float4* wp = (const float4*)(Wp2 + tx*32);
    #pragma unroll
    for(int j = 0; j < 8; j++) wv[j] = wp[j];
    float part[4][4];
    #pragma unroll
    for(int i = 0; i < 4; i++){
        part[i][0] = part[i][1] = part[i][2] = part[i][3] = 0.f;
        bool ok = (m0 + ty*4 + i) < Nn;
        #pragma unroll
        for(int j = 0; j < 8; j++){
            float v0 = ok ? fmaxf(acc[i][j] + bb[j], 0.f) : 0.f;
            part[i][0] += v0*wv[j].x;
            part[i][1] += v0*wv[j].y;
            part[i][2] += v0*wv[j].z;
            part[i][3] += v0*wv[j].w;
        }
    }
    #pragma unroll
    for(int i = 0; i < 4; i++)
        #pragma unroll
        for(int c = 0; c < 4; c++){
            #pragma unroll
            for(int o = 1; o < 16; o <<= 1)
                part[i][c] += __shfl_xor_sync(0xffffffffu, part[i][c], o);
        }
    if(tx == 0){
        #pragma unroll
        for(int i = 0; i < 4; i++){
            int gm = m0 + ty*4 + i;
            if(gm < Nn){
                float4 r4 = make_float4(part[i][0]+bp2[0], part[i][1]+bp2[1],
                                        part[i][2]+bp2[2], part[i][3]+bp2[3]);
                *(float4*)(g_pl + gm*4) = r4;
            }
        }
    }
}

// ---------------- two-phase global softmax over 40000 logits ----------------
__global__ void k_red1(){
    __shared__ float sm[256];
    int bid = blockIdx.x, tid = threadIdx.x;
    const int chunk = (Nn*4 + NRED - 1) / NRED;
    int lo = bid*chunk, hi = min(lo + chunk, Nn*4);
    float m = -3.4e38f;
    for(int i = lo + tid; i < hi; i += 256) m = fmaxf(m, g_pl[i]);
    sm[tid] = m; __syncthreads();
    for(int o = 128; o > 0; o >>= 1){ if(tid < o) sm[tid] = fmaxf(sm[tid], sm[tid+o]); __syncthreads(); }
    float mx = sm[0]; __syncthreads();
    float s = 0.f;
    for(int i = lo + tid; i < hi; i += 256) s += __expf(g_pl[i] - mx);
    sm[tid] = s; __syncthreads();
    for(int o = 128; o > 0; o >>= 1){ if(tid < o) sm[tid] += sm[tid+o]; __syncthreads(); }
    if(tid == 0){ g_pmax[bid] = mx; g_psum[bid] = sm[0]; }
}
// output (combines the NRED partials in-block) + restore state for next replay
__global__ void k_out(float* __restrict__ out){
    __shared__ float sMS[2];
    if(threadIdx.x == 0){
        float M = -3.4e38f;
        #pragma unroll
        for(int j = 0; j < NRED; j++) M = fmaxf(M, g_pmax[j]);
        float S = 0.f;
        #pragma unroll
        for(int j = 0; j < NRED; j++) S += g_psum[j] * __expf(g_pmax[j] - M);
        sMS[0] = M; sMS[1] = 1.f / S;
    }
    __syncthreads();
    int i = blockIdx.x*blockDim.x + threadIdx.x;
    if(i < Nn*4) out[i] = __expf(g_pl[i] - sMS[0]) * sMS[1];
    if(i < Nn){ g_cnt[i] = 0; g_loop[i] = 0.f; }
}

// ---------------- launch ----------------
extern "C" void kernel_launch(void* const* d_in, const int* in_sizes, int n_in,
                              void* d_out, int out_size){
    const float* x     = (const float*)d_in[0];
    const int*   ei    = (const int*)  d_in[1];
    const float* ea    = (const float*)d_in[2];
    const float* Wl1   = (const float*)d_in[3];
    const float* bl1   = (const float*)d_in[4];
    const float* Wr1   = (const float*)d_in[5];
    const float* br1   = (const float*)d_in[6];
    const float* We1   = (const float*)d_in[7];
    const float* att1  = (const float*)d_in[8];
    const float* bias1 = (const float*)d_in[9];
    const float* g1    = (const float*)d_in[10];
    const float* be1   = (const float*)d_in[11];
    const float* Wl2   = (const float*)d_in[12];
    const float* bl2   = (const float*)d_in[13];
    const float* Wr2   = (const float*)d_in[14];
    const float* br2   = (const float*)d_in[15];
    const float* We2   = (const float*)d_in[16];
    const float* att2  = (const float*)d_in[17];
    const float* bias2 = (const float*)d_in[18];
    const float* g2    = (const float*)d_in[19];
    const float* be2   = (const float*)d_in[20];
    const float* Wp1   = (const float*)d_in[21];
    const float* bp1   = (const float*)d_in[22];
    const float* Wp2   = (const float*)d_in[23];
    const float* bp2   = (const float*)d_in[24];
    const int* src = ei;
    const int* dst = ei + Ne;
    float* out = (float*)d_out;

    const int TB = 256;

    // CSR build + conv1 linear (merged)
    k_hist_lin1<<<HB + (Nn*64+TB-1)/TB, TB>>>(dst, ea, x, Wl1, bl1, Wr1, br1);
    k_scanprep<<<1, 1024>>>();
    k_scatter<<<(Ne+TB-1)/TB, TB>>>(src, dst, ea);

    // conv1 (low-rank aggregation) — one warp-block per node
    k_conv1lr<<<Nn, 32>>>(x, Wl1, bl1, We1, att1, bias1, g1, be1);

    // conv2
    k_gemm_dual<<<dim3(8, (Nn+63)/64), 256>>>(Wl2, bl2, Wr2, br2);
    k_conv2<<<Nn, 32>>>(We2, att2, bias2, g2, be2);

    // policy head (fused final projection)
    k_gemm_pol<<<(Nn+63)/64, 256>>>(Wp1, bp1, Wp2, bp2);

    // global softmax (two-phase)
    k_red1<<<NRED, 256>>>();
    k_out<<<(Nn*4+TB-1)/TB, TB>>>(out);
}

// round 12
// speedup vs baseline: 1.2982x; 1.2069x over previous
#include <cuda_runtime.h>
#include <cuda_fp16.h>
#include <mma.h>
using namespace nvcuda;

#define Nn   10000
#define Ne   320000
#define EAt  330000      // edges + self loops
#define HID  256
#define NRED 20          // partial-reduction blocks for final softmax

// ---------------- scratch (static device globals; zero-initialized at load) ------
__device__ float    g_loop[Nn];
__device__ int      g_cnt[Nn];
__device__ int      g_row[Nn+1];
__device__ int      g_woff[Nn];
__device__ int2     g_ced[EAt];        // (src, edge_attr bits)
__device__ __half2  g_xlh[Nn*128];     // fp16 xl feature table (edge-gathered)
__device__ __half2  g_hh[Nn*128];      // fp16 conv1 output (GEMM A operand)
__device__ float    g_xr[Nn*HID];
__device__ float    g_h[Nn*HID];       // fp32 conv2 output (policy GEMM A operand)
__device__ float    g_pl[Nn*4];
__device__ float    g_pmax[NRED];
__device__ float    g_psum[NRED];

__device__ __forceinline__ float lrelu(float v){ return v > 0.f ? v : 0.2f * v; }

__device__ __forceinline__ float dot8(float4 l0, float4 l1, float4 r0, float4 r1,
                                      float ev, float4 w0, float4 w1,
                                      float4 t0, float4 t1){
    float p = 0.f;
    p += lrelu(l0.x + r0.x + ev*w0.x) * t0.x;
    p += lrelu(l0.y + r0.y + ev*w0.y) * t0.y;
    p += lrelu(l0.z + r0.z + ev*w0.z) * t0.z;
    p += lrelu(l0.w + r0.w + ev*w0.w) * t0.w;
    p += lrelu(l1.x + r1.x + ev*w1.x) * t1.x;
    p += lrelu(l1.y + r1.y + ev*w1.y) * t1.y;
    p += lrelu(l1.z + r1.z + ev*w1.z) * t1.z;
    p += lrelu(l1.w + r1.w + ev*w1.w) * t1.w;
    return p;
}

// load 8 fp16 channels (one 16B load) -> two float4
__device__ __forceinline__ void ldh8(const __half2* base, float4& lo, float4& hi){
    uint4 raw = *(const uint4*)base;
    float2 f0 = __half22float2(*(__half2*)&raw.x);
    float2 f1 = __half22float2(*(__half2*)&raw.y);
    float2 f2 = __half22float2(*(__half2*)&raw.z);
    float2 f3 = __half22float2(*(__half2*)&raw.w);
    lo = make_float4(f0.x, f0.y, f1.x, f1.y);
    hi = make_float4(f2.x, f2.y, f3.x, f3.y);
}

// ---------------- kernel 1: edge histogram (+loop attr sum)  ||  lin1 ----------------
#define HB 1250   // (Ne+255)/256
__global__ void k_hist_lin1(const int* __restrict__ dst, const float* __restrict__ ea,
                            const float* __restrict__ x,
                            const float* __restrict__ Wl, const float* __restrict__ bl,
                            const float* __restrict__ Wr, const float* __restrict__ br){
    int b = blockIdx.x;
    if(b < HB){
        int e = b*256 + threadIdx.x;
        if(e < Ne){
            int d = dst[e];
            atomicAdd(&g_cnt[d], 1);
            atomicAdd(&g_loop[d], ea[e]);
        }
    } else {
        int t = (b - HB)*256 + threadIdx.x;
        if(t < Nn*64){
            int n = t >> 6, c4 = (t & 63) << 2;
            float4 xv = *(const float4*)(x + n*4);
            float4 l = *(const float4*)(bl + c4);
            float4 r = *(const float4*)(br + c4);
            float4 w;
            w = *(const float4*)(Wl + 0*256 + c4); l.x+=xv.x*w.x; l.y+=xv.x*w.y; l.z+=xv.x*w.z; l.w+=xv.x*w.w;
            w = *(const float4*)(Wl + 1*256 + c4); l.x+=xv.y*w.x; l.y+=xv.y*w.y; l.z+=xv.y*w.z; l.w+=xv.y*w.w;
            w = *(const float4*)(Wl + 2*256 + c4); l.x+=xv.z*w.x; l.y+=xv.z*w.y; l.z+=xv.z*w.z; l.w+=xv.z*w.w;
            w = *(const float4*)(Wl + 3*256 + c4); l.x+=xv.w*w.x; l.y+=xv.w*w.y; l.z+=xv.w*w.z; l.w+=xv.w*w.w;
            w = *(const float4*)(Wr + 0*256 + c4); r.x+=xv.x*w.x; r.y+=xv.x*w.y; r.z+=xv.x*w.z; r.w+=xv.x*w.w;
            w = *(const float4*)(Wr + 1*256 + c4); r.x+=xv.y*w.x; r.y+=xv.y*w.y; r.z+=xv.y*w.z; r.w+=xv.y*w.w;
            w = *(const float4*)(Wr + 2*256 + c4); r.x+=xv.z*w.x; r.y+=xv.z*w.y; r.z+=xv.z*w.z; r.w+=xv.z*w.w;
            w = *(const float4*)(Wr + 3*256 + c4); r.x+=xv.w*w.x; r.y+=xv.w*w.y; r.z+=xv.w*w.z; r.w+=xv.w*w.w;
            __half2 h0 = __floats2half2_rn(l.x, l.y);
            __half2 h1 = __floats2half2_rn(l.z, l.w);
            __half2* dst2 = g_xlh + n*128 + (c4 >> 1);
            dst2[0] = h0; dst2[1] = h1;
            *(float4*)(g_xr + n*256 + c4) = r;
        }
    }
}

// ---------------- kernel 2: scan + prep (single block) ----------------
__global__ void k_scanprep(){
    __shared__ int part[1024];
    const int NP = 10;
    int tid = threadIdx.x;
    int base = tid * NP;
    int cnt[NP], loc[NP];
    int s = 0;
    #pragma unroll
    for(int i = 0; i < NP; i++){
        int idx = base + i;
        int c = (idx < Nn) ? g_cnt[idx] : 0;
        cnt[i] = c;
        loc[i] = s;
        s += (idx < Nn) ? (c + 1) : 0;
    }
    part[tid] = s; __syncthreads();
    for(int o = 1; o < 1024; o <<= 1){
        int v = (tid >= o) ? part[tid - o] : 0;
        __syncthreads();
        if(tid >= o) part[tid] += v;
        __syncthreads();
    }
    int off = (tid > 0) ? part[tid - 1] : 0;
    #pragma unroll
    for(int i = 0; i < NP; i++){
        int idx = base + i;
        if(idx < Nn){
            int rs = off + loc[i];
            int re = rs + cnt[i] + 1;
            g_row[idx] = rs;
            if(idx == Nn-1) g_row[Nn] = re;
            float lp = g_loop[idx] / fmaxf((float)cnt[i], 1.f);
            g_ced[re-1] = make_int2(idx, __float_as_int(lp));
            g_woff[idx] = rs;
        }
    }
}

// ---------------- kernel 3: scatter edges into CSR ----------------
__global__ void k_scatter(const int* __restrict__ src, const int* __restrict__ dst,
                          const float* __restrict__ ea){
    int e = blockIdx.x*blockDim.x + threadIdx.x;
    if(e >= Ne) return;
    int d = dst[e];
    int pos = atomicAdd(&g_woff[d], 1);
    g_ced[pos] = make_int2(src[e], __float_as_int(ea[e]));
}

// ---------------- fused conv1 (low-rank aggregation; fp16 gathers; fp16 out) -----
__global__ void __launch_bounds__(32) k_conv1lr(
        const float* __restrict__ x,
        const float* __restrict__ Wl, const float* __restrict__ bl,
        const float* __restrict__ We, const float* __restrict__ att,
        const float* __restrict__ bias, const float* __restrict__ gam,
        const float* __restrict__ bet){
    int n = blockIdx.x;
    int lane = threadIdx.x;
    int c0 = lane * 8;
    const float4* pr = (const float4*)(g_xr + n*HID + c0);
    float4 r0 = pr[0], r1 = pr[1];
    float4 w0 = *(const float4*)(We + c0),  w1 = *(const float4*)(We + c0 + 4);
    float4 t0 = *(const float4*)(att + c0), t1 = *(const float4*)(att + c0 + 4);
    int j = lane & 3;
    float acc1 = 0.f, den = 0.f;
    int b = g_row[n], e = g_row[n+1];
    int i = b;
    for(; i + 1 < e; i += 2){
        int2 ed0 = g_ced[i], ed1 = g_ced[i+1];
        float ev0 = __int_as_float(ed0.y), ev1 = __int_as_float(ed1.y);
        float4 a0, a1, b0, b1;
        ldh8(g_xlh + ed0.x*128 + lane*4, a0, a1);
        ldh8(g_xlh + ed1.x*128 + lane*4, b0, b1);
        float xs0 = x[ed0.x*4 + j];
        float xs1 = x[ed1.x*4 + j];
        float p0 = dot8(a0, a1, r0, r1, ev0, w0, w1, t0, t1);
        float p1 = dot8(b0, b1, r0, r1, ev1, w0, w1, t0, t1);
        #pragma unroll
        for(int o = 0; o < 3; o++){
            p0 += __shfl_xor_sync(0xffffffffu, p0, 1 << o);
            p1 += __shfl_xor_sync(0xffffffffu, p1, 1 << o);
        }
        float e0 = __expf(p0);
        float e1 = __expf(p1);
        den += e0 + e1;
        acc1 += xs0*e0 + xs1*e1;
    }
    if(i < e){
        int2 ed0 = g_ced[i];
        float ev0 = __int_as_float(ed0.y);
        float4 a0, a1;
        ldh8(g_xlh + ed0.x*128 + lane*4, a0, a1);
        float xs0 = x[ed0.x*4 + j];
        float p0 = dot8(a0, a1, r0, r1, ev0, w0, w1, t0, t1);
        #pragma unroll
        for(int o = 0; o < 3; o++)
            p0 += __shfl_xor_sync(0xffffffffu, p0, 1 << o);
        float e0 = __expf(p0);
        den += e0;
        acc1 += xs0*e0;
    }
    float inv = 1.f / den;
    int h8 = lane & 24;
    float ax0 = __shfl_sync(0xffffffffu, acc1, h8+0) * inv;
    float ax1 = __shfl_sync(0xffffffffu, acc1, h8+1) * inv;
    float ax2 = __shfl_sync(0xffffffffu, acc1, h8+2) * inv;
    float ax3 = __shfl_sync(0xffffffffu, acc1, h8+3) * inv;
    float4 wr0A = *(const float4*)(Wl + 0*256 + c0), wr0B = *(const float4*)(Wl + 0*256 + c0 + 4);
    float4 wr1A = *(const float4*)(Wl + 1*256 + c0), wr1B = *(const float4*)(Wl + 1*256 + c0 + 4);
    float4 wr2A = *(const float4*)(Wl + 2*256 + c0), wr2B = *(const float4*)(Wl + 2*256 + c0 + 4);
    float4 wr3A = *(const float4*)(Wl + 3*256 + c0), wr3B = *(const float4*)(Wl + 3*256 + c0 + 4);
    float4 blA = *(const float4*)(bl + c0),   blB = *(const float4*)(bl + c0 + 4);
    float4 biA = *(const float4*)(bias + c0), biB = *(const float4*)(bias + c0 + 4);
    float v[8];
    v[0] = ax0*wr0A.x + ax1*wr1A.x + ax2*wr2A.x + ax3*wr3A.x + blA.x + biA.x;
    v[1] = ax0*wr0A.y + ax1*wr1A.y + ax2*wr2A.y + ax3*wr3A.y + blA.y + biA.y;
    v[2] = ax0*wr0A.z + ax1*wr1A.z + ax2*wr2A.z + ax3*wr3A.z + blA.z + biA.z;
    v[3] = ax0*wr0A.w + ax1*wr1A.w + ax2*wr2A.w + ax3*wr3A.w + blA.w + biA.w;
    v[4] = ax0*wr0B.x + ax1*wr1B.x + ax2*wr2B.x + ax3*wr3B.x + blB.x + biB.x;
    v[5] = ax0*wr0B.y + ax1*wr1B.y + ax2*wr2B.y + ax3*wr3B.y + blB.y + biB.y;
    v[6] = ax0*wr0B.z + ax1*wr1B.z + ax2*wr2B.z + ax3*wr3B.z + blB.z + biB.z;
    v[7] = ax0*wr0B.w + ax1*wr1B.w + ax2*wr2B.w + ax3*wr3B.w + blB.w + biB.w;
    float s = 0.f;
    #pragma unroll
    for(int k = 0; k < 8; k++) s += v[k];
    #pragma unroll
    for(int o = 16; o; o >>= 1) s += __shfl_xor_sync(0xffffffffu, s, o);
    float mu = s * (1.f/256.f);
    float q = 0.f;
    #pragma unroll
    for(int k = 0; k < 8; k++){ float dd = v[k]-mu; q += dd*dd; }
    #pragma unroll
    for(int o = 16; o; o >>= 1) q += __shfl_xor_sync(0xffffffffu, q, o);
    float rstd = rsqrtf(q*(1.f/256.f) + 1e-5f);
    float4 gA = *(const float4*)(gam + c0), gB = *(const float4*)(gam + c0 + 4);
    float4 eA = *(const float4*)(bet + c0), eB = *(const float4*)(bet + c0 + 4);
    float gv[8] = {gA.x,gA.y,gA.z,gA.w,gB.x,gB.y,gB.z,gB.w};
    float ev[8] = {eA.x,eA.y,eA.z,eA.w,eB.x,eB.y,eB.z,eB.w};
    float o0[8];
    #pragma unroll
    for(int k = 0; k < 8; k++)
        o0[k] = fmaxf((v[k]-mu)*rstd*gv[k] + ev[k], 0.f);
    // fp16 output only (consumed by the fp16 tensor-core GEMM)
    __half2* dh = g_hh + n*128 + lane*4;
    dh[0] = __floats2half2_rn(o0[0], o0[1]);
    dh[1] = __floats2half2_rn(o0[2], o0[3]);
    dh[2] = __floats2half2_rn(o0[4], o0[5]);
    dh[3] = __floats2half2_rn(o0[6], o0[7]);
}

// ---------------- fused conv2 (H=1, C=256): fp16 gathers, fp32 accumulate --------
__global__ void __launch_bounds__(32) k_conv2(
        const float* __restrict__ We, const float* __restrict__ att,
        const float* __restrict__ bias, const float* __restrict__ gam,
        const float* __restrict__ bet){
    int n = blockIdx.x;
    int lane = threadIdx.x;
    int c0 = lane * 8;
    const float4* pr = (const float4*)(g_xr + n*HID + c0);
    float4 r0 = pr[0], r1 = pr[1];
    float4 w0 = *(const float4*)(We + c0),  w1 = *(const float4*)(We + c0 + 4);
    float4 t0 = *(const float4*)(att + c0), t1 = *(const float4*)(att + c0 + 4);
    float acc[8] = {0,0,0,0,0,0,0,0};
    float den = 0.f;
    int b = g_row[n], e = g_row[n+1];
    int i = b;
    for(; i + 1 < e; i += 2){
        int2 ed0 = g_ced[i], ed1 = g_ced[i+1];
        float ev0 = __int_as_float(ed0.y), ev1 = __int_as_float(ed1.y);
        float4 a0, a1, b0, b1;
        ldh8(g_xlh + ed0.x*128 + lane*4, a0, a1);
        ldh8(g_xlh + ed1.x*128 + lane*4, b0, b1);
        float p0 = dot8(a0, a1, r0, r1, ev0, w0, w1, t0, t1);
        float p1 = dot8(b0, b1, r0, r1, ev1, w0, w1, t0, t1);
        #pragma unroll
        for(int o = 0; o < 5; o++){
            p0 += __shfl_xor_sync(0xffffffffu, p0, 1 << o);
            p1 += __shfl_xor_sync(0xffffffffu, p1, 1 << o);
        }
        float e0 = __expf(p0);
        float e1 = __expf(p1);
        den += e0 + e1;
        acc[0] += a0.x*e0 + b0.x*e1; acc[1] += a0.y*e0 + b0.y*e1;
        acc[2] += a0.z*e0 + b0.z*e1; acc[3] += a0.w*e0 + b0.w*e1;
        acc[4] += a1.x*e0 + b1.x*e1; acc[5] += a1.y*e0 + b1.y*e1;
        acc[6] += a1.z*e0 + b1.z*e1; acc[7] += a1.w*e0 + b1.w*e1;
    }
    if(i < e){
        int2 ed0 = g_ced[i];
        float ev0 = __int_as_float(ed0.y);
        float4 a0, a1;
        ldh8(g_xlh + ed0.x*128 + lane*4, a0, a1);
        float p0 = dot8(a0, a1, r0, r1, ev0, w0, w1, t0, t1);
        #pragma unroll
        for(int o = 0; o < 5; o++)
            p0 += __shfl_xor_sync(0xffffffffu, p0, 1 << o);
        float e0 = __expf(p0);
        den += e0;
        acc[0] += a0.x*e0; acc[1] += a0.y*e0;
        acc[2] += a0.z*e0; acc[3] += a0.w*e0;
        acc[4] += a1.x*e0; acc[5] += a1.y*e0;
        acc[6] += a1.z*e0; acc[7] += a1.w*e0;
    }
    float inv = 1.f / den;
    float4 biA = *(const float4*)(bias + c0), biB = *(const float4*)(bias + c0 + 4);
    float bi[8] = {biA.x,biA.y,biA.z,biA.w,biB.x,biB.y,biB.z,biB.w};
    float v[8];
    float s = 0.f;
    #pragma unroll
    for(int k = 0; k < 8; k++){ v[k] = acc[k]*inv + bi[k]; s += v[k]; }
    #pragma unroll
    for(int o = 16; o; o >>= 1) s += __shfl_xor_sync(0xffffffffu, s, o);
    float mu = s * (1.f/256.f);
    float q = 0.f;
    #pragma unroll
    for(int k = 0; k < 8; k++){ float dd = v[k]-mu; q += dd*dd; }
    #pragma unroll
    for(int o = 16; o; o >>= 1) q += __shfl_xor_sync(0xffffffffu, q, o);
    float rstd = rsqrtf(q*(1.f/256.f) + 1e-5f);
    float4 gA = *(const float4*)(gam + c0), gB = *(const float4*)(gam + c0 + 4);
    float4 eA = *(const float4*)(bet + c0), eB = *(const float4*)(bet + c0 + 4);
    float gv[8] = {gA.x,gA.y,gA.z,gA.w,gB.x,gB.y,gB.z,gB.w};
    float evv[8] = {eA.x,eA.y,eA.z,eA.w,eB.x,eB.y,eB.z,eB.w};
    float o0[8];
    #pragma unroll
    for(int k = 0; k < 8; k++)
        o0[k] = fmaxf((v[k]-mu)*rstd*gv[k] + evv[k], 0.f);
    *(float4*)(g_h + n*HID + c0)     = make_float4(o0[0],o0[1],o0[2],o0[3]);
    *(float4*)(g_h + n*HID + c0 + 4) = make_float4(o0[4],o0[5],o0[6],o0[7]);
}

// ---------------- dual GEMM: fp16 tensor cores (m16n16k16, fp32 accum) ----------
// A = g_hh[Nn,256] (fp16), B = W (fp32->fp16 staged). xl -> g_xlh (fp16), xr -> fp32.
__global__ void __launch_bounds__(128) k_gemm_dual(
        const float* __restrict__ Wl, const float* __restrict__ bl,
        const float* __restrict__ Wr, const float* __restrict__ br){
    __shared__ __align__(16) __half As[64][40];
    __shared__ __align__(16) __half Bs[32][72];
    __shared__ __align__(16) float  Cs[64][68];
    int half_ = blockIdx.x >> 2;
    int nblk = blockIdx.x & 3;
    const float* B    = half_ ? Wr : Wl;
    const float* bias = half_ ? br : bl;
    int m0 = blockIdx.y*64, n0 = nblk*64;
    int t = threadIdx.x;
    int warp = t >> 5, wy = warp >> 1, wx = warp & 1;

    wmma::fragment<wmma::accumulator,16,16,16,float> acc[2][2];
    #pragma unroll
    for(int i = 0; i < 2; i++)
        #pragma unroll
        for(int jj = 0; jj < 2; jj++)
            wmma::fill_fragment(acc[i][jj], 0.f);

    int arow = t >> 1, aseg = t & 1;          // A: 64 rows x 32 halfs per chunk
    int brow = t >> 2, bcol = (t & 3) * 16;   // B: 32 rows x 64 floats per chunk
    for(int k0 = 0; k0 < 256; k0 += 32){
        int gm = m0 + arow;
        uint4 z4 = make_uint4(0,0,0,0);
        const uint4* srcA = (const uint4*)(g_hh + gm*128 + (k0 >> 1) + aseg*8);
        uint4 av0 = (gm < Nn) ? srcA[0] : z4;
        uint4 av1 = (gm < Nn) ? srcA[1] : z4;
        *(uint4*)&As[arow][aseg*16]     = av0;
        *(uint4*)&As[arow][aseg*16 + 8] = av1;
        const float4* srcB = (const float4*)(B + (k0+brow)*256 + n0 + bcol);
        float4 f0 = srcB[0], f1 = srcB[1], f2 = srcB[2], f3 = srcB[3];
        __half2* db = (__half2*)&Bs[brow][bcol];
        db[0] = __floats2half2_rn(f0.x,f0.y); db[1] = __floats2half2_rn(f0.z,f0.w);
        db[2] = __floats2half2_rn(f1.x,f1.y); db[3] = __floats2half2_rn(f1.z,f1.w);
        db[4] = __floats2half2_rn(f2.x,f2.y); db[5] = __floats2half2_rn(f2.z,f2.w);
        db[6] = __floats2half2_rn(f3.x,f3.y); db[7] = __floats2half2_rn(f3.z,f3.w);
        __syncthreads();
        #pragma unroll
        for(int ks = 0; ks < 2; ks++){
            wmma::fragment<wmma::matrix_a,16,16,16,__half,wmma::row_major> af[2];
            wmma::fragment<wmma::matrix_b,16,16,16,__half,wmma::row_major> bf[2];
            #pragma unroll
            for(int i = 0; i < 2; i++)
                wmma::load_matrix_sync(af[i], &As[wy*32 + i*16][ks*16], 40);
            #pragma unroll
            for(int jj = 0; jj < 2; jj++)
                wmma::load_matrix_sync(bf[jj], &Bs[ks*16][wx*32 + jj*16], 72);
            #pragma unroll
            for(int i = 0; i < 2; i++)
                #pragma unroll
                for(int jj = 0; jj < 2; jj++)
                    wmma::mma_sync(acc[i][jj], af[i], bf[jj], acc[i][jj]);
        }
        __syncthreads();
    }
    #pragma unroll
    for(int i = 0; i < 2; i++)
        #pragma unroll
        for(int jj = 0; jj < 2; jj++)
            wmma::store_matrix_sync(&Cs[wy*32 + i*16][wx*32 + jj*16], acc[i][jj], 68, wmma::mem_row_major);
    __syncthreads();
    // epilogue: bias add; xr -> fp32, xl -> fp16 table
    for(int idx = t; idx < 64*16; idx += 128){
        int row = idx >> 4;
        int c4 = (idx & 15) * 4;
        int gm = m0 + row;
        if(gm >= Nn) continue;
        float4 v = *(float4*)&Cs[row][c4];
        float4 bv = *(const float4*)(bias + n0 + c4);
        v.x += bv.x; v.y += bv.y; v.z += bv.z; v.w += bv.w;
        if(half_){
            *(float4*)(g_xr + gm*256 + n0 + c4) = v;
        } else {
            __half2* d2 = g_xlh + gm*128 + ((n0 + c4) >> 1);
            d2[0] = __floats2half2_rn(v.x, v.y);
            d2[1] = __floats2half2_rn(v.z, v.w);
        }
    }
}

// ---------------- policy GEMM (fp32 mainloop) + fused final projection ----------
__global__ void k_gemm_pol(const float* __restrict__ Wp1, const float* __restrict__ bp1,
                           const float* __restrict__ Wp2, const float* __restrict__ bp2){
    __shared__ __align__(16) float As[16][68];
    __shared__ __align__(16) float Bs[16][132];
    int m0 = blockIdx.x * 64;
    int t = threadIdx.x;
    int tx = t & 15, ty = t >> 4;
    int ar = t >> 2, ak = (t & 3) * 4;
    int br_ = t >> 4, bc = (t & 15) * 8;
    float acc[4][8] = {};
    for(int k0 = 0; k0 < 256; k0 += 16){
        float4 av = make_float4(0.f,0.f,0.f,0.f);
        int gm = m0 + ar;
        if(gm < Nn) av = *(const float4*)(g_h + gm*256 + k0 + ak);
        As[ak+0][ar] = av.x; As[ak+1][ar] = av.y;
        As[ak+2][ar] = av.z; As[ak+3][ar] = av.w;
        *(float4*)&Bs[br_][bc]   = *(const float4*)(Wp1 + (k0+br_)*128 + bc);
        *(float4*)&Bs[br_][bc+4] = *(const float4*)(Wp1 + (k0+br_)*128 + bc + 4);
        __syncthreads();
        #pragma unroll
        for(int kk = 0; kk < 16; kk++){
            float4 a = *(float4*)&As[kk][ty*4];
            float4 b0 = *(float4*)&Bs[kk][tx*8];
            float4 b1 = *(float4*)&Bs[kk][tx*8+4];
            float av4[4] = {a.x,a.y,a.z,a.w};
            float bv[8] = {b0.x,b0.y,b0.z,b0.w,b1.x,b1.y,b1.z,b1.w};
            #pragma unroll
            for(int i = 0; i < 4; i++)
                #pragma unroll
                for(int j = 0; j < 8; j++)
                    acc[i][j] += av4[i]*bv[j];
        }
        __syncthreads();
    }
    float4 bpA = *(const float4*)(bp1 + tx*8);
    float4 bpB = *(const float4*)(bp1 + tx*8 + 4);
    float bb[8] = {bpA.x,bpA.y,bpA.z,bpA.w,bpB.x,bpB.y,bpB.z,bpB.w};
    float4 wv[8];
    const float4* wp = (const float4*)(Wp2 + tx*32);
    #pragma unroll
    for(int j = 0; j < 8; j++) wv[j] = wp[j];
    float part[4][4];
    #pragma unroll
    for(int i = 0; i < 4; i++){
        part[i][0] = part[i][1] = part[i][2] = part[i][3] = 0.f;
        bool ok = (m0 + ty*4 + i) < Nn;
        #pragma unroll
        for(int j = 0; j < 8; j++){
            float v0 = ok ? fmaxf(acc[i][j] + bb[j], 0.f) : 0.f;
            part[i][0] += v0*wv[j].x;
            part[i][1] += v0*wv[j].y;
            part[i][2] += v0*wv[j].z;
            part[i][3] += v0*wv[j].w;
        }
    }
    #pragma unroll
    for(int i = 0; i < 4; i++)
        #pragma unroll
        for(int c = 0; c < 4; c++){
            #pragma unroll
            for(int o = 1; o < 16; o <<= 1)
                part[i][c] += __shfl_xor_sync(0xffffffffu, part[i][c], o);
        }
    if(tx == 0){
        #pragma unroll
        for(int i = 0; i < 4; i++){
            int gm = m0 + ty*4 + i;
            if(gm < Nn){
                float4 r4 = make_float4(part[i][0]+bp2[0], part[i][1]+bp2[1],
                                        part[i][2]+bp2[2], part[i][3]+bp2[3]);
                *(float4*)(g_pl + gm*4) = r4;
            }
        }
    }
}

// ---------------- two-phase global softmax over 40000 logits ----------------
__global__ void k_red1(){
    __shared__ float sm[256];
    int bid = blockIdx.x, tid = threadIdx.x;
    const int chunk = (Nn*4 + NRED - 1) / NRED;
    int lo = bid*chunk, hi = min(lo + chunk, Nn*4);
    float m = -3.4e38f;
    for(int i = lo + tid; i < hi; i += 256) m = fmaxf(m, g_pl[i]);
    sm[tid] = m; __syncthreads();
    for(int o = 128; o > 0; o >>= 1){ if(tid < o) sm[tid] = fmaxf(sm[tid], sm[tid+o]); __syncthreads(); }
    float mx = sm[0]; __syncthreads();
    float s = 0.f;
    for(int i = lo + tid; i < hi; i += 256) s += __expf(g_pl[i] - mx);
    sm[tid] = s; __syncthreads();
    for(int o = 128; o > 0; o >>= 1){ if(tid < o) sm[tid] += sm[tid+o]; __syncthreads(); }
    if(tid == 0){ g_pmax[bid] = mx; g_psum[bid] = sm[0]; }
}
// output (combines the NRED partials in-block) + restore state for next replay
__global__ void k_out(float* __restrict__ out){
    __shared__ float sMS[2];
    if(threadIdx.x == 0){
        float M = -3.4e38f;
        #pragma unroll
        for(int j = 0; j < NRED; j++) M = fmaxf(M, g_pmax[j]);
        float S = 0.f;
        #pragma unroll
        for(int j = 0; j < NRED; j++) S += g_psum[j] * __expf(g_pmax[j] - M);
        sMS[0] = M; sMS[1] = 1.f / S;
    }
    __syncthreads();
    int i = blockIdx.x*blockDim.x + threadIdx.x;
    if(i < Nn*4) out[i] = __expf(g_pl[i] - sMS[0]) * sMS[1];
    if(i < Nn){ g_cnt[i] = 0; g_loop[i] = 0.f; }
}

// ---------------- launch ----------------
extern "C" void kernel_launch(void* const* d_in, const int* in_sizes, int n_in,
                              void* d_out, int out_size){
    const float* x     = (const float*)d_in[0];
    const int*   ei    = (const int*)  d_in[1];
    const float* ea    = (const float*)d_in[2];
    const float* Wl1   = (const float*)d_in[3];
    const float* bl1   = (const float*)d_in[4];
    const float* Wr1   = (const float*)d_in[5];
    const float* br1   = (const float*)d_in[6];
    const float* We1   = (const float*)d_in[7];
    const float* att1  = (const float*)d_in[8];
    const float* bias1 = (const float*)d_in[9];
    const float* g1    = (const float*)d_in[10];
    const float* be1   = (const float*)d_in[11];
    const float* Wl2   = (const float*)d_in[12];
    const float* bl2   = (const float*)d_in[13];
    const float* Wr2   = (const float*)d_in[14];
    const float* br2   = (const float*)d_in[15];
    const float* We2   = (const float*)d_in[16];
    const float* att2  = (const float*)d_in[17];
    const float* bias2 = (const float*)d_in[18];
    const float* g2    = (const float*)d_in[19];
    const float* be2   = (const float*)d_in[20];
    const float* Wp1   = (const float*)d_in[21];
    const float* bp1   = (const float*)d_in[22];
    const float* Wp2   = (const float*)d_in[23];
    const float* bp2   = (const float*)d_in[24];
    const int* src = ei;
    const int* dst = ei + Ne;
    float* out = (float*)d_out;

    const int TB = 256;

    // CSR build + conv1 linear (merged)
    k_hist_lin1<<<HB + (Nn*64+TB-1)/TB, TB>>>(dst, ea, x, Wl1, bl1, Wr1, br1);
    k_scanprep<<<1, 1024>>>();
    k_scatter<<<(Ne+TB-1)/TB, TB>>>(src, dst, ea);

    // conv1 (low-rank aggregation) — one warp-block per node
    k_conv1lr<<<Nn, 32>>>(x, Wl1, bl1, We1, att1, bias1, g1, be1);

    // conv2 (fp16 tensor-core dual GEMM)
    k_gemm_dual<<<dim3(8, (Nn+63)/64), 128>>>(Wl2, bl2, Wr2, br2);
    k_conv2<<<Nn, 32>>>(We2, att2, bias2, g2, be2);

    // policy head (fused final projection)
    k_gemm_pol<<<(Nn+63)/64, 256>>>(Wp1, bp1, Wp2, bp2);

    // global softmax (two-phase)
    k_red1<<<NRED, 256>>>();
    k_out<<<(Nn*4+TB-1)/TB, TB>>>(out);
}

// round 13
// speedup vs baseline: 1.5098x; 1.1630x over previous
#include <cuda_runtime.h>
#include <cuda_fp16.h>
#include <mma.h>
using namespace nvcuda;

#define Nn   10000
#define Ne   320000
#define EAt  330000      // edges + self loops
#define HID  256
#define NRED 20          // partial-reduction blocks for final softmax

// ---------------- scratch (static device globals; zero-initialized at load) ------
__device__ float    g_loop[Nn];
__device__ int      g_cnt[Nn];
__device__ int      g_row[Nn+1];
__device__ int      g_woff[Nn];
__device__ int2     g_ced[EAt];        // (src, edge_attr bits)
__device__ __half2  g_xlh[Nn*128];     // fp16 xl feature table (edge-gathered)
__device__ __half2  g_hh[Nn*128];      // fp16 activations: conv1 out, then conv2 out
__device__ float    g_xr[Nn*HID];
__device__ float    g_pl[Nn*4];
__device__ float    g_pmax[NRED];
__device__ float    g_psum[NRED];

__device__ __forceinline__ float lrelu(float v){ return v > 0.f ? v : 0.2f * v; }

__device__ __forceinline__ float dot8(float4 l0, float4 l1, float4 r0, float4 r1,
                                      float ev, float4 w0, float4 w1,
                                      float4 t0, float4 t1){
    float p = 0.f;
    p += lrelu(l0.x + r0.x + ev*w0.x) * t0.x;
    p += lrelu(l0.y + r0.y + ev*w0.y) * t0.y;
    p += lrelu(l0.z + r0.z + ev*w0.z) * t0.z;
    p += lrelu(l0.w + r0.w + ev*w0.w) * t0.w;
    p += lrelu(l1.x + r1.x + ev*w1.x) * t1.x;
    p += lrelu(l1.y + r1.y + ev*w1.y) * t1.y;
    p += lrelu(l1.z + r1.z + ev*w1.z) * t1.z;
    p += lrelu(l1.w + r1.w + ev*w1.w) * t1.w;
    return p;
}

// load 8 fp16 channels (one 16B load) -> two float4
__device__ __forceinline__ void ldh8(const __half2* base, float4& lo, float4& hi){
    uint4 raw = *(const uint4*)base;
    float2 f0 = __half22float2(*(__half2*)&raw.x);
    float2 f1 = __half22float2(*(__half2*)&raw.y);
    float2 f2 = __half22float2(*(__half2*)&raw.z);
    float2 f3 = __half22float2(*(__half2*)&raw.w);
    lo = make_float4(f0.x, f0.y, f1.x, f1.y);
    hi = make_float4(f2.x, f2.y, f3.x, f3.y);
}

// ---------------- kernel 1: edge histogram (+loop attr sum)  ||  lin1 ----------------
#define HB 1250   // (Ne+255)/256
__global__ void k_hist_lin1(const int* __restrict__ dst, const float* __restrict__ ea,
                            const float* __restrict__ x,
                            const float* __restrict__ Wl, const float* __restrict__ bl,
                            const float* __restrict__ Wr, const float* __restrict__ br){
    int b = blockIdx.x;
    if(b < HB){
        int e = b*256 + threadIdx.x;
        if(e < Ne){
            int d = dst[e];
            atomicAdd(&g_cnt[d], 1);
            atomicAdd(&g_loop[d], ea[e]);
        }
    } else {
        int t = (b - HB)*256 + threadIdx.x;
        if(t < Nn*64){
            int n = t >> 6, c4 = (t & 63) << 2;
            float4 xv = *(const float4*)(x + n*4);
            float4 l = *(const float4*)(bl + c4);
            float4 r = *(const float4*)(br + c4);
            float4 w;
            w = *(const float4*)(Wl + 0*256 + c4); l.x+=xv.x*w.x; l.y+=xv.x*w.y; l.z+=xv.x*w.z; l.w+=xv.x*w.w;
            w = *(const float4*)(Wl + 1*256 + c4); l.x+=xv.y*w.x; l.y+=xv.y*w.y; l.z+=xv.y*w.z; l.w+=xv.y*w.w;
            w = *(const float4*)(Wl + 2*256 + c4); l.x+=xv.z*w.x; l.y+=xv.z*w.y; l.z+=xv.z*w.z; l.w+=xv.z*w.w;
            w = *(const float4*)(Wl + 3*256 + c4); l.x+=xv.w*w.x; l.y+=xv.w*w.y; l.z+=xv.w*w.z; l.w+=xv.w*w.w;
            w = *(const float4*)(Wr + 0*256 + c4); r.x+=xv.x*w.x; r.y+=xv.x*w.y; r.z+=xv.x*w.z; r.w+=xv.x*w.w;
            w = *(const float4*)(Wr + 1*256 + c4); r.x+=xv.y*w.x; r.y+=xv.y*w.y; r.z+=xv.y*w.z; r.w+=xv.y*w.w;
            w = *(const float4*)(Wr + 2*256 + c4); r.x+=xv.z*w.x; r.y+=xv.z*w.y; r.z+=xv.z*w.z; r.w+=xv.z*w.w;
            w = *(const float4*)(Wr + 3*256 + c4); r.x+=xv.w*w.x; r.y+=xv.w*w.y; r.z+=xv.w*w.z; r.w+=xv.w*w.w;
            __half2 h0 = __floats2half2_rn(l.x, l.y);
            __half2 h1 = __floats2half2_rn(l.z, l.w);
            __half2* dst2 = g_xlh + n*128 + (c4 >> 1);
            dst2[0] = h0; dst2[1] = h1;
            *(float4*)(g_xr + n*256 + c4) = r;
        }
    }
}

// ---------------- kernel 2: scan + prep (single block) ----------------
__global__ void k_scanprep(){
    __shared__ int part[1024];
    const int NP = 10;
    int tid = threadIdx.x;
    int base = tid * NP;
    int cnt[NP], loc[NP];
    int s = 0;
    #pragma unroll
    for(int i = 0; i < NP; i++){
        int idx = base + i;
        int c = (idx < Nn) ? g_cnt[idx] : 0;
        cnt[i] = c;
        loc[i] = s;
        s += (idx < Nn) ? (c + 1) : 0;
    }
    part[tid] = s; __syncthreads();
    for(int o = 1; o < 1024; o <<= 1){
        int v = (tid >= o) ? part[tid - o] : 0;
        __syncthreads();
        if(tid >= o) part[tid] += v;
        __syncthreads();
    }
    int off = (tid > 0) ? part[tid - 1] : 0;
    #pragma unroll
    for(int i = 0; i < NP; i++){
        int idx = base + i;
        if(idx < Nn){
            int rs = off + loc[i];
            int re = rs + cnt[i] + 1;
            g_row[idx] = rs;
            if(idx == Nn-1) g_row[Nn] = re;
            float lp = g_loop[idx] / fmaxf((float)cnt[i], 1.f);
            g_ced[re-1] = make_int2(idx, __float_as_int(lp));
            g_woff[idx] = rs;
        }
    }
}

// ---------------- kernel 3: scatter edges into CSR ----------------
__global__ void k_scatter(const int* __restrict__ src, const int* __restrict__ dst,
                          const float* __restrict__ ea){
    int e = blockIdx.x*blockDim.x + threadIdx.x;
    if(e >= Ne) return;
    int d = dst[e];
    int pos = atomicAdd(&g_woff[d], 1);
    g_ced[pos] = make_int2(src[e], __float_as_int(ea[e]));
}

// ---------------- fused conv1 (low-rank aggregation; fp16 gathers; fp16 out) -----
__global__ void __launch_bounds__(32) k_conv1lr(
        const float* __restrict__ x,
        const float* __restrict__ Wl, const float* __restrict__ bl,
        const float* __restrict__ We, const float* __restrict__ att,
        const float* __restrict__ bias, const float* __restrict__ gam,
        const float* __restrict__ bet){
    int n = blockIdx.x;
    int lane = threadIdx.x;
    int c0 = lane * 8;
    const float4* pr = (const float4*)(g_xr + n*HID + c0);
    float4 r0 = pr[0], r1 = pr[1];
    float4 w0 = *(const float4*)(We + c0),  w1 = *(const float4*)(We + c0 + 4);
    float4 t0 = *(const float4*)(att + c0), t1 = *(const float4*)(att + c0 + 4);
    int j = lane & 3;
    float acc1 = 0.f, den = 0.f;
    int b = g_row[n], e = g_row[n+1];
    int i = b;
    for(; i + 1 < e; i += 2){
        int2 ed0 = g_ced[i], ed1 = g_ced[i+1];
        float ev0 = __int_as_float(ed0.y), ev1 = __int_as_float(ed1.y);
        float4 a0, a1, b0, b1;
        ldh8(g_xlh + ed0.x*128 + lane*4, a0, a1);
        ldh8(g_xlh + ed1.x*128 + lane*4, b0, b1);
        float xs0 = x[ed0.x*4 + j];
        float xs1 = x[ed1.x*4 + j];
        float p0 = dot8(a0, a1, r0, r1, ev0, w0, w1, t0, t1);
        float p1 = dot8(b0, b1, r0, r1, ev1, w0, w1, t0, t1);
        #pragma unroll
        for(int o = 0; o < 3; o++){
            p0 += __shfl_xor_sync(0xffffffffu, p0, 1 << o);
            p1 += __shfl_xor_sync(0xffffffffu, p1, 1 << o);
        }
        float e0 = __expf(p0);
        float e1 = __expf(p1);
        den += e0 + e1;
        acc1 += xs0*e0 + xs1*e1;
    }
    if(i < e){
        int2 ed0 = g_ced[i];
        float ev0 = __int_as_float(ed0.y);
        float4 a0, a1;
        ldh8(g_xlh + ed0.x*128 + lane*4, a0, a1);
        float xs0 = x[ed0.x*4 + j];
        float p0 = dot8(a0, a1, r0, r1, ev0, w0, w1, t0, t1);
        #pragma unroll
        for(int o = 0; o < 3; o++)
            p0 += __shfl_xor_sync(0xffffffffu, p0, 1 << o);
        float e0 = __expf(p0);
        den += e0;
        acc1 += xs0*e0;
    }
    float inv = 1.f / den;
    int h8 = lane & 24;
    float ax0 = __shfl_sync(0xffffffffu, acc1, h8+0) * inv;
    float ax1 = __shfl_sync(0xffffffffu, acc1, h8+1) * inv;
    float ax2 = __shfl_sync(0xffffffffu, acc1, h8+2) * inv;
    float ax3 = __shfl_sync(0xffffffffu, acc1, h8+3) * inv;
    float4 wr0A = *(const float4*)(Wl + 0*256 + c0), wr0B = *(const float4*)(Wl + 0*256 + c0 + 4);
    float4 wr1A = *(const float4*)(Wl + 1*256 + c0), wr1B = *(const float4*)(Wl + 1*256 + c0 + 4);
    float4 wr2A = *(const float4*)(Wl + 2*256 + c0), wr2B = *(const float4*)(Wl + 2*256 + c0 + 4);
    float4 wr3A = *(const float4*)(Wl + 3*256 + c0), wr3B = *(const float4*)(Wl + 3*256 + c0 + 4);
    float4 blA = *(const float4*)(bl + c0),   blB = *(const float4*)(bl + c0 + 4);
    float4 biA = *(const float4*)(bias + c0), biB = *(const float4*)(bias + c0 + 4);
    float v[8];
    v[0] = ax0*wr0A.x + ax1*wr1A.x + ax2*wr2A.x + ax3*wr3A.x + blA.x + biA.x;
    v[1] = ax0*wr0A.y + ax1*wr1A.y + ax2*wr2A.y + ax3*wr3A.y + blA.y + biA.y;
    v[2] = ax0*wr0A.z + ax1*wr1A.z + ax2*wr2A.z + ax3*wr3A.z + blA.z + biA.z;
    v[3] = ax0*wr0A.w + ax1*wr1A.w + ax2*wr2A.w + ax3*wr3A.w + blA.w + biA.w;
    v[4] = ax0*wr0B.x + ax1*wr1B.x + ax2*wr2B.x + ax3*wr3B.x + blB.x + biB.x;
    v[5] = ax0*wr0B.y + ax1*wr1B.y + ax2*wr2B.y + ax3*wr3B.y + blB.y + biB.y;
    v[6] = ax0*wr0B.z + ax1*wr1B.z + ax2*wr2B.z + ax3*wr3B.z + blB.z + biB.z;
    v[7] = ax0*wr0B.w + ax1*wr1B.w + ax2*wr2B.w + ax3*wr3B.w + blB.w + biB.w;
    float s = 0.f;
    #pragma unroll
    for(int k = 0; k < 8; k++) s += v[k];
    #pragma unroll
    for(int o = 16; o; o >>= 1) s += __shfl_xor_sync(0xffffffffu, s, o);
    float mu = s * (1.f/256.f);
    float q = 0.f;
    #pragma unroll
    for(int k = 0; k < 8; k++){ float dd = v[k]-mu; q += dd*dd; }
    #pragma unroll
    for(int o = 16; o; o >>= 1) q += __shfl_xor_sync(0xffffffffu, q, o);
    float rstd = rsqrtf(q*(1.f/256.f) + 1e-5f);
    float4 gA = *(const float4*)(gam + c0), gB = *(const float4*)(gam + c0 + 4);
    float4 eA = *(const float4*)(bet + c0), eB = *(const float4*)(bet + c0 + 4);
    float gv[8] = {gA.x,gA.y,gA.z,gA.w,gB.x,gB.y,gB.z,gB.w};
    float ev[8] = {eA.x,eA.y,eA.z,eA.w,eB.x,eB.y,eB.z,eB.w};
    float o0[8];
    #pragma unroll
    for(int k = 0; k < 8; k++)
        o0[k] = fmaxf((v[k]-mu)*rstd*gv[k] + ev[k], 0.f);
    __half2* dh = g_hh + n*128 + lane*4;
    dh[0] = __floats2half2_rn(o0[0], o0[1]);
    dh[1] = __floats2half2_rn(o0[2], o0[3]);
    dh[2] = __floats2half2_rn(o0[4], o0[5]);
    dh[3] = __floats2half2_rn(o0[6], o0[7]);
}

// ---------------- fused conv2 (H=1, C=256): fp16 gathers, fp32 accum, fp16 out ---
__global__ void __launch_bounds__(32) k_conv2(
        const float* __restrict__ We, const float* __restrict__ att,
        const float* __restrict__ bias, const float* __restrict__ gam,
        const float* __restrict__ bet){
    int n = blockIdx.x;
    int lane = threadIdx.x;
    int c0 = lane * 8;
    const float4* pr = (const float4*)(g_xr + n*HID + c0);
    float4 r0 = pr[0], r1 = pr[1];
    float4 w0 = *(const float4*)(We + c0),  w1 = *(const float4*)(We + c0 + 4);
    float4 t0 = *(const float4*)(att + c0), t1 = *(const float4*)(att + c0 + 4);
    float acc[8] = {0,0,0,0,0,0,0,0};
    float den = 0.f;
    int b = g_row[n], e = g_row[n+1];
    int i = b;
    for(; i + 1 < e; i += 2){
        int2 ed0 = g_ced[i], ed1 = g_ced[i+1];
        float ev0 = __int_as_float(ed0.y), ev1 = __int_as_float(ed1.y);
        float4 a0, a1, b0, b1;
        ldh8(g_xlh + ed0.x*128 + lane*4, a0, a1);
        ldh8(g_xlh + ed1.x*128 + lane*4, b0, b1);
        float p0 = dot8(a0, a1, r0, r1, ev0, w0, w1, t0, t1);
        float p1 = dot8(b0, b1, r0, r1, ev1, w0, w1, t0, t1);
        #pragma unroll
        for(int o = 0; o < 5; o++){
            p0 += __shfl_xor_sync(0xffffffffu, p0, 1 << o);
            p1 += __shfl_xor_sync(0xffffffffu, p1, 1 << o);
        }
        float e0 = __expf(p0);
        float e1 = __expf(p1);
        den += e0 + e1;
        acc[0] += a0.x*e0 + b0.x*e1; acc[1] += a0.y*e0 + b0.y*e1;
        acc[2] += a0.z*e0 + b0.z*e1; acc[3] += a0.w*e0 + b0.w*e1;
        acc[4] += a1.x*e0 + b1.x*e1; acc[5] += a1.y*e0 + b1.y*e1;
        acc[6] += a1.z*e0 + b1.z*e1; acc[7] += a1.w*e0 + b1.w*e1;
    }
    if(i < e){
        int2 ed0 = g_ced[i];
        float ev0 = __int_as_float(ed0.y);
        float4 a0, a1;
        ldh8(g_xlh + ed0.x*128 + lane*4, a0, a1);
        float p0 = dot8(a0, a1, r0, r1, ev0, w0, w1, t0, t1);
        #pragma unroll
        for(int o = 0; o < 5; o++)
            p0 += __shfl_xor_sync(0xffffffffu, p0, 1 << o);
        float e0 = __expf(p0);
        den += e0;
        acc[0] += a0.x*e0; acc[1] += a0.y*e0;
        acc[2] += a0.z*e0; acc[3] += a0.w*e0;
        acc[4] += a1.x*e0; acc[5] += a1.y*e0;
        acc[6] += a1.z*e0; acc[7] += a1.w*e0;
    }
    float inv = 1.f / den;
    float4 biA = *(const float4*)(bias + c0), biB = *(const float4*)(bias + c0 + 4);
    float bi[8] = {biA.x,biA.y,biA.z,biA.w,biB.x,biB.y,biB.z,biB.w};
    float v[8];
    float s = 0.f;
    #pragma unroll
    for(int k = 0; k < 8; k++){ v[k] = acc[k]*inv + bi[k]; s += v[k]; }
    #pragma unroll
    for(int o = 16; o; o >>= 1) s += __shfl_xor_sync(0xffffffffu, s, o);
    float mu = s * (1.f/256.f);
    float q = 0.f;
    #pragma unroll
    for(int k = 0; k < 8; k++){ float dd = v[k]-mu; q += dd*dd; }
    #pragma unroll
    for(int o = 16; o; o >>= 1) q += __shfl_xor_sync(0xffffffffu, q, o);
    float rstd = rsqrtf(q*(1.f/256.f) + 1e-5f);
    float4 gA = *(const float4*)(gam + c0), gB = *(const float4*)(gam + c0 + 4);
    float4 eA = *(const float4*)(bet + c0), eB = *(const float4*)(bet + c0 + 4);
    float gv[8] = {gA.x,gA.y,gA.z,gA.w,gB.x,gB.y,gB.z,gB.w};
    float evv[8] = {eA.x,eA.y,eA.z,eA.w,eB.x,eB.y,eB.z,eB.w};
    float o0[8];
    #pragma unroll
    for(int k = 0; k < 8; k++)
        o0[k] = fmaxf((v[k]-mu)*rstd*gv[k] + evv[k], 0.f);
    // fp16 output (overwrites conv1 activations — sole consumer k_gemm_dual already ran)
    __half2* dh = g_hh + n*128 + lane*4;
    dh[0] = __floats2half2_rn(o0[0], o0[1]);
    dh[1] = __floats2half2_rn(o0[2], o0[3]);
    dh[2] = __floats2half2_rn(o0[4], o0[5]);
    dh[3] = __floats2half2_rn(o0[6], o0[7]);
}

// ---------------- dual GEMM: fp16 tensor cores (m16n16k16, fp32 accum) ----------
__global__ void __launch_bounds__(128) k_gemm_dual(
        const float* __restrict__ Wl, const float* __restrict__ bl,
        const float* __restrict__ Wr, const float* __restrict__ br){
    __shared__ __align__(16) __half As[64][40];
    __shared__ __align__(16) __half Bs[32][72];
    __shared__ __align__(16) float  Cs[64][68];
    int half_ = blockIdx.x >> 2;
    int nblk = blockIdx.x & 3;
    const float* B    = half_ ? Wr : Wl;
    const float* bias = half_ ? br : bl;
    int m0 = blockIdx.y*64, n0 = nblk*64;
    int t = threadIdx.x;
    int warp = t >> 5, wy = warp >> 1, wx = warp & 1;

    wmma::fragment<wmma::accumulator,16,16,16,float> acc[2][2];
    #pragma unroll
    for(int i = 0; i < 2; i++)
        #pragma unroll
        for(int jj = 0; jj < 2; jj++)
            wmma::fill_fragment(acc[i][jj], 0.f);

    int arow = t >> 1, aseg = t & 1;
    int brow = t >> 2, bcol = (t & 3) * 16;
    for(int k0 = 0; k0 < 256; k0 += 32){
        int gm = m0 + arow;
        uint4 z4 = make_uint4(0,0,0,0);
        const uint4* srcA = (const uint4*)(g_hh + gm*128 + (k0 >> 1) + aseg*8);
        uint4 av0 = (gm < Nn) ? srcA[0] : z4;
        uint4 av1 = (gm < Nn) ? srcA[1] : z4;
        *(uint4*)&As[arow][aseg*16]     = av0;
        *(uint4*)&As[arow][aseg*16 + 8] = av1;
        const float4* srcB = (const float4*)(B + (k0+brow)*256 + n0 + bcol);
        float4 f0 = srcB[0], f1 = srcB[1], f2 = srcB[2], f3 = srcB[3];
        __half2* db = (__half2*)&Bs[brow][bcol];
        db[0] = __floats2half2_rn(f0.x,f0.y); db[1] = __floats2half2_rn(f0.z,f0.w);
        db[2] = __floats2half2_rn(f1.x,f1.y); db[3] = __floats2half2_rn(f1.z,f1.w);
        db[4] = __floats2half2_rn(f2.x,f2.y); db[5] = __floats2half2_rn(f2.z,f2.w);
        db[6] = __floats2half2_rn(f3.x,f3.y); db[7] = __floats2half2_rn(f3.z,f3.w);
        __syncthreads();
        #pragma unroll
        for(int ks = 0; ks < 2; ks++){
            wmma::fragment<wmma::matrix_a,16,16,16,__half,wmma::row_major> af[2];
            wmma::fragment<wmma::matrix_b,16,16,16,__half,wmma::row_major> bf[2];
            #pragma unroll
            for(int i = 0; i < 2; i++)
                wmma::load_matrix_sync(af[i], &As[wy*32 + i*16][ks*16], 40);
            #pragma unroll
            for(int jj = 0; jj < 2; jj++)
                wmma::load_matrix_sync(bf[jj], &Bs[ks*16][wx*32 + jj*16], 72);
            #pragma unroll
            for(int i = 0; i < 2; i++)
                #pragma unroll
                for(int jj = 0; jj < 2; jj++)
                    wmma::mma_sync(acc[i][jj], af[i], bf[jj], acc[i][jj]);
        }
        __syncthreads();
    }
    #pragma unroll
    for(int i = 0; i < 2; i++)
        #pragma unroll
        for(int jj = 0; jj < 2; jj++)
            wmma::store_matrix_sync(&Cs[wy*32 + i*16][wx*32 + jj*16], acc[i][jj], 68, wmma::mem_row_major);
    __syncthreads();
    for(int idx = t; idx < 64*16; idx += 128){
        int row = idx >> 4;
        int c4 = (idx & 15) * 4;
        int gm = m0 + row;
        if(gm >= Nn) continue;
        float4 v = *(float4*)&Cs[row][c4];
        float4 bv = *(const float4*)(bias + n0 + c4);
        v.x += bv.x; v.y += bv.y; v.z += bv.z; v.w += bv.w;
        if(half_){
            *(float4*)(g_xr + gm*256 + n0 + c4) = v;
        } else {
            __half2* d2 = g_xlh + gm*128 + ((n0 + c4) >> 1);
            d2[0] = __floats2half2_rn(v.x, v.y);
            d2[1] = __floats2half2_rn(v.z, v.w);
        }
    }
}

// ---------------- policy GEMM: fp16 tensor cores + fused Wp2 projection ----------
// p1 = relu(h2@Wp1+bp1) [64x128 block tile], logits = p1@Wp2+bp2 -> g_pl
__global__ void __launch_bounds__(128) k_gemm_pol(
        const float* __restrict__ Wp1, const float* __restrict__ bp1,
        const float* __restrict__ Wp2, const float* __restrict__ bp2){
    __shared__ __align__(16) __half As[64][40];
    __shared__ __align__(16) __half Bs[32][136];
    __shared__ __align__(16) float  Cs[64][132];
    int m0 = blockIdx.x * 64;
    int t = threadIdx.x;
    int warp = t >> 5, wy = warp >> 1, wx = warp & 1;

    wmma::fragment<wmma::accumulator,16,16,16,float> acc[2][4];
    #pragma unroll
    for(int i = 0; i < 2; i++)
        #pragma unroll
        for(int jj = 0; jj < 4; jj++)
            wmma::fill_fragment(acc[i][jj], 0.f);

    int arow = t >> 1, aseg = t & 1;
    int brow = t >> 2, bcol = (t & 3) * 32;
    for(int k0 = 0; k0 < 256; k0 += 32){
        int gm = m0 + arow;
        uint4 z4 = make_uint4(0,0,0,0);
        const uint4* srcA = (const uint4*)(g_hh + gm*128 + (k0 >> 1) + aseg*8);
        uint4 av0 = (gm < Nn) ? srcA[0] : z4;
        uint4 av1 = (gm < Nn) ? srcA[1] : z4;
        *(uint4*)&As[arow][aseg*16]     = av0;
        *(uint4*)&As[arow][aseg*16 + 8] = av1;
        const float4* srcB = (const float4*)(Wp1 + (k0+brow)*128 + bcol);
        __half2* db = (__half2*)&Bs[brow][bcol];
        #pragma unroll
        for(int q = 0; q < 8; q++){
            float4 f = srcB[q];
            db[2*q]   = __floats2half2_rn(f.x, f.y);
            db[2*q+1] = __floats2half2_rn(f.z, f.w);
        }
        __syncthreads();
        #pragma unroll
        for(int ks = 0; ks < 2; ks++){
            wmma::fragment<wmma::matrix_a,16,16,16,__half,wmma::row_major> af[2];
            wmma::fragment<wmma::matrix_b,16,16,16,__half,wmma::row_major> bf[4];
            #pragma unroll
            for(int i = 0; i < 2; i++)
                wmma::load_matrix_sync(af[i], &As[wy*32 + i*16][ks*16], 40);
            #pragma unroll
            for(int jj = 0; jj < 4; jj++)
                wmma::load_matrix_sync(bf[jj], &Bs[ks*16][wx*64 + jj*16], 136);
            #pragma unroll
            for(int i = 0; i < 2; i++)
                #pragma unroll
                for(int jj = 0; jj < 4; jj++)
                    wmma::mma_sync(acc[i][jj], af[i], bf[jj], acc[i][jj]);
        }
        __syncthreads();
    }
    #pragma unroll
    for(int i = 0; i < 2; i++)
        #pragma unroll
        for(int jj = 0; jj < 4; jj++)
            wmma::store_matrix_sync(&Cs[wy*32 + i*16][wx*64 + jj*16], acc[i][jj], 132, wmma::mem_row_major);
    __syncthreads();
    // epilogue: relu(+bp1), project through Wp2[128,4], 2 threads per row
    {
        int row = t >> 1;
        int seg = t & 1;          // 64-column half
        int gm = m0 + row;
        float part0 = 0.f, part1 = 0.f, part2 = 0.f, part3 = 0.f;
        #pragma unroll 8
        for(int j = 0; j < 64; j++){
            int col = seg*64 + j;
            float v = fmaxf(Cs[row][col] + bp1[col], 0.f);
            const float4 wv = *(const float4*)(Wp2 + col*4);
            part0 += v*wv.x; part1 += v*wv.y; part2 += v*wv.z; part3 += v*wv.w;
        }
        part0 += __shfl_xor_sync(0xffffffffu, part0, 1);
        part1 += __shfl_xor_sync(0xffffffffu, part1, 1);
        part2 += __shfl_xor_sync(0xffffffffu, part2, 1);
        part3 += __shfl_xor_sync(0xffffffffu, part3, 1);
        if(seg == 0 && gm < Nn){
            float4 r4 = make_float4(part0 + bp2[0], part1 + bp2[1],
                                    part2 + bp2[2], part3 + bp2[3]);
            *(float4*)(g_pl + gm*4) = r4;
        }
    }
}

// ---------------- two-phase global softmax over 40000 logits ----------------
__global__ void k_red1(){
    __shared__ float sm[256];
    int bid = blockIdx.x, tid = threadIdx.x;
    const int chunk = (Nn*4 + NRED - 1) / NRED;
    int lo = bid*chunk, hi = min(lo + chunk, Nn*4);
    float m = -3.4e38f;
    for(int i = lo + tid; i < hi; i += 256) m = fmaxf(m, g_pl[i]);
    sm[tid] = m; __syncthreads();
    for(int o = 128; o > 0; o >>= 1){ if(tid < o) sm[tid] = fmaxf(sm[tid], sm[tid+o]); __syncthreads(); }
    float mx = sm[0]; __syncthreads();
    float s = 0.f;
    for(int i = lo + tid; i < hi; i += 256) s += __expf(g_pl[i] - mx);
    sm[tid] = s; __syncthreads();
    for(int o = 128; o > 0; o >>= 1){ if(tid < o) sm[tid] += sm[tid+o]; __syncthreads(); }
    if(tid == 0){ g_pmax[bid] = mx; g_psum[bid] = sm[0]; }
}
// output (combines the NRED partials in-block) + restore state for next replay
__global__ void k_out(float* __restrict__ out){
    __shared__ float sMS[2];
    if(threadIdx.x == 0){
        float M = -3.4e38f;
        #pragma unroll
        for(int j = 0; j < NRED; j++) M = fmaxf(M, g_pmax[j]);
        float S = 0.f;
        #pragma unroll
        for(int j = 0; j < NRED; j++) S += g_psum[j] * __expf(g_pmax[j] - M);
        sMS[0] = M; sMS[1] = 1.f / S;
    }
    __syncthreads();
    int i = blockIdx.x*blockDim.x + threadIdx.x;
    if(i < Nn*4) out[i] = __expf(g_pl[i] - sMS[0]) * sMS[1];
    if(i < Nn){ g_cnt[i] = 0; g_loop[i] = 0.f; }
}

// ---------------- launch ----------------
extern "C" void kernel_launch(void* const* d_in, const int* in_sizes, int n_in,
                              void* d_out, int out_size){
    const float* x     = (const float*)d_in[0];
    const int*   ei    = (const int*)  d_in[1];
    const float* ea    = (const float*)d_in[2];
    const float* Wl1   = (const float*)d_in[3];
    const float* bl1   = (const float*)d_in[4];
    const float* Wr1   = (const float*)d_in[5];
    const float* br1   = (const float*)d_in[6];
    const float* We1   = (const float*)d_in[7];
    const float* att1  = (const float*)d_in[8];
    const float* bias1 = (const float*)d_in[9];
    const float* g1    = (const float*)d_in[10];
    const float* be1   = (const float*)d_in[11];
    const float* Wl2   = (const float*)d_in[12];
    const float* bl2   = (const float*)d_in[13];
    const float* Wr2   = (const float*)d_in[14];
    const float* br2   = (const float*)d_in[15];
    const float* We2   = (const float*)d_in[16];
    const float* att2  = (const float*)d_in[17];
    const float* bias2 = (const float*)d_in[18];
    const float* g2    = (const float*)d_in[19];
    const float* be2   = (const float*)d_in[20];
    const float* Wp1   = (const float*)d_in[21];
    const float* bp1   = (const float*)d_in[22];
    const float* Wp2   = (const float*)d_in[23];
    const float* bp2   = (const float*)d_in[24];
    const int* src = ei;
    const int* dst = ei + Ne;
    float* out = (float*)d_out;

    const int TB = 256;

    // CSR build + conv1 linear (merged)
    k_hist_lin1<<<HB + (Nn*64+TB-1)/TB, TB>>>(dst, ea, x, Wl1, bl1, Wr1, br1);
    k_scanprep<<<1, 1024>>>();
    k_scatter<<<(Ne+TB-1)/TB, TB>>>(src, dst, ea);

    // conv1 (low-rank aggregation) — one warp-block per node
    k_conv1lr<<<Nn, 32>>>(x, Wl1, bl1, We1, att1, bias1, g1, be1);

    // conv2 (fp16 tensor-core dual GEMM)
    k_gemm_dual<<<dim3(8, (Nn+63)/64), 128>>>(Wl2, bl2, Wr2, br2);
    k_conv2<<<Nn, 32>>>(We2, att2, bias2, g2, be2);

    // policy head (fp16 tensor-core GEMM + fused final projection)
    k_gemm_pol<<<(Nn+63)/64, 128>>>(Wp1, bp1, Wp2, bp2);

    // global softmax (two-phase)
    k_red1<<<NRED, 256>>>();
    k_out<<<(Nn*4+TB-1)/TB, TB>>>(out);
}

// round 14
// speedup vs baseline: 1.6365x; 1.0839x over previous
#include <cuda_runtime.h>
#include <cuda_fp16.h>
#include <mma.h>
using namespace nvcuda;

#define Nn   10000
#define Ne   320000
#define EAt  330000      // edges + self loops
#define HID  256
#define NRED 20          // partial-reduction blocks for final softmax

// ---------------- scratch (static device globals; zero-initialized at load) ------
__device__ float    g_loop[Nn];
__device__ int      g_cnt[Nn];
__device__ int      g_row[Nn+1];
__device__ int      g_woff[Nn];
__device__ int2     g_ced[EAt];        // (src, edge_attr bits)
__device__ __half2  g_xlh[Nn*128];     // fp16 xl feature table (edge-gathered)
__device__ __half2  g_hh[Nn*128];      // fp16 activations: conv1 out, then conv2 out
__device__ float    g_xr[Nn*HID];
__device__ float    g_pl[Nn*4];
__device__ float    g_pmax[NRED];
__device__ float    g_psum[NRED];

// half2 logit kernel: p_lane = Σ_j [ (0.6att)·z + (0.4att)·|z| ],  z = la + r + ev·w
__device__ __forceinline__ float dot8h(const __half2* la, const __half2* rh,
                                       const __half2* wh, const __half2* a06,
                                       const __half2* a04, __half2 evh){
    __half2 pa = __float2half2_rn(0.f), pb = __float2half2_rn(0.f);
    #pragma unroll
    for(int j4 = 0; j4 < 4; j4++){
        __half2 z = __hfma2(evh, wh[j4], __hadd2(la[j4], rh[j4]));
        pa = __hfma2(z, a06[j4], pa);
        pb = __hfma2(__habs2(z), a04[j4], pb);
    }
    float2 f = __half22float2(__hadd2(pa, pb));
    return f.x + f.y;
}

// ---------------- kernel 1: edge histogram (+loop attr sum)  ||  lin1 ----------------
#define HB 1250   // (Ne+255)/256
__global__ void k_hist_lin1(const int* __restrict__ dst, const float* __restrict__ ea,
                            const float* __restrict__ x,
                            const float* __restrict__ Wl, const float* __restrict__ bl,
                            const float* __restrict__ Wr, const float* __restrict__ br){
    int b = blockIdx.x;
    if(b < HB){
        int e = b*256 + threadIdx.x;
        if(e < Ne){
            int d = dst[e];
            atomicAdd(&g_cnt[d], 1);
            atomicAdd(&g_loop[d], ea[e]);
        }
    } else {
        int t = (b - HB)*256 + threadIdx.x;
        if(t < Nn*64){
            int n = t >> 6, c4 = (t & 63) << 2;
            float4 xv = *(const float4*)(x + n*4);
            float4 l = *(const float4*)(bl + c4);
            float4 r = *(const float4*)(br + c4);
            float4 w;
            w = *(const float4*)(Wl + 0*256 + c4); l.x+=xv.x*w.x; l.y+=xv.x*w.y; l.z+=xv.x*w.z; l.w+=xv.x*w.w;
            w = *(const float4*)(Wl + 1*256 + c4); l.x+=xv.y*w.x; l.y+=xv.y*w.y; l.z+=xv.y*w.z; l.w+=xv.y*w.w;
            w = *(const float4*)(Wl + 2*256 + c4); l.x+=xv.z*w.x; l.y+=xv.z*w.y; l.z+=xv.z*w.z; l.w+=xv.z*w.w;
            w = *(const float4*)(Wl + 3*256 + c4); l.x+=xv.w*w.x; l.y+=xv.w*w.y; l.z+=xv.w*w.z; l.w+=xv.w*w.w;
            w = *(const float4*)(Wr + 0*256 + c4); r.x+=xv.x*w.x; r.y+=xv.x*w.y; r.z+=xv.x*w.z; r.w+=xv.x*w.w;
            w = *(const float4*)(Wr + 1*256 + c4); r.x+=xv.y*w.x; r.y+=xv.y*w.y; r.z+=xv.y*w.z; r.w+=xv.y*w.w;
            w = *(const float4*)(Wr + 2*256 + c4); r.x+=xv.z*w.x; r.y+=xv.z*w.y; r.z+=xv.z*w.z; r.w+=xv.z*w.w;
            w = *(const float4*)(Wr + 3*256 + c4); r.x+=xv.w*w.x; r.y+=xv.w*w.y; r.z+=xv.w*w.z; r.w+=xv.w*w.w;
            __half2 h0 = __floats2half2_rn(l.x, l.y);
            __half2 h1 = __floats2half2_rn(l.z, l.w);
            __half2* dst2 = g_xlh + n*128 + (c4 >> 1);
            dst2[0] = h0; dst2[1] = h1;
            *(float4*)(g_xr + n*256 + c4) = r;
        }
    }
}

// ---------------- kernel 2: scan + prep (single block) ----------------
__global__ void k_scanprep(){
    __shared__ int part[1024];
    const int NP = 10;
    int tid = threadIdx.x;
    int base = tid * NP;
    int cnt[NP], loc[NP];
    int s = 0;
    #pragma unroll
    for(int i = 0; i < NP; i++){
        int idx = base + i;
        int c = (idx < Nn) ? g_cnt[idx] : 0;
        cnt[i] = c;
        loc[i] = s;
        s += (idx < Nn) ? (c + 1) : 0;
    }
    part[tid] = s; __syncthreads();
    for(int o = 1; o < 1024; o <<= 1){
        int v = (tid >= o) ? part[tid - o] : 0;
        __syncthreads();
        if(tid >= o) part[tid] += v;
        __syncthreads();
    }
    int off = (tid > 0) ? part[tid - 1] : 0;
    #pragma unroll
    for(int i = 0; i < NP; i++){
        int idx = base + i;
        if(idx < Nn){
            int rs = off + loc[i];
            int re = rs + cnt[i] + 1;
            g_row[idx] = rs;
            if(idx == Nn-1) g_row[Nn] = re;
            float lp = g_loop[idx] / fmaxf((float)cnt[i], 1.f);
            g_ced[re-1] = make_int2(idx, __float_as_int(lp));
            g_woff[idx] = rs;
        }
    }
}

// ---------------- kernel 3: scatter edges into CSR ----------------
__global__ void k_scatter(const int* __restrict__ src, const int* __restrict__ dst,
                          const float* __restrict__ ea){
    int e = blockIdx.x*blockDim.x + threadIdx.x;
    if(e >= Ne) return;
    int d = dst[e];
    int pos = atomicAdd(&g_woff[d], 1);
    g_ced[pos] = make_int2(src[e], __float_as_int(ea[e]));
}

// ---------------- fused conv1 (low-rank aggregation; half2 logit path) -----------
__global__ void __launch_bounds__(32) k_conv1lr(
        const float* __restrict__ x,
        const float* __restrict__ Wl, const float* __restrict__ bl,
        const float* __restrict__ We, const float* __restrict__ att,
        const float* __restrict__ bias, const float* __restrict__ gam,
        const float* __restrict__ bet){
    int n = blockIdx.x;
    int lane = threadIdx.x;
    int c0 = lane * 8;
    // loop-invariant half2 constants
    __half2 rh[4], wh[4], a06[4], a04[4];
    {
        float4 rA = *(const float4*)(g_xr + n*HID + c0);
        float4 rB = *(const float4*)(g_xr + n*HID + c0 + 4);
        rh[0] = __floats2half2_rn(rA.x, rA.y); rh[1] = __floats2half2_rn(rA.z, rA.w);
        rh[2] = __floats2half2_rn(rB.x, rB.y); rh[3] = __floats2half2_rn(rB.z, rB.w);
        float4 wA = *(const float4*)(We + c0), wB = *(const float4*)(We + c0 + 4);
        wh[0] = __floats2half2_rn(wA.x, wA.y); wh[1] = __floats2half2_rn(wA.z, wA.w);
        wh[2] = __floats2half2_rn(wB.x, wB.y); wh[3] = __floats2half2_rn(wB.z, wB.w);
        float4 tA = *(const float4*)(att + c0), tB = *(const float4*)(att + c0 + 4);
        a06[0] = __floats2half2_rn(0.6f*tA.x, 0.6f*tA.y); a06[1] = __floats2half2_rn(0.6f*tA.z, 0.6f*tA.w);
        a06[2] = __floats2half2_rn(0.6f*tB.x, 0.6f*tB.y); a06[3] = __floats2half2_rn(0.6f*tB.z, 0.6f*tB.w);
        a04[0] = __floats2half2_rn(0.4f*tA.x, 0.4f*tA.y); a04[1] = __floats2half2_rn(0.4f*tA.z, 0.4f*tA.w);
        a04[2] = __floats2half2_rn(0.4f*tB.x, 0.4f*tB.y); a04[3] = __floats2half2_rn(0.4f*tB.z, 0.4f*tB.w);
    }
    int j = lane & 3;
    float acc1 = 0.f, den = 0.f;
    int b = g_row[n], e = g_row[n+1];
    int i = b;
    for(; i + 1 < e; i += 2){
        int2 ed0 = g_ced[i], ed1 = g_ced[i+1];
        uint4 raw0 = *(const uint4*)(g_xlh + ed0.x*128 + lane*4);
        uint4 raw1 = *(const uint4*)(g_xlh + ed1.x*128 + lane*4);
        const __half2* la = (const __half2*)&raw0;
        const __half2* lb = (const __half2*)&raw1;
        __half2 evh0 = __float2half2_rn(__int_as_float(ed0.y));
        __half2 evh1 = __float2half2_rn(__int_as_float(ed1.y));
        float xs0 = x[ed0.x*4 + j];
        float xs1 = x[ed1.x*4 + j];
        float p0 = dot8h(la, rh, wh, a06, a04, evh0);
        float p1 = dot8h(lb, rh, wh, a06, a04, evh1);
        #pragma unroll
        for(int o = 0; o < 3; o++){
            p0 += __shfl_xor_sync(0xffffffffu, p0, 1 << o);
            p1 += __shfl_xor_sync(0xffffffffu, p1, 1 << o);
        }
        float e0 = __expf(p0);
        float e1 = __expf(p1);
        den += e0 + e1;
        acc1 += xs0*e0 + xs1*e1;
    }
    if(i < e){
        int2 ed0 = g_ced[i];
        uint4 raw0 = *(const uint4*)(g_xlh + ed0.x*128 + lane*4);
        const __half2* la = (const __half2*)&raw0;
        __half2 evh0 = __float2half2_rn(__int_as_float(ed0.y));
        float xs0 = x[ed0.x*4 + j];
        float p0 = dot8h(la, rh, wh, a06, a04, evh0);
        #pragma unroll
        for(int o = 0; o < 3; o++)
            p0 += __shfl_xor_sync(0xffffffffu, p0, 1 << o);
        float e0 = __expf(p0);
        den += e0;
        acc1 += xs0*e0;
    }
    float inv = 1.f / den;
    int h8 = lane & 24;
    float ax0 = __shfl_sync(0xffffffffu, acc1, h8+0) * inv;
    float ax1 = __shfl_sync(0xffffffffu, acc1, h8+1) * inv;
    float ax2 = __shfl_sync(0xffffffffu, acc1, h8+2) * inv;
    float ax3 = __shfl_sync(0xffffffffu, acc1, h8+3) * inv;
    float4 wr0A = *(const float4*)(Wl + 0*256 + c0), wr0B = *(const float4*)(Wl + 0*256 + c0 + 4);
    float4 wr1A = *(const float4*)(Wl + 1*256 + c0), wr1B = *(const float4*)(Wl + 1*256 + c0 + 4);
    float4 wr2A = *(const float4*)(Wl + 2*256 + c0), wr2B = *(const float4*)(Wl + 2*256 + c0 + 4);
    float4 wr3A = *(const float4*)(Wl + 3*256 + c0), wr3B = *(const float4*)(Wl + 3*256 + c0 + 4);
    float4 blA = *(const float4*)(bl + c0),   blB = *(const float4*)(bl + c0 + 4);
    float4 biA = *(const float4*)(bias + c0), biB = *(const float4*)(bias + c0 + 4);
    float v[8];
    v[0] = ax0*wr0A.x + ax1*wr1A.x + ax2*wr2A.x + ax3*wr3A.x + blA.x + biA.x;
    v[1] = ax0*wr0A.y + ax1*wr1A.y + ax2*wr2A.y + ax3*wr3A.y + blA.y + biA.y;
    v[2] = ax0*wr0A.z + ax1*wr1A.z + ax2*wr2A.z + ax3*wr3A.z + blA.z + biA.z;
    v[3] = ax0*wr0A.w + ax1*wr1A.w + ax2*wr2A.w + ax3*wr3A.w + blA.w + biA.w;
    v[4] = ax0*wr0B.x + ax1*wr1B.x + ax2*wr2B.x + ax3*wr3B.x + blB.x + biB.x;
    v[5] = ax0*wr0B.y + ax1*wr1B.y + ax2*wr2B.y + ax3*wr3B.y + blB.y + biB.y;
    v[6] = ax0*wr0B.z + ax1*wr1B.z + ax2*wr2B.z + ax3*wr3B.z + blB.z + biB.z;
    v[7] = ax0*wr0B.w + ax1*wr1B.w + ax2*wr2B.w + ax3*wr3B.w + blB.w + biB.w;
    float s = 0.f;
    #pragma unroll
    for(int k = 0; k < 8; k++) s += v[k];
    #pragma unroll
    for(int o = 16; o; o >>= 1) s += __shfl_xor_sync(0xffffffffu, s, o);
    float mu = s * (1.f/256.f);
    float q = 0.f;
    #pragma unroll
    for(int k = 0; k < 8; k++){ float dd = v[k]-mu; q += dd*dd; }
    #pragma unroll
    for(int o = 16; o; o >>= 1) q += __shfl_xor_sync(0xffffffffu, q, o);
    float rstd = rsqrtf(q*(1.f/256.f) + 1e-5f);
    float4 gA = *(const float4*)(gam + c0), gB = *(const float4*)(gam + c0 + 4);
    float4 eA = *(const float4*)(bet + c0), eB = *(const float4*)(bet + c0 + 4);
    float gv[8] = {gA.x,gA.y,gA.z,gA.w,gB.x,gB.y,gB.z,gB.w};
    float ev[8] = {eA.x,eA.y,eA.z,eA.w,eB.x,eB.y,eB.z,eB.w};
    float o0[8];
    #pragma unroll
    for(int k = 0; k < 8; k++)
        o0[k] = fmaxf((v[k]-mu)*rstd*gv[k] + ev[k], 0.f);
    __half2* dh = g_hh + n*128 + lane*4;
    dh[0] = __floats2half2_rn(o0[0], o0[1]);
    dh[1] = __floats2half2_rn(o0[2], o0[3]);
    dh[2] = __floats2half2_rn(o0[4], o0[5]);
    dh[3] = __floats2half2_rn(o0[6], o0[7]);
}

// ---------------- fused conv2 (H=1, C=256): half2 logits, fp32 aggregation -------
__global__ void __launch_bounds__(32) k_conv2(
        const float* __restrict__ We, const float* __restrict__ att,
        const float* __restrict__ bias, const float* __restrict__ gam,
        const float* __restrict__ bet){
    int n = blockIdx.x;
    int lane = threadIdx.x;
    int c0 = lane * 8;
    __half2 rh[4], wh[4], a06[4], a04[4];
    {
        float4 rA = *(const float4*)(g_xr + n*HID + c0);
        float4 rB = *(const float4*)(g_xr + n*HID + c0 + 4);
        rh[0] = __floats2half2_rn(rA.x, rA.y); rh[1] = __floats2half2_rn(rA.z, rA.w);
        rh[2] = __floats2half2_rn(rB.x, rB.y); rh[3] = __floats2half2_rn(rB.z, rB.w);
        float4 wA = *(const float4*)(We + c0), wB = *(const float4*)(We + c0 + 4);
        wh[0] = __floats2half2_rn(wA.x, wA.y); wh[1] = __floats2half2_rn(wA.z, wA.w);
        wh[2] = __floats2half2_rn(wB.x, wB.y); wh[3] = __floats2half2_rn(wB.z, wB.w);
        float4 tA = *(const float4*)(att + c0), tB = *(const float4*)(att + c0 + 4);
        a06[0] = __floats2half2_rn(0.6f*tA.x, 0.6f*tA.y); a06[1] = __floats2half2_rn(0.6f*tA.z, 0.6f*tA.w);
        a06[2] = __floats2half2_rn(0.6f*tB.x, 0.6f*tB.y); a06[3] = __floats2half2_rn(0.6f*tB.z, 0.6f*tB.w);
        a04[0] = __floats2half2_rn(0.4f*tA.x, 0.4f*tA.y); a04[1] = __floats2half2_rn(0.4f*tA.z, 0.4f*tA.w);
        a04[2] = __floats2half2_rn(0.4f*tB.x, 0.4f*tB.y); a04[3] = __floats2half2_rn(0.4f*tB.z, 0.4f*tB.w);
    }
    float acc[8] = {0,0,0,0,0,0,0,0};
    float den = 0.f;
    int b = g_row[n], e = g_row[n+1];
    int i = b;
    for(; i + 1 < e; i += 2){
        int2 ed0 = g_ced[i], ed1 = g_ced[i+1];
        uint4 raw0 = *(const uint4*)(g_xlh + ed0.x*128 + lane*4);
        uint4 raw1 = *(const uint4*)(g_xlh + ed1.x*128 + lane*4);
        const __half2* la = (const __half2*)&raw0;
        const __half2* lb = (const __half2*)&raw1;
        __half2 evh0 = __float2half2_rn(__int_as_float(ed0.y));
        __half2 evh1 = __float2half2_rn(__int_as_float(ed1.y));
        float p0 = dot8h(la, rh, wh, a06, a04, evh0);
        float p1 = dot8h(lb, rh, wh, a06, a04, evh1);
        #pragma unroll
        for(int o = 0; o < 5; o++){
            p0 += __shfl_xor_sync(0xffffffffu, p0, 1 << o);
            p1 += __shfl_xor_sync(0xffffffffu, p1, 1 << o);
        }
        float e0 = __expf(p0);
        float e1 = __expf(p1);
        den += e0 + e1;
        float2 a0 = __half22float2(la[0]), a1 = __half22float2(la[1]);
        float2 a2 = __half22float2(la[2]), a3 = __half22float2(la[3]);
        float2 b0 = __half22float2(lb[0]), b1 = __half22float2(lb[1]);
        float2 b2 = __half22float2(lb[2]), b3 = __half22float2(lb[3]);
        acc[0] += a0.x*e0 + b0.x*e1; acc[1] += a0.y*e0 + b0.y*e1;
        acc[2] += a1.x*e0 + b1.x*e1; acc[3] += a1.y*e0 + b1.y*e1;
        acc[4] += a2.x*e0 + b2.x*e1; acc[5] += a2.y*e0 + b2.y*e1;
        acc[6] += a3.x*e0 + b3.x*e1; acc[7] += a3.y*e0 + b3.y*e1;
    }
    if(i < e){
        int2 ed0 = g_ced[i];
        uint4 raw0 = *(const uint4*)(g_xlh + ed0.x*128 + lane*4);
        const __half2* la = (const __half2*)&raw0;
        __half2 evh0 = __float2half2_rn(__int_as_float(ed0.y));
        float p0 = dot8h(la, rh, wh, a06, a04, evh0);
        #pragma unroll
        for(int o = 0; o < 5; o++)
            p0 += __shfl_xor_sync(0xffffffffu, p0, 1 << o);
        float e0 = __expf(p0);
        den += e0;
        float2 a0 = __half22float2(la[0]), a1 = __half22float2(la[1]);
        float2 a2 = __half22float2(la[2]), a3 = __half22float2(la[3]);
        acc[0] += a0.x*e0; acc[1] += a0.y*e0;
        acc[2] += a1.x*e0; acc[3] += a1.y*e0;
        acc[4] += a2.x*e0; acc[5] += a2.y*e0;
        acc[6] += a3.x*e0; acc[7] += a3.y*e0;
    }
    float inv = 1.f / den;
    float4 biA = *(const float4*)(bias + c0), biB = *(const float4*)(bias + c0 + 4);
    float bi[8] = {biA.x,biA.y,biA.z,biA.w,biB.x,biB.y,biB.z,biB.w};
    float v[8];
    float s = 0.f;
    #pragma unroll
    for(int k = 0; k < 8; k++){ v[k] = acc[k]*inv + bi[k]; s += v[k]; }
    #pragma unroll
    for(int o = 16; o; o >>= 1) s += __shfl_xor_sync(0xffffffffu, s, o);
    float mu = s * (1.f/256.f);
    float q = 0.f;
    #pragma unroll
    for(int k = 0; k < 8; k++){ float dd = v[k]-mu; q += dd*dd; }
    #pragma unroll
    for(int o = 16; o; o >>= 1) q += __shfl_xor_sync(0xffffffffu, q, o);
    float rstd = rsqrtf(q*(1.f/256.f) + 1e-5f);
    float4 gA = *(const float4*)(gam + c0), gB = *(const float4*)(gam + c0 + 4);
    float4 eA = *(const float4*)(bet + c0), eB = *(const float4*)(bet + c0 + 4);
    float gv[8] = {gA.x,gA.y,gA.z,gA.w,gB.x,gB.y,gB.z,gB.w};
    float evv[8] = {eA.x,eA.y,eA.z,eA.w,eB.x,eB.y,eB.z,eB.w};
    float o0[8];
    #pragma unroll
    for(int k = 0; k < 8; k++)
        o0[k] = fmaxf((v[k]-mu)*rstd*gv[k] + evv[k], 0.f);
    __half2* dh = g_hh + n*128 + lane*4;
    dh[0] = __floats2half2_rn(o0[0], o0[1]);
    dh[1] = __floats2half2_rn(o0[2], o0[3]);
    dh[2] = __floats2half2_rn(o0[4], o0[5]);
    dh[3] = __floats2half2_rn(o0[6], o0[7]);
}

// ---------------- dual GEMM: fp16 tensor cores (m16n16k16, fp32 accum) ----------
__global__ void __launch_bounds__(128) k_gemm_dual(
        const float* __restrict__ Wl, const float* __restrict__ bl,
        const float* __restrict__ Wr, const float* __restrict__ br){
    __shared__ __align__(16) __half As[64][40];
    __shared__ __align__(16) __half Bs[32][72];
    __shared__ __align__(16) float  Cs[64][68];
    int half_ = blockIdx.x >> 2;
    int nblk = blockIdx.x & 3;
    const float* B    = half_ ? Wr : Wl;
    const float* bias = half_ ? br : bl;
    int m0 = blockIdx.y*64, n0 = nblk*64;
    int t = threadIdx.x;
    int warp = t >> 5, wy = warp >> 1, wx = warp & 1;

    wmma::fragment<wmma::accumulator,16,16,16,float> acc[2][2];
    #pragma unroll
    for(int i = 0; i < 2; i++)
        #pragma unroll
        for(int jj = 0; jj < 2; jj++)
            wmma::fill_fragment(acc[i][jj], 0.f);

    int arow = t >> 1, aseg = t & 1;
    int brow = t >> 2, bcol = (t & 3) * 16;
    for(int k0 = 0; k0 < 256; k0 += 32){
        int gm = m0 + arow;
        uint4 z4 = make_uint4(0,0,0,0);
        const uint4* srcA = (const uint4*)(g_hh + gm*128 + (k0 >> 1) + aseg*8);
        uint4 av0 = (gm < Nn) ? srcA[0] : z4;
        uint4 av1 = (gm < Nn) ? srcA[1] : z4;
        *(uint4*)&As[arow][aseg*16]     = av0;
        *(uint4*)&As[arow][aseg*16 + 8] = av1;
        const float4* srcB = (const float4*)(B + (k0+brow)*256 + n0 + bcol);
        float4 f0 = srcB[0], f1 = srcB[1], f2 = srcB[2], f3 = srcB[3];
        __half2* db = (__half2*)&Bs[brow][bcol];
        db[0] = __floats2half2_rn(f0.x,f0.y); db[1] = __floats2half2_rn(f0.z,f0.w);
        db[2] = __floats2half2_rn(f1.x,f1.y); db[3] = __floats2half2_rn(f1.z,f1.w);
        db[4] = __floats2half2_rn(f2.x,f2.y); db[5] = __floats2half2_rn(f2.z,f2.w);
        db[6] = __floats2half2_rn(f3.x,f3.y); db[7] = __floats2half2_rn(f3.z,f3.w);
        __syncthreads();
        #pragma unroll
        for(int ks = 0; ks < 2; ks++){
            wmma::fragment<wmma::matrix_a,16,16,16,__half,wmma::row_major> af[2];
            wmma::fragment<wmma::matrix_b,16,16,16,__half,wmma::row_major> bf[2];
            #pragma unroll
            for(int i = 0; i < 2; i++)
                wmma::load_matrix_sync(af[i], &As[wy*32 + i*16][ks*16], 40);
            #pragma unroll
            for(int jj = 0; jj < 2; jj++)
                wmma::load_matrix_sync(bf[jj], &Bs[ks*16][wx*32 + jj*16], 72);
            #pragma unroll
            for(int i = 0; i < 2; i++)
                #pragma unroll
                for(int jj = 0; jj < 2; jj++)
                    wmma::mma_sync(acc[i][jj], af[i], bf[jj], acc[i][jj]);
        }
        __syncthreads();
    }
    #pragma unroll
    for(int i = 0; i < 2; i++)
        #pragma unroll
        for(int jj = 0; jj < 2; jj++)
            wmma::store_matrix_sync(&Cs[wy*32 + i*16][wx*32 + jj*16], acc[i][jj], 68, wmma::mem_row_major);
    __syncthreads();
    for(int idx = t; idx < 64*16; idx += 128){
        int row = idx >> 4;
        int c4 = (idx & 15) * 4;
        int gm = m0 + row;
        if(gm >= Nn) continue;
        float4 v = *(float4*)&Cs[row][c4];
        float4 bv = *(const float4*)(bias + n0 + c4);
        v.x += bv.x; v.y += bv.y; v.z += bv.z; v.w += bv.w;
        if(half_){
            *(float4*)(g_xr + gm*256 + n0 + c4) = v;
        } else {
            __half2* d2 = g_xlh + gm*128 + ((n0 + c4) >> 1);
            d2[0] = __floats2half2_rn(v.x, v.y);
            d2[1] = __floats2half2_rn(v.z, v.w);
        }
    }
}

// ---------------- policy GEMM: fp16 tensor cores + fused Wp2 projection ----------
__global__ void __launch_bounds__(128) k_gemm_pol(
        const float* __restrict__ Wp1, const float* __restrict__ bp1,
        const float* __restrict__ Wp2, const float* __restrict__ bp2){
    __shared__ __align__(16) __half As[64][40];
    __shared__ __align__(16) __half Bs[32][136];
    __shared__ __align__(16) float  Cs[64][132];
    int m0 = blockIdx.x * 64;
    int t = threadIdx.x;
    int warp = t >> 5, wy = warp >> 1, wx = warp & 1;

    wmma::fragment<wmma::accumulator,16,16,16,float> acc[2][4];
    #pragma unroll
    for(int i = 0; i < 2; i++)
        #pragma unroll
        for(int jj = 0; jj < 4; jj++)
            wmma::fill_fragment(acc[i][jj], 0.f);

    int arow = t >> 1, aseg = t & 1;
    int brow = t >> 2, bcol = (t & 3) * 32;
    for(int k0 = 0; k0 < 256; k0 += 32){
        int gm = m0 + arow;
        uint4 z4 = make_uint4(0,0,0,0);
        const uint4* srcA = (const uint4*)(g_hh + gm*128 + (k0 >> 1) + aseg*8);
        uint4 av0 = (gm < Nn) ? srcA[0] : z4;
        uint4 av1 = (gm < Nn) ? srcA[1] : z4;
        *(uint4*)&As[arow][aseg*16]     = av0;
        *(uint4*)&As[arow][aseg*16 + 8] = av1;
        const float4* srcB = (const float4*)(Wp1 + (k0+brow)*128 + bcol);
        __half2* db = (__half2*)&Bs[brow][bcol];
        #pragma unroll
        for(int q = 0; q < 8; q++){
            float4 f = srcB[q];
            db[2*q]   = __floats2half2_rn(f.x, f.y);
            db[2*q+1] = __floats2half2_rn(f.z, f.w);
        }
        __syncthreads();
        #pragma unroll
        for(int ks = 0; ks < 2; ks++){
            wmma::fragment<wmma::matrix_a,16,16,16,__half,wmma::row_major> af[2];
            wmma::fragment<wmma::matrix_b,16,16,16,__half,wmma::row_major> bf[4];
            #pragma unroll
            for(int i = 0; i < 2; i++)
                wmma::load_matrix_sync(af[i], &As[wy*32 + i*16][ks*16], 40);
            #pragma unroll
            for(int jj = 0; jj < 4; jj++)
                wmma::load_matrix_sync(bf[jj], &Bs[ks*16][wx*64 + jj*16], 136);
            #pragma unroll
            for(int i = 0; i < 2; i++)
                #pragma unroll
                for(int jj = 0; jj < 4; jj++)
                    wmma::mma_sync(acc[i][jj], af[i], bf[jj], acc[i][jj]);
        }
        __syncthreads();
    }
    #pragma unroll
    for(int i = 0; i < 2; i++)
        #pragma unroll
        for(int jj = 0; jj < 4; jj++)
            wmma::store_matrix_sync(&Cs[wy*32 + i*16][wx*64 + jj*16], acc[i][jj], 132, wmma::mem_row_major);
    __syncthreads();
    {
        int row = t >> 1;
        int seg = t & 1;
        int gm = m0 + row;
        float part0 = 0.f, part1 = 0.f, part2 = 0.f, part3 = 0.f;
        #pragma unroll 8
        for(int j = 0; j < 64; j++){
            int col = seg*64 + j;
            float v = fmaxf(Cs[row][col] + bp1[col], 0.f);
            const float4 wv = *(const float4*)(Wp2 + col*4);
            part0 += v*wv.x; part1 += v*wv.y; part2 += v*wv.z; part3 += v*wv.w;
        }
        part0 += __shfl_xor_sync(0xffffffffu, part0, 1);
        part1 += __shfl_xor_sync(0xffffffffu, part1, 1);
        part2 += __shfl_xor_sync(0xffffffffu, part2, 1);
        part3 += __shfl_xor_sync(0xffffffffu, part3, 1);
        if(seg == 0 && gm < Nn){
            float4 r4 = make_float4(part0 + bp2[0], part1 + bp2[1],
                                    part2 + bp2[2], part3 + bp2[3]);
            *(float4*)(g_pl + gm*4) = r4;
        }
    }
}

// ---------------- two-phase global softmax over 40000 logits ----------------
__global__ void k_red1(){
    __shared__ float sm[256];
    int bid = blockIdx.x, tid = threadIdx.x;
    const int chunk = (Nn*4 + NRED - 1) / NRED;
    int lo = bid*chunk, hi = min(lo + chunk, Nn*4);
    float m = -3.4e38f;
    for(int i = lo + tid; i < hi; i += 256) m = fmaxf(m, g_pl[i]);
    sm[tid] = m; __syncthreads();
    for(int o = 128; o > 0; o >>= 1){ if(tid < o) sm[tid] = fmaxf(sm[tid], sm[tid+o]); __syncthreads(); }
    float mx = sm[0]; __syncthreads();
    float s = 0.f;
    for(int i = lo + tid; i < hi; i += 256) s += __expf(g_pl[i] - mx);
    sm[tid] = s; __syncthreads();
    for(int o = 128; o > 0; o >>= 1){ if(tid < o) sm[tid] += sm[tid+o]; __syncthreads(); }
    if(tid == 0){ g_pmax[bid] = mx; g_psum[bid] = sm[0]; }
}
// output (combines the NRED partials in-block) + restore state for next replay
__global__ void k_out(float* __restrict__ out){
    __shared__ float sMS[2];
    if(threadIdx.x == 0){
        float M = -3.4e38f;
        #pragma unroll
        for(int j = 0; j < NRED; j++) M = fmaxf(M, g_pmax[j]);
        float S = 0.f;
        #pragma unroll
        for(int j = 0; j < NRED; j++) S += g_psum[j] * __expf(g_pmax[j] - M);
        sMS[0] = M; sMS[1] = 1.f / S;
    }
    __syncthreads();
    int i = blockIdx.x*blockDim.x + threadIdx.x;
    if(i < Nn*4) out[i] = __expf(g_pl[i] - sMS[0]) * sMS[1];
    if(i < Nn){ g_cnt[i] = 0; g_loop[i] = 0.f; }
}

// ---------------- launch ----------------
extern "C" void kernel_launch(void* const* d_in, const int* in_sizes, int n_in,
                              void* d_out, int out_size){
    const float* x     = (const float*)d_in[0];
    const int*   ei    = (const int*)  d_in[1];
    const float* ea    = (const float*)d_in[2];
    const float* Wl1   = (const float*)d_in[3];
    const float* bl1   = (const float*)d_in[4];
    const float* Wr1   = (const float*)d_in[5];
    const float* br1   = (const float*)d_in[6];
    const float* We1   = (const float*)d_in[7];
    const float* att1  = (const float*)d_in[8];
    const float* bias1 = (const float*)d_in[9];
    const float* g1    = (const float*)d_in[10];
    const float* be1   = (const float*)d_in[11];
    const float* Wl2   = (const float*)d_in[12];
    const float* bl2   = (const float*)d_in[13];
    const float* Wr2   = (const float*)d_in[14];
    const float* br2   = (const float*)d_in[15];
    const float* We2   = (const float*)d_in[16];
    const float* att2  = (const float*)d_in[17];
    const float* bias2 = (const float*)d_in[18];
    const float* g2    = (const float*)d_in[19];
    const float* be2   = (const float*)d_in[20];
    const float* Wp1   = (const float*)d_in[21];
    const float* bp1   = (const float*)d_in[22];
    const float* Wp2   = (const float*)d_in[23];
    const float* bp2   = (const float*)d_in[24];
    const int* src = ei;
    const int* dst = ei + Ne;
    float* out = (float*)d_out;

    const int TB = 256;

    // CSR build + conv1 linear (merged)
    k_hist_lin1<<<HB + (Nn*64+TB-1)/TB, TB>>>(dst, ea, x, Wl1, bl1, Wr1, br1);
    k_scanprep<<<1, 1024>>>();
    k_scatter<<<(Ne+TB-1)/TB, TB>>>(src, dst, ea);

    // conv1 (low-rank aggregation, half2 logits) — one warp-block per node
    k_conv1lr<<<Nn, 32>>>(x, Wl1, bl1, We1, att1, bias1, g1, be1);

    // conv2 (fp16 tensor-core dual GEMM)
    k_gemm_dual<<<dim3(8, (Nn+63)/64), 128>>>(Wl2, bl2, Wr2, br2);
    k_conv2<<<Nn, 32>>>(We2, att2, bias2, g2, be2);

    // policy head (fp16 tensor-core GEMM + fused final projection)
    k_gemm_pol<<<(Nn+63)/64, 128>>>(Wp1, bp1, Wp2, bp2);

    // global softmax (two-phase)
    k_red1<<<NRED, 256>>>();
    k_out<<<(Nn*4+TB-1)/TB, TB>>>(out);
}

// round 15
// speedup vs baseline: 1.7169x; 1.0492x over previous
#include <cuda_runtime.h>
#include <cuda_fp16.h>
#include <mma.h>
using namespace nvcuda;

#define Nn   10000
#define Ne   320000
#define EAt  330000      // edges + self loops
#define HID  256
#define NRED 157         // one partial per gemm_pol block

// ---------------- scratch (static device globals; zero-initialized at load) ------
__device__ float    g_loop[Nn];
__device__ int      g_cnt[Nn];
__device__ int      g_row[Nn+1];
__device__ int      g_woff[Nn];
__device__ int2     g_ced[EAt];        // (src, edge_attr bits)
__device__ __half2  g_xlh[Nn*128];     // fp16 xl feature table (edge-gathered)
__device__ __half2  g_hh[Nn*128];      // fp16 activations: conv1 out, then conv2 out
__device__ float    g_xr[Nn*HID];
__device__ float    g_pl[Nn*4];
__device__ float    g_pmax[NRED];
__device__ float    g_psum[NRED];

// half2 logit kernel: p_lane = Σ_j [ (0.6att)·z + (0.4att)·|z| ],  z = la + r + ev·w
__device__ __forceinline__ float dot8h(const __half2* la, const __half2* rh,
                                       const __half2* wh, const __half2* a06,
                                       const __half2* a04, __half2 evh){
    __half2 pa = __float2half2_rn(0.f), pb = __float2half2_rn(0.f);
    #pragma unroll
    for(int j4 = 0; j4 < 4; j4++){
        __half2 z = __hfma2(evh, wh[j4], __hadd2(la[j4], rh[j4]));
        pa = __hfma2(z, a06[j4], pa);
        pb = __hfma2(__habs2(z), a04[j4], pb);
    }
    float2 f = __half22float2(__hadd2(pa, pb));
    return f.x + f.y;
}

// ---------------- kernel 1: edge histogram (+loop attr sum)  ||  lin1 ----------------
#define HB 1250   // (Ne+255)/256
__global__ void k_hist_lin1(const int* __restrict__ dst, const float* __restrict__ ea,
                            const float* __restrict__ x,
                            const float* __restrict__ Wl, const float* __restrict__ bl,
                            const float* __restrict__ Wr, const float* __restrict__ br){
    int b = blockIdx.x;
    if(b < HB){
        int e = b*256 + threadIdx.x;
        if(e < Ne){
            int d = dst[e];
            atomicAdd(&g_cnt[d], 1);
            atomicAdd(&g_loop[d], ea[e]);
        }
    } else {
        int t = (b - HB)*256 + threadIdx.x;
        if(t < Nn*64){
            int n = t >> 6, c4 = (t & 63) << 2;
            float4 xv = *(const float4*)(x + n*4);
            float4 l = *(const float4*)(bl + c4);
            float4 r = *(const float4*)(br + c4);
            float4 w;
            w = *(const float4*)(Wl + 0*256 + c4); l.x+=xv.x*w.x; l.y+=xv.x*w.y; l.z+=xv.x*w.z; l.w+=xv.x*w.w;
            w = *(const float4*)(Wl + 1*256 + c4); l.x+=xv.y*w.x; l.y+=xv.y*w.y; l.z+=xv.y*w.z; l.w+=xv.y*w.w;
            w = *(const float4*)(Wl + 2*256 + c4); l.x+=xv.z*w.x; l.y+=xv.z*w.y; l.z+=xv.z*w.z; l.w+=xv.z*w.w;
            w = *(const float4*)(Wl + 3*256 + c4); l.x+=xv.w*w.x; l.y+=xv.w*w.y; l.z+=xv.w*w.z; l.w+=xv.w*w.w;
            w = *(const float4*)(Wr + 0*256 + c4); r.x+=xv.x*w.x; r.y+=xv.x*w.y; r.z+=xv.x*w.z; r.w+=xv.x*w.w;
            w = *(const float4*)(Wr + 1*256 + c4); r.x+=xv.y*w.x; r.y+=xv.y*w.y; r.z+=xv.y*w.z; r.w+=xv.y*w.w;
            w = *(const float4*)(Wr + 2*256 + c4); r.x+=xv.z*w.x; r.y+=xv.z*w.y; r.z+=xv.z*w.z; r.w+=xv.z*w.w;
            w = *(const float4*)(Wr + 3*256 + c4); r.x+=xv.w*w.x; r.y+=xv.w*w.y; r.z+=xv.w*w.z; r.w+=xv.w*w.w;
            __half2 h0 = __floats2half2_rn(l.x, l.y);
            __half2 h1 = __floats2half2_rn(l.z, l.w);
            __half2* dst2 = g_xlh + n*128 + (c4 >> 1);
            dst2[0] = h0; dst2[1] = h1;
            *(float4*)(g_xr + n*256 + c4) = r;
        }
    }
}

// ---------------- kernel 2: scan + prep (single block) ----------------
__global__ void k_scanprep(){
    __shared__ int part[1024];
    const int NP = 10;
    int tid = threadIdx.x;
    int base = tid * NP;
    int cnt[NP], loc[NP];
    int s = 0;
    #pragma unroll
    for(int i = 0; i < NP; i++){
        int idx = base + i;
        int c = (idx < Nn) ? g_cnt[idx] : 0;
        cnt[i] = c;
        loc[i] = s;
        s += (idx < Nn) ? (c + 1) : 0;
    }
    part[tid] = s; __syncthreads();
    for(int o = 1; o < 1024; o <<= 1){
        int v = (tid >= o) ? part[tid - o] : 0;
        __syncthreads();
        if(tid >= o) part[tid] += v;
        __syncthreads();
    }
    int off = (tid > 0) ? part[tid - 1] : 0;
    #pragma unroll
    for(int i = 0; i < NP; i++){
        int idx = base + i;
        if(idx < Nn){
            int rs = off + loc[i];
            int re = rs + cnt[i] + 1;
            g_row[idx] = rs;
            if(idx == Nn-1) g_row[Nn] = re;
            float lp = g_loop[idx] / fmaxf((float)cnt[i], 1.f);
            g_ced[re-1] = make_int2(idx, __float_as_int(lp));
            g_woff[idx] = rs;
        }
    }
}

// ---------------- kernel 3: scatter edges into CSR ----------------
__global__ void k_scatter(const int* __restrict__ src, const int* __restrict__ dst,
                          const float* __restrict__ ea){
    int e = blockIdx.x*blockDim.x + threadIdx.x;
    if(e >= Ne) return;
    int d = dst[e];
    int pos = atomicAdd(&g_woff[d], 1);
    g_ced[pos] = make_int2(src[e], __float_as_int(ea[e]));
}

// ---------------- fused conv1 (low-rank aggregation; half2 logit path) -----------
__global__ void __launch_bounds__(32) k_conv1lr(
        const float* __restrict__ x,
        const float* __restrict__ Wl, const float* __restrict__ bl,
        const float* __restrict__ We, const float* __restrict__ att,
        const float* __restrict__ bias, const float* __restrict__ gam,
        const float* __restrict__ bet){
    int n = blockIdx.x;
    int lane = threadIdx.x;
    int c0 = lane * 8;
    __half2 rh[4], wh[4], a06[4], a04[4];
    {
        float4 rA = *(const float4*)(g_xr + n*HID + c0);
        float4 rB = *(const float4*)(g_xr + n*HID + c0 + 4);
        rh[0] = __floats2half2_rn(rA.x, rA.y); rh[1] = __floats2half2_rn(rA.z, rA.w);
        rh[2] = __floats2half2_rn(rB.x, rB.y); rh[3] = __floats2half2_rn(rB.z, rB.w);
        float4 wA = *(const float4*)(We + c0), wB = *(const float4*)(We + c0 + 4);
        wh[0] = __floats2half2_rn(wA.x, wA.y); wh[1] = __floats2half2_rn(wA.z, wA.w);
        wh[2] = __floats2half2_rn(wB.x, wB.y); wh[3] = __floats2half2_rn(wB.z, wB.w);
        float4 tA = *(const float4*)(att + c0), tB = *(const float4*)(att + c0 + 4);
        a06[0] = __floats2half2_rn(0.6f*tA.x, 0.6f*tA.y); a06[1] = __floats2half2_rn(0.6f*tA.z, 0.6f*tA.w);
        a06[2] = __floats2half2_rn(0.6f*tB.x, 0.6f*tB.y); a06[3] = __floats2half2_rn(0.6f*tB.z, 0.6f*tB.w);
        a04[0] = __floats2half2_rn(0.4f*tA.x, 0.4f*tA.y); a04[1] = __floats2half2_rn(0.4f*tA.z, 0.4f*tA.w);
        a04[2] = __floats2half2_rn(0.4f*tB.x, 0.4f*tB.y); a04[3] = __floats2half2_rn(0.4f*tB.z, 0.4f*tB.w);
    }
    int j = lane & 3;
    float acc1 = 0.f, den = 0.f;
    int b = g_row[n], e = g_row[n+1];
    int i = b;
    for(; i + 1 < e; i += 2){
        int2 ed0 = g_ced[i], ed1 = g_ced[i+1];
        uint4 raw0 = *(const uint4*)(g_xlh + ed0.x*128 + lane*4);
        uint4 raw1 = *(const uint4*)(g_xlh + ed1.x*128 + lane*4);
        const __half2* la = (const __half2*)&raw0;
        const __half2* lb = (const __half2*)&raw1;
        __half2 evh0 = __float2half2_rn(__int_as_float(ed0.y));
        __half2 evh1 = __float2half2_rn(__int_as_float(ed1.y));
        float xs0 = x[ed0.x*4 + j];
        float xs1 = x[ed1.x*4 + j];
        float p0 = dot8h(la, rh, wh, a06, a04, evh0);
        float p1 = dot8h(lb, rh, wh, a06, a04, evh1);
        #pragma unroll
        for(int o = 0; o < 3; o++){
            p0 += __shfl_xor_sync(0xffffffffu, p0, 1 << o);
            p1 += __shfl_xor_sync(0xffffffffu, p1, 1 << o);
        }
        float e0 = __expf(p0);
        float e1 = __expf(p1);
        den += e0 + e1;
        acc1 += xs0*e0 + xs1*e1;
    }
    if(i < e){
        int2 ed0 = g_ced[i];
        uint4 raw0 = *(const uint4*)(g_xlh + ed0.x*128 + lane*4);
        const __half2* la = (const __half2*)&raw0;
        __half2 evh0 = __float2half2_rn(__int_as_float(ed0.y));
        float xs0 = x[ed0.x*4 + j];
        float p0 = dot8h(la, rh, wh, a06, a04, evh0);
        #pragma unroll
        for(int o = 0; o < 3; o++)
            p0 += __shfl_xor_sync(0xffffffffu, p0, 1 << o);
        float e0 = __expf(p0);
        den += e0;
        acc1 += xs0*e0;
    }
    float inv = 1.f / den;
    int h8 = lane & 24;
    float ax0 = __shfl_sync(0xffffffffu, acc1, h8+0) * inv;
    float ax1 = __shfl_sync(0xffffffffu, acc1, h8+1) * inv;
    float ax2 = __shfl_sync(0xffffffffu, acc1, h8+2) * inv;
    float ax3 = __shfl_sync(0xffffffffu, acc1, h8+3) * inv;
    float4 wr0A = *(const float4*)(Wl + 0*256 + c0), wr0B = *(const float4*)(Wl + 0*256 + c0 + 4);
    float4 wr1A = *(const float4*)(Wl + 1*256 + c0), wr1B = *(const float4*)(Wl + 1*256 + c0 + 4);
    float4 wr2A = *(const float4*)(Wl + 2*256 + c0), wr2B = *(const float4*)(Wl + 2*256 + c0 + 4);
    float4 wr3A = *(const float4*)(Wl + 3*256 + c0), wr3B = *(const float4*)(Wl + 3*256 + c0 + 4);
    float4 blA = *(const float4*)(bl + c0),   blB = *(const float4*)(bl + c0 + 4);
    float4 biA = *(const float4*)(bias + c0), biB = *(const float4*)(bias + c0 + 4);
    float v[8];
    v[0] = ax0*wr0A.x + ax1*wr1A.x + ax2*wr2A.x + ax3*wr3A.x + blA.x + biA.x;
    v[1] = ax0*wr0A.y + ax1*wr1A.y + ax2*wr2A.y + ax3*wr3A.y + blA.y + biA.y;
    v[2] = ax0*wr0A.z + ax1*wr1A.z + ax2*wr2A.z + ax3*wr3A.z + blA.z + biA.z;
    v[3] = ax0*wr0A.w + ax1*wr1A.w + ax2*wr2A.w + ax3*wr3A.w + blA.w + biA.w;
    v[4] = ax0*wr0B.x + ax1*wr1B.x + ax2*wr2B.x + ax3*wr3B.x + blB.x + biB.x;
    v[5] = ax0*wr0B.y + ax1*wr1B.y + ax2*wr2B.y + ax3*wr3B.y + blB.y + biB.y;
    v[6] = ax0*wr0B.z + ax1*wr1B.z + ax2*wr2B.z + ax3*wr3B.z + blB.z + biB.z;
    v[7] = ax0*wr0B.w + ax1*wr1B.w + ax2*wr2B.w + ax3*wr3B.w + blB.w + biB.w;
    float s = 0.f;
    #pragma unroll
    for(int k = 0; k < 8; k++) s += v[k];
    #pragma unroll
    for(int o = 16; o; o >>= 1) s += __shfl_xor_sync(0xffffffffu, s, o);
    float mu = s * (1.f/256.f);
    float q = 0.f;
    #pragma unroll
    for(int k = 0; k < 8; k++){ float dd = v[k]-mu; q += dd*dd; }
    #pragma unroll
    for(int o = 16; o; o >>= 1) q += __shfl_xor_sync(0xffffffffu, q, o);
    float rstd = rsqrtf(q*(1.f/256.f) + 1e-5f);
    float4 gA = *(const float4*)(gam + c0), gB = *(const float4*)(gam + c0 + 4);
    float4 eA = *(const float4*)(bet + c0), eB = *(const float4*)(bet + c0 + 4);
    float gv[8] = {gA.x,gA.y,gA.z,gA.w,gB.x,gB.y,gB.z,gB.w};
    float ev[8] = {eA.x,eA.y,eA.z,eA.w,eB.x,eB.y,eB.z,eB.w};
    float o0[8];
    #pragma unroll
    for(int k = 0; k < 8; k++)
        o0[k] = fmaxf((v[k]-mu)*rstd*gv[k] + ev[k], 0.f);
    __half2* dh = g_hh + n*128 + lane*4;
    dh[0] = __floats2half2_rn(o0[0], o0[1]);
    dh[1] = __floats2half2_rn(o0[2], o0[3]);
    dh[2] = __floats2half2_rn(o0[4], o0[5]);
    dh[3] = __floats2half2_rn(o0[6], o0[7]);
}

// ---------------- fused conv2: half2 logits + half2 aggregation w/ fp32 flush ----
__global__ void __launch_bounds__(32) k_conv2(
        const float* __restrict__ We, const float* __restrict__ att,
        const float* __restrict__ bias, const float* __restrict__ gam,
        const float* __restrict__ bet){
    int n = blockIdx.x;
    int lane = threadIdx.x;
    int c0 = lane * 8;
    __half2 rh[4], wh[4], a06[4], a04[4];
    {
        float4 rA = *(const float4*)(g_xr + n*HID + c0);
        float4 rB = *(const float4*)(g_xr + n*HID + c0 + 4);
        rh[0] = __floats2half2_rn(rA.x, rA.y); rh[1] = __floats2half2_rn(rA.z, rA.w);
        rh[2] = __floats2half2_rn(rB.x, rB.y); rh[3] = __floats2half2_rn(rB.z, rB.w);
        float4 wA = *(const float4*)(We + c0), wB = *(const float4*)(We + c0 + 4);
        wh[0] = __floats2half2_rn(wA.x, wA.y); wh[1] = __floats2half2_rn(wA.z, wA.w);
        wh[2] = __floats2half2_rn(wB.x, wB.y); wh[3] = __floats2half2_rn(wB.z, wB.w);
        float4 tA = *(const float4*)(att + c0), tB = *(const float4*)(att + c0 + 4);
        a06[0] = __floats2half2_rn(0.6f*tA.x, 0.6f*tA.y); a06[1] = __floats2half2_rn(0.6f*tA.z, 0.6f*tA.w);
        a06[2] = __floats2half2_rn(0.6f*tB.x, 0.6f*tB.y); a06[3] = __floats2half2_rn(0.6f*tB.z, 0.6f*tB.w);
        a04[0] = __floats2half2_rn(0.4f*tA.x, 0.4f*tA.y); a04[1] = __floats2half2_rn(0.4f*tA.z, 0.4f*tA.w);
        a04[2] = __floats2half2_rn(0.4f*tB.x, 0.4f*tB.y); a04[3] = __floats2half2_rn(0.4f*tB.z, 0.4f*tB.w);
    }
    float acc[8] = {0,0,0,0,0,0,0,0};
    __half2 zero2 = __float2half2_rn(0.f);
    __half2 hacc[4] = {zero2, zero2, zero2, zero2};
    float den = 0.f;
    int flush = 0;
    int b = g_row[n], e = g_row[n+1];
    int i = b;
    for(; i + 1 < e; i += 2){
        int2 ed0 = g_ced[i], ed1 = g_ced[i+1];
        uint4 raw0 = *(const uint4*)(g_xlh + ed0.x*128 + lane*4);
        uint4 raw1 = *(const uint4*)(g_xlh + ed1.x*128 + lane*4);
        const __half2* la = (const __half2*)&raw0;
        const __half2* lb = (const __half2*)&raw1;
        __half2 evh0 = __float2half2_rn(__int_as_float(ed0.y));
        __half2 evh1 = __float2half2_rn(__int_as_float(ed1.y));
        float p0 = dot8h(la, rh, wh, a06, a04, evh0);
        float p1 = dot8h(lb, rh, wh, a06, a04, evh1);
        #pragma unroll
        for(int o = 0; o < 5; o++){
            p0 += __shfl_xor_sync(0xffffffffu, p0, 1 << o);
            p1 += __shfl_xor_sync(0xffffffffu, p1, 1 << o);
        }
        float e0 = __expf(p0);
        float e1 = __expf(p1);
        den += e0 + e1;
        __half2 eh0 = __float2half2_rn(e0);
        __half2 eh1 = __float2half2_rn(e1);
        #pragma unroll
        for(int j4 = 0; j4 < 4; j4++){
            hacc[j4] = __hfma2(la[j4], eh0, hacc[j4]);
            hacc[j4] = __hfma2(lb[j4], eh1, hacc[j4]);
        }
        if(++flush == 4){
            flush = 0;
            #pragma unroll
            for(int j4 = 0; j4 < 4; j4++){
                float2 f = __half22float2(hacc[j4]);
                acc[2*j4]   += f.x;
                acc[2*j4+1] += f.y;
                hacc[j4] = zero2;
            }
        }
    }
    if(i < e){
        int2 ed0 = g_ced[i];
        uint4 raw0 = *(const uint4*)(g_xlh + ed0.x*128 + lane*4);
        const __half2* la = (const __half2*)&raw0;
        __half2 evh0 = __float2half2_rn(__int_as_float(ed0.y));
        float p0 = dot8h(la, rh, wh, a06, a04, evh0);
        #pragma unroll
        for(int o = 0; o < 5; o++)
            p0 += __shfl_xor_sync(0xffffffffu, p0, 1 << o);
        float e0 = __expf(p0);
        den += e0;
        __half2 eh0 = __float2half2_rn(e0);
        #pragma unroll
        for(int j4 = 0; j4 < 4; j4++)
            hacc[j4] = __hfma2(la[j4], eh0, hacc[j4]);
    }
    // final flush
    #pragma unroll
    for(int j4 = 0; j4 < 4; j4++){
        float2 f = __half22float2(hacc[j4]);
        acc[2*j4]   += f.x;
        acc[2*j4+1] += f.y;
    }
    float inv = 1.f / den;
    float4 biA = *(const float4*)(bias + c0), biB = *(const float4*)(bias + c0 + 4);
    float bi[8] = {biA.x,biA.y,biA.z,biA.w,biB.x,biB.y,biB.z,biB.w};
    float v[8];
    float s = 0.f;
    #pragma unroll
    for(int k = 0; k < 8; k++){ v[k] = acc[k]*inv + bi[k]; s += v[k]; }
    #pragma unroll
    for(int o = 16; o; o >>= 1) s += __shfl_xor_sync(0xffffffffu, s, o);
    float mu = s * (1.f/256.f);
    float q = 0.f;
    #pragma unroll
    for(int k = 0; k < 8; k++){ float dd = v[k]-mu; q += dd*dd; }
    #pragma unroll
    for(int o = 16; o; o >>= 1) q += __shfl_xor_sync(0xffffffffu, q, o);
    float rstd = rsqrtf(q*(1.f/256.f) + 1e-5f);
    float4 gA = *(const float4*)(gam + c0), gB = *(const float4*)(gam + c0 + 4);
    float4 eA = *(const float4*)(bet + c0), eB = *(const float4*)(bet + c0 + 4);
    float gv[8] = {gA.x,gA.y,gA.z,gA.w,gB.x,gB.y,gB.z,gB.w};
    float evv[8] = {eA.x,eA.y,eA.z,eA.w,eB.x,eB.y,eB.z,eB.w};
    float o0[8];
    #pragma unroll
    for(int k = 0; k < 8; k++)
        o0[k] = fmaxf((v[k]-mu)*rstd*gv[k] + evv[k], 0.f);
    __half2* dh = g_hh + n*128 + lane*4;
    dh[0] = __floats2half2_rn(o0[0], o0[1]);
    dh[1] = __floats2half2_rn(o0[2], o0[3]);
    dh[2] = __floats2half2_rn(o0[4], o0[5]);
    dh[3] = __floats2half2_rn(o0[6], o0[7]);
}

// ---------------- dual GEMM: fp16 tensor cores (m16n16k16, fp32 accum) ----------
__global__ void __launch_bounds__(128) k_gemm_dual(
        const float* __restrict__ Wl, const float* __restrict__ bl,
        const float* __restrict__ Wr, const float* __restrict__ br){
    __shared__ __align__(16) __half As[64][40];
    __shared__ __align__(16) __half Bs[32][72];
    __shared__ __align__(16) float  Cs[64][68];
    int half_ = blockIdx.x >> 2;
    int nblk = blockIdx.x & 3;
    const float* B    = half_ ? Wr : Wl;
    const float* bias = half_ ? br : bl;
    int m0 = blockIdx.y*64, n0 = nblk*64;
    int t = threadIdx.x;
    int warp = t >> 5, wy = warp >> 1, wx = warp & 1;

    wmma::fragment<wmma::accumulator,16,16,16,float> acc[2][2];
    #pragma unroll
    for(int i = 0; i < 2; i++)
        #pragma unroll
        for(int jj = 0; jj < 2; jj++)
            wmma::fill_fragment(acc[i][jj], 0.f);

    int arow = t >> 1, aseg = t & 1;
    int brow = t >> 2, bcol = (t & 3) * 16;
    for(int k0 = 0; k0 < 256; k0 += 32){
        int gm = m0 + arow;
        uint4 z4 = make_uint4(0,0,0,0);
        const uint4* srcA = (const uint4*)(g_hh + gm*128 + (k0 >> 1) + aseg*8);
        uint4 av0 = (gm < Nn) ? srcA[0] : z4;
        uint4 av1 = (gm < Nn) ? srcA[1] : z4;
        *(uint4*)&As[arow][aseg*16]     = av0;
        *(uint4*)&As[arow][aseg*16 + 8] = av1;
        const float4* srcB = (const float4*)(B + (k0+brow)*256 + n0 + bcol);
        float4 f0 = srcB[0], f1 = srcB[1], f2 = srcB[2], f3 = srcB[3];
        __half2* db = (__half2*)&Bs[brow][bcol];
        db[0] = __floats2half2_rn(f0.x,f0.y); db[1] = __floats2half2_rn(f0.z,f0.w);
        db[2] = __floats2half2_rn(f1.x,f1.y); db[3] = __floats2half2_rn(f1.z,f1.w);
        db[4] = __floats2half2_rn(f2.x,f2.y); db[5] = __floats2half2_rn(f2.z,f2.w);
        db[6] = __floats2half2_rn(f3.x,f3.y); db[7] = __floats2half2_rn(f3.z,f3.w);
        __syncthreads();
        #pragma unroll
        for(int ks = 0; ks < 2; ks++){
            wmma::fragment<wmma::matrix_a,16,16,16,__half,wmma::row_major> af[2];
            wmma::fragment<wmma::matrix_b,16,16,16,__half,wmma::row_major> bf[2];
            #pragma unroll
            for(int i = 0; i < 2; i++)
                wmma::load_matrix_sync(af[i], &As[wy*32 + i*16][ks*16], 40);
            #pragma unroll
            for(int jj = 0; jj < 2; jj++)
                wmma::load_matrix_sync(bf[jj], &Bs[ks*16][wx*32 + jj*16], 72);
            #pragma unroll
            for(int i = 0; i < 2; i++)
                #pragma unroll
                for(int jj = 0; jj < 2; jj++)
                    wmma::mma_sync(acc[i][jj], af[i], bf[jj], acc[i][jj]);
        }
        __syncthreads();
    }
    #pragma unroll
    for(int i = 0; i < 2; i++)
        #pragma unroll
        for(int jj = 0; jj < 2; jj++)
            wmma::store_matrix_sync(&Cs[wy*32 + i*16][wx*32 + jj*16], acc[i][jj], 68, wmma::mem_row_major);
    __syncthreads();
    for(int idx = t; idx < 64*16; idx += 128){
        int row = idx >> 4;
        int c4 = (idx & 15) * 4;
        int gm = m0 + row;
        if(gm >= Nn) continue;
        float4 v = *(float4*)&Cs[row][c4];
        float4 bv = *(const float4*)(bias + n0 + c4);
        v.x += bv.x; v.y += bv.y; v.z += bv.z; v.w += bv.w;
        if(half_){
            *(float4*)(g_xr + gm*256 + n0 + c4) = v;
        } else {
            __half2* d2 = g_xlh + gm*128 + ((n0 + c4) >> 1);
            d2[0] = __floats2half2_rn(v.x, v.y);
            d2[1] = __floats2half2_rn(v.z, v.w);
        }
    }
}

// ---------------- policy GEMM: fp16 TC + fused Wp2 projection + softmax partials --
__global__ void __launch_bounds__(128) k_gemm_pol(
        const float* __restrict__ Wp1, const float* __restrict__ bp1,
        const float* __restrict__ Wp2, const float* __restrict__ bp2){
    __shared__ __align__(16) __half As[64][40];
    __shared__ __align__(16) __half Bs[32][136];
    __shared__ __align__(16) float  Cs[64][132];
    int m0 = blockIdx.x * 64;
    int t = threadIdx.x;
    int warp = t >> 5, wy = warp >> 1, wx = warp & 1;

    wmma::fragment<wmma::accumulator,16,16,16,float> acc[2][4];
    #pragma unroll
    for(int i = 0; i < 2; i++)
        #pragma unroll
        for(int jj = 0; jj < 4; jj++)
            wmma::fill_fragment(acc[i][jj], 0.f);

    int arow = t >> 1, aseg = t & 1;
    int brow = t >> 2, bcol = (t & 3) * 32;
    for(int k0 = 0; k0 < 256; k0 += 32){
        int gm = m0 + arow;
        uint4 z4 = make_uint4(0,0,0,0);
        const uint4* srcA = (const uint4*)(g_hh + gm*128 + (k0 >> 1) + aseg*8);
        uint4 av0 = (gm < Nn) ? srcA[0] : z4;
        uint4 av1 = (gm < Nn) ? srcA[1] : z4;
        *(uint4*)&As[arow][aseg*16]     = av0;
        *(uint4*)&As[arow][aseg*16 + 8] = av1;
        const float4* srcB = (const float4*)(Wp1 + (k0+brow)*128 + bcol);
        __half2* db = (__half2*)&Bs[brow][bcol];
        #pragma unroll
        for(int q = 0; q < 8; q++){
            float4 f = srcB[q];
            db[2*q]   = __floats2half2_rn(f.x, f.y);
            db[2*q+1] = __floats2half2_rn(f.z, f.w);
        }
        __syncthreads();
        #pragma unroll
        for(int ks = 0; ks < 2; ks++){
            wmma::fragment<wmma::matrix_a,16,16,16,__half,wmma::row_major> af[2];
            wmma::fragment<wmma::matrix_b,16,16,16,__half,wmma::row_major> bf[4];
            #pragma unroll
            for(int i = 0; i < 2; i++)
                wmma::load_matrix_sync(af[i], &As[wy*32 + i*16][ks*16], 40);
            #pragma unroll
            for(int jj = 0; jj < 4; jj++)
                wmma::load_matrix_sync(bf[jj], &Bs[ks*16][wx*64 + jj*16], 136);
            #pragma unroll
            for(int i = 0; i < 2; i++)
                #pragma unroll
                for(int jj = 0; jj < 4; jj++)
                    wmma::mma_sync(acc[i][jj], af[i], bf[jj], acc[i][jj]);
        }
        __syncthreads();
    }
    #pragma unroll
    for(int i = 0; i < 2; i++)
        #pragma unroll
        for(int jj = 0; jj < 4; jj++)
            wmma::store_matrix_sync(&Cs[wy*32 + i*16][wx*64 + jj*16], acc[i][jj], 132, wmma::mem_row_major);
    __syncthreads();
    // epilogue: relu(+bp1), project through Wp2[128,4]; then block softmax partials
    int row = t >> 1;
    int seg = t & 1;
    int gm = m0 + row;
    float part0 = 0.f, part1 = 0.f, part2 = 0.f, part3 = 0.f;
    #pragma unroll 8
    for(int jq = 0; jq < 64; jq++){
        int col = seg*64 + jq;
        float v = fmaxf(Cs[row][col] + bp1[col], 0.f);
        const float4 wv = *(const float4*)(Wp2 + col*4);
        part0 += v*wv.x; part1 += v*wv.y; part2 += v*wv.z; part3 += v*wv.w;
    }
    part0 += __shfl_xor_sync(0xffffffffu, part0, 1);
    part1 += __shfl_xor_sync(0xffffffffu, part1, 1);
    part2 += __shfl_xor_sync(0xffffffffu, part2, 1);
    part3 += __shfl_xor_sync(0xffffffffu, part3, 1);
    float4 r4 = make_float4(0.f, 0.f, 0.f, 0.f);
    bool valid = (seg == 0) && (gm < Nn);
    float lmax = -3.4e38f;
    if(valid){
        r4 = make_float4(part0 + bp2[0], part1 + bp2[1], part2 + bp2[2], part3 + bp2[3]);
        *(float4*)(g_pl + gm*4) = r4;
        lmax = fmaxf(fmaxf(r4.x, r4.y), fmaxf(r4.z, r4.w));
    }
    // block reduce (reuse dead As smem as float scratch)
    float* red = (float*)As;
    red[t] = lmax; __syncthreads();
    for(int o = 64; o > 0; o >>= 1){ if(t < o) red[t] = fmaxf(red[t], red[t+o]); __syncthreads(); }
    float M = red[0]; __syncthreads();
    float ls = 0.f;
    if(valid)
        ls = __expf(r4.x - M) + __expf(r4.y - M) + __expf(r4.z - M) + __expf(r4.w - M);
    red[t] = ls; __syncthreads();
    for(int o = 64; o > 0; o >>= 1){ if(t < o) red[t] += red[t+o]; __syncthreads(); }
    if(t == 0){ g_pmax[blockIdx.x] = M; g_psum[blockIdx.x] = red[0]; }
}

// ---------------- output: combine partials + softmax + restore replay state ------
__global__ void k_out(float* __restrict__ out){
    __shared__ float sm[256];
    __shared__ float sMS[2];
    int tid = threadIdx.x;
    float m = (tid < NRED) ? g_pmax[tid] : -3.4e38f;
    sm[tid] = m; __syncthreads();
    for(int o = 128; o > 0; o >>= 1){ if(tid < o) sm[tid] = fmaxf(sm[tid], sm[tid+o]); __syncthreads(); }
    float M = sm[0]; __syncthreads();
    float s = (tid < NRED) ? g_psum[tid] * __expf(g_pmax[tid] - M) : 0.f;
    sm[tid] = s; __syncthreads();
    for(int o = 128; o > 0; o >>= 1){ if(tid < o) sm[tid] += sm[tid+o]; __syncthreads(); }
    if(tid == 0){ sMS[0] = M; sMS[1] = 1.f / sm[0]; }
    __syncthreads();
    int i = blockIdx.x*blockDim.x + tid;
    if(i < Nn*4) out[i] = __expf(g_pl[i] - sMS[0]) * sMS[1];
    if(i < Nn){ g_cnt[i] = 0; g_loop[i] = 0.f; }
}

// ---------------- launch ----------------
extern "C" void kernel_launch(void* const* d_in, const int* in_sizes, int n_in,
                              void* d_out, int out_size){
    const float* x     = (const float*)d_in[0];
    const int*   ei    = (const int*)  d_in[1];
    const float* ea    = (const float*)d_in[2];
    const float* Wl1   = (const float*)d_in[3];
    const float* bl1   = (const float*)d_in[4];
    const float* Wr1   = (const float*)d_in[5];
    const float* br1   = (const float*)d_in[6];
    const float* We1   = (const float*)d_in[7];
    const float* att1  = (const float*)d_in[8];
    const float* bias1 = (const float*)d_in[9];
    const float* g1    = (const float*)d_in[10];
    const float* be1   = (const float*)d_in[11];
    const float* Wl2   = (const float*)d_in[12];
    const float* bl2   = (const float*)d_in[13];
    const float* Wr2   = (const float*)d_in[14];
    const float* br2   = (const float*)d_in[15];
    const float* We2   = (const float*)d_in[16];
    const float* att2  = (const float*)d_in[17];
    const float* bias2 = (const float*)d_in[18];
    const float* g2    = (const float*)d_in[19];
    const float* be2   = (const float*)d_in[20];
    const float* Wp1   = (const float*)d_in[21];
    const float* bp1   = (const float*)d_in[22];
    const float* Wp2   = (const float*)d_in[23];
    const float* bp2   = (const float*)d_in[24];
    const int* src = ei;
    const int* dst = ei + Ne;
    float* out = (float*)d_out;

    const int TB = 256;

    // CSR build + conv1 linear (merged)
    k_hist_lin1<<<HB + (Nn*64+TB-1)/TB, TB>>>(dst, ea, x, Wl1, bl1, Wr1, br1);
    k_scanprep<<<1, 1024>>>();
    k_scatter<<<(Ne+TB-1)/TB, TB>>>(src, dst, ea);

    // conv1 (low-rank aggregation, half2 logits) — one warp-block per node
    k_conv1lr<<<Nn, 32>>>(x, Wl1, bl1, We1, att1, bias1, g1, be1);

    // conv2 (fp16 tensor-core dual GEMM)
    k_gemm_dual<<<dim3(8, (Nn+63)/64), 128>>>(Wl2, bl2, Wr2, br2);
    k_conv2<<<Nn, 32>>>(We2, att2, bias2, g2, be2);

    // policy head (fp16 TC GEMM + fused projection + softmax partials)
    k_gemm_pol<<<NRED, 128>>>(Wp1, bp1, Wp2, bp2);

    // output
    k_out<<<(Nn*4+TB-1)/TB, TB>>>(out);
}